// round 2
// baseline (speedup 1.0000x reference)
#include <cuda_runtime.h>

#define BB 2
#define TT 2048
#define DD 1024
#define HH 16
#define HD 64

// ---- scratch (device globals: allocation-free) ----
__device__ float g_ln [(size_t)BB*TT*DD];          // 16 MB
__device__ float g_q  [(size_t)BB*TT*DD];          // 16 MB  [B,H,T,hd]
__device__ float g_k  [(size_t)BB*TT*DD];
__device__ float g_v  [(size_t)BB*TT*DD];
__device__ float g_ctx[(size_t)BB*TT*DD];          // [B,T,D]
__device__ float g_h  [(size_t)BB*TT*DD];
__device__ float g_s  [(size_t)BB*HH*TT*TT];       // 512 MB scores/attn

// ---------------------------------------------------------------------------
// LayerNorm (faithful bug: scale * x_norm + scale)
// ---------------------------------------------------------------------------
__global__ void ln_kernel(const float* __restrict__ x,
                          const float* __restrict__ scale,
                          float* __restrict__ y) {
    int row = blockIdx.x;                      // B*T rows
    const float* xr = x + (size_t)row * DD;
    float* yr = y + (size_t)row * DD;
    int tid = threadIdx.x;                     // 256
    float v[4];
    float s = 0.f, s2 = 0.f;
#pragma unroll
    for (int i = 0; i < 4; i++) {
        v[i] = xr[tid + 256 * i];
        s  += v[i];
        s2 += v[i] * v[i];
    }
    __shared__ float sh[256], sh2[256];
    sh[tid] = s; sh2[tid] = s2;
    __syncthreads();
    for (int o = 128; o > 0; o >>= 1) {
        if (tid < o) { sh[tid] += sh[tid + o]; sh2[tid] += sh2[tid + o]; }
        __syncthreads();
    }
    float mean = sh[0] * (1.f / DD);
    float var  = sh2[0] * (1.f / DD) - mean * mean;
    float rstd = rsqrtf(var + 1e-5f);
#pragma unroll
    for (int i = 0; i < 4; i++) {
        int c = tid + 256 * i;
        float sc = scale[c];
        yr[c] = sc * ((v[i] - mean) * rstd) + sc;
    }
}

// ---------------------------------------------------------------------------
// GEMM: P = A @ W^T, A[4096,1024], W[1024,1024]; store into [B,H,T,hd]
// 64x64x32 tiles, 256 threads, 4x4 micro-tile
// ---------------------------------------------------------------------------
__global__ void gemm_qkv_kernel(const float* __restrict__ A,
                                const float* __restrict__ W,
                                float* __restrict__ out) {
    __shared__ float As[64][33];
    __shared__ float Bs[64][33];
    int m0 = blockIdx.y * 64, n0 = blockIdx.x * 64;
    int tid = threadIdx.x;
    int ty = tid >> 4, tx = tid & 15;
    float acc[4][4] = {};
    for (int k0 = 0; k0 < DD; k0 += 32) {
#pragma unroll
        for (int r = 0; r < 2; r++) {
            int f = tid + r * 256;
            int row = f >> 3, c4 = (f & 7) * 4;
            float4 av = *(const float4*)(A + (size_t)(m0 + row) * DD + k0 + c4);
            As[row][c4] = av.x; As[row][c4+1] = av.y; As[row][c4+2] = av.z; As[row][c4+3] = av.w;
            float4 bv = *(const float4*)(W + (size_t)(n0 + row) * DD + k0 + c4);
            Bs[row][c4] = bv.x; Bs[row][c4+1] = bv.y; Bs[row][c4+2] = bv.z; Bs[row][c4+3] = bv.w;
        }
        __syncthreads();
#pragma unroll
        for (int kk = 0; kk < 32; kk++) {
            float a[4], b[4];
#pragma unroll
            for (int i = 0; i < 4; i++) { a[i] = As[ty*4+i][kk]; b[i] = Bs[tx*4+i][kk]; }
#pragma unroll
            for (int i = 0; i < 4; i++)
#pragma unroll
                for (int j = 0; j < 4; j++)
                    acc[i][j] += a[i] * b[j];
        }
        __syncthreads();
    }
#pragma unroll
    for (int i = 0; i < 4; i++)
#pragma unroll
        for (int j = 0; j < 4; j++) {
            int r = m0 + ty*4 + i, c = n0 + tx*4 + j;
            int b = r >> 11, t = r & 2047;
            int h = c >> 6,  d = c & 63;
            out[(((size_t)(b * HH + h)) * TT + t) * HD + d] = acc[i][j];
        }
}

// ---------------------------------------------------------------------------
// Scores: per (b,h): S = Q @ K^T (raw, causal tiles skipped). lda = 64.
// ---------------------------------------------------------------------------
__global__ void attn_scores_kernel(const float* __restrict__ Q,
                                   const float* __restrict__ Kt,
                                   float* __restrict__ S) {
    int m0 = blockIdx.y * 64, n0 = blockIdx.x * 64;
    if (n0 > m0 + 63) return;                       // fully masked tile
    int bh = blockIdx.z;
    const float* Qb = Q  + (size_t)bh * TT * HD;
    const float* Kb = Kt + (size_t)bh * TT * HD;
    float* Sb = S + (size_t)bh * TT * TT;
    __shared__ float As[64][33];
    __shared__ float Bs[64][33];
    int tid = threadIdx.x;
    int ty = tid >> 4, tx = tid & 15;
    float acc[4][4] = {};
    for (int k0 = 0; k0 < HD; k0 += 32) {
#pragma unroll
        for (int r = 0; r < 2; r++) {
            int f = tid + r * 256;
            int row = f >> 3, c4 = (f & 7) * 4;
            float4 av = *(const float4*)(Qb + (size_t)(m0 + row) * HD + k0 + c4);
            As[row][c4] = av.x; As[row][c4+1] = av.y; As[row][c4+2] = av.z; As[row][c4+3] = av.w;
            float4 bv = *(const float4*)(Kb + (size_t)(n0 + row) * HD + k0 + c4);
            Bs[row][c4] = bv.x; Bs[row][c4+1] = bv.y; Bs[row][c4+2] = bv.z; Bs[row][c4+3] = bv.w;
        }
        __syncthreads();
#pragma unroll
        for (int kk = 0; kk < 32; kk++) {
            float a[4], b[4];
#pragma unroll
            for (int i = 0; i < 4; i++) { a[i] = As[ty*4+i][kk]; b[i] = Bs[tx*4+i][kk]; }
#pragma unroll
            for (int i = 0; i < 4; i++)
#pragma unroll
                for (int j = 0; j < 4; j++)
                    acc[i][j] += a[i] * b[j];
        }
        __syncthreads();
    }
#pragma unroll
    for (int i = 0; i < 4; i++)
#pragma unroll
        for (int j = 0; j < 4; j++)
            Sb[(size_t)(m0 + ty*4 + i) * TT + (n0 + tx*4 + j)] = acc[i][j];
}

// ---------------------------------------------------------------------------
// Causal softmax of scores/8 per row; zero-fill up to the row's tile edge so
// the ctx GEMM (K bounded at tile diagonal) never reads garbage.
// ---------------------------------------------------------------------------
__global__ void softmax_kernel(float* __restrict__ S) {
    int idx = blockIdx.x;                 // B*H*T rows
    int q = idx & (TT - 1);
    int bh = idx >> 11;
    float* row = S + (size_t)bh * TT * TT + (size_t)q * TT;
    int n = q + 1;
    int tid = threadIdx.x;                // 128
    __shared__ float sh[128];

    float mx = -1e30f;
    for (int j = tid; j < n; j += 128) mx = fmaxf(mx, row[j] * 0.125f);
    sh[tid] = mx; __syncthreads();
    for (int o = 64; o > 0; o >>= 1) {
        if (tid < o) sh[tid] = fmaxf(sh[tid], sh[tid + o]);
        __syncthreads();
    }
    mx = sh[0];
    __syncthreads();

    float sum = 0.f;
    for (int j = tid; j < n; j += 128) {
        float e = __expf(row[j] * 0.125f - mx);
        row[j] = e;
        sum += e;
    }
    sh[tid] = sum; __syncthreads();
    for (int o = 64; o > 0; o >>= 1) {
        if (tid < o) sh[tid] += sh[tid + o];
        __syncthreads();
    }
    float inv = 1.f / sh[0];
    for (int j = tid; j < n; j += 128) row[j] *= inv;
    int zend = ((q >> 6) + 1) << 6;       // tile edge
    for (int j = n + tid; j < zend; j += 128) row[j] = 0.f;
}

// ---------------------------------------------------------------------------
// ctx = attn @ V per (b,h); K-loop bounded at the tile diagonal (causal).
// Store straight into [B,T,D].
// ---------------------------------------------------------------------------
__global__ void attn_ctx_kernel(const float* __restrict__ S,
                                const float* __restrict__ V,
                                float* __restrict__ C) {
    int bh = blockIdx.z;
    int m0 = blockIdx.y * 64;
    const float* Sb = S + (size_t)bh * TT * TT;
    const float* Vb = V + (size_t)bh * TT * HD;
    __shared__ float As[64][33];
    __shared__ float Bs[32][65];
    int tid = threadIdx.x;
    int ty = tid >> 4, tx = tid & 15;
    float acc[4][4] = {};
    int kend = m0 + 64;                   // causal bound
    for (int k0 = 0; k0 < kend; k0 += 32) {
#pragma unroll
        for (int r = 0; r < 2; r++) {
            int f = tid + r * 256;
            int row = f >> 3, c4 = (f & 7) * 4;
            float4 av = *(const float4*)(Sb + (size_t)(m0 + row) * TT + k0 + c4);
            As[row][c4] = av.x; As[row][c4+1] = av.y; As[row][c4+2] = av.z; As[row][c4+3] = av.w;
            int vrow = f >> 4, vc4 = (f & 15) * 4;
            float4 bv = *(const float4*)(Vb + (size_t)(k0 + vrow) * HD + vc4);
            Bs[vrow][vc4] = bv.x; Bs[vrow][vc4+1] = bv.y; Bs[vrow][vc4+2] = bv.z; Bs[vrow][vc4+3] = bv.w;
        }
        __syncthreads();
#pragma unroll
        for (int kk = 0; kk < 32; kk++) {
            float a[4], b[4];
#pragma unroll
            for (int i = 0; i < 4; i++) { a[i] = As[ty*4+i][kk]; b[i] = Bs[kk][tx*4+i]; }
#pragma unroll
            for (int i = 0; i < 4; i++)
#pragma unroll
                for (int j = 0; j < 4; j++)
                    acc[i][j] += a[i] * b[j];
        }
        __syncthreads();
    }
    int b = bh >> 4, h = bh & 15;
#pragma unroll
    for (int i = 0; i < 4; i++) {
        int q = m0 + ty*4 + i;
#pragma unroll
        for (int j = 0; j < 4; j++)
            C[((size_t)(b * TT + q)) * DD + h * HD + tx*4 + j] = acc[i][j];
    }
}

// ---------------------------------------------------------------------------
// out = res + bo + CTX @ WO^T
// ---------------------------------------------------------------------------
__global__ void gemm_out_kernel(const float* __restrict__ A,
                                const float* __restrict__ W,
                                const float* __restrict__ bias,
                                const float* __restrict__ res,
                                float* __restrict__ out) {
    __shared__ float As[64][33];
    __shared__ float Bs[64][33];
    int m0 = blockIdx.y * 64, n0 = blockIdx.x * 64;
    int tid = threadIdx.x;
    int ty = tid >> 4, tx = tid & 15;
    float acc[4][4] = {};
    for (int k0 = 0; k0 < DD; k0 += 32) {
#pragma unroll
        for (int r = 0; r < 2; r++) {
            int f = tid + r * 256;
            int row = f >> 3, c4 = (f & 7) * 4;
            float4 av = *(const float4*)(A + (size_t)(m0 + row) * DD + k0 + c4);
            As[row][c4] = av.x; As[row][c4+1] = av.y; As[row][c4+2] = av.z; As[row][c4+3] = av.w;
            float4 bv = *(const float4*)(W + (size_t)(n0 + row) * DD + k0 + c4);
            Bs[row][c4] = bv.x; Bs[row][c4+1] = bv.y; Bs[row][c4+2] = bv.z; Bs[row][c4+3] = bv.w;
        }
        __syncthreads();
#pragma unroll
        for (int kk = 0; kk < 32; kk++) {
            float a[4], b[4];
#pragma unroll
            for (int i = 0; i < 4; i++) { a[i] = As[ty*4+i][kk]; b[i] = Bs[tx*4+i][kk]; }
#pragma unroll
            for (int i = 0; i < 4; i++)
#pragma unroll
                for (int j = 0; j < 4; j++)
                    acc[i][j] += a[i] * b[j];
        }
        __syncthreads();
    }
#pragma unroll
    for (int i = 0; i < 4; i++)
#pragma unroll
        for (int j = 0; j < 4; j++) {
            int r = m0 + ty*4 + i, c = n0 + tx*4 + j;
            out[(size_t)r * DD + c] = res[(size_t)r * DD + c] + bias[c] + acc[i][j];
        }
}

// ---------------------------------------------------------------------------
// Host driver
// ---------------------------------------------------------------------------
static void run_block(const float* x_in, const float* ln_scale,
                      const float* wq, const float* wk, const float* wv,
                      const float* wo, const float* bo,
                      float* lnp, float* qp, float* kp, float* vp,
                      float* sp, float* ctxp, float* out) {
    dim3 gG(DD / 64, (BB * TT) / 64);
    ln_kernel<<<BB * TT, 256>>>(x_in, ln_scale, lnp);
    gemm_qkv_kernel<<<gG, 256>>>(lnp, wq, qp);
    gemm_qkv_kernel<<<gG, 256>>>(lnp, wk, kp);
    gemm_qkv_kernel<<<gG, 256>>>(lnp, wv, vp);
    attn_scores_kernel<<<dim3(TT / 64, TT / 64, BB * HH), 256>>>(qp, kp, sp);
    softmax_kernel<<<BB * HH * TT, 128>>>(sp);
    attn_ctx_kernel<<<dim3(1, TT / 64, BB * HH), 256>>>(sp, vp, ctxp);
    gemm_out_kernel<<<gG, 256>>>(ctxp, wo, bo, x_in, out);
}

extern "C" void kernel_launch(void* const* d_in, const int* in_sizes, int n_in,
                              void* d_out, int out_size) {
    const float* x   = (const float*)d_in[0];
    const float* wq  = (const float*)d_in[1];
    const float* wk  = (const float*)d_in[2];
    const float* wv  = (const float*)d_in[3];
    const float* wo  = (const float*)d_in[4];
    const float* bo  = (const float*)d_in[5];
    const float* ln1 = (const float*)d_in[6];
    const float* ln2 = (const float*)d_in[7];
    float* out = (float*)d_out;

    float *lnp, *qp, *kp, *vp, *sp, *ctxp, *hp;
    cudaGetSymbolAddress((void**)&lnp,  g_ln);
    cudaGetSymbolAddress((void**)&qp,   g_q);
    cudaGetSymbolAddress((void**)&kp,   g_k);
    cudaGetSymbolAddress((void**)&vp,   g_v);
    cudaGetSymbolAddress((void**)&sp,   g_s);
    cudaGetSymbolAddress((void**)&ctxp, g_ctx);
    cudaGetSymbolAddress((void**)&hp,   g_h);

    // Block 1: h = x + mhsa(ln(x, ln1))
    run_block(x,  ln1, wq, wk, wv, wo, bo, lnp, qp, kp, vp, sp, ctxp, hp);
    // Block 2: out = h + mhsa(ln(h, ln2))  (same attention weights)
    run_block(hp, ln2, wq, wk, wv, wo, bo, lnp, qp, kp, vp, sp, ctxp, out);
}

// round 4
// speedup vs baseline: 2.4601x; 2.4601x over previous
#include <cuda_runtime.h>
#include <cstdint>

#define BB 2
#define TT 2048
#define DD 1024
#define HH 16
#define HD 64

// ---- scratch (device globals: allocation-free) ----
__device__ float g_ln [(size_t)BB*TT*DD];
__device__ float g_q  [(size_t)BB*TT*DD];          // [B,H,T,hd]
__device__ float g_k  [(size_t)BB*TT*DD];
__device__ float g_v  [(size_t)BB*TT*DD];
__device__ float g_ctx[(size_t)BB*TT*DD];          // [B,T,D]
__device__ float g_h  [(size_t)BB*TT*DD];
__device__ float g_s  [(size_t)BB*HH*TT*TT];       // 512 MB scores/attn

// ===========================================================================
// helpers
// ===========================================================================
__device__ __forceinline__ uint32_t f2tf(float x) {   // round-to-nearest tf32
    uint32_t u;
    asm("cvt.rna.tf32.f32 %0, %1;" : "=r"(u) : "f"(x));
    return u;
}

// D += A(16x8) @ B(8x8), tf32 inputs, f32 accum. Baseline sm_80+ feature.
__device__ __forceinline__ void mma8(float* c, const uint32_t* a, const uint32_t* b) {
    asm volatile(
        "mma.sync.aligned.m16n8k8.row.col.f32.tf32.tf32.f32 "
        "{%0,%1,%2,%3}, {%4,%5,%6,%7}, {%8,%9}, {%0,%1,%2,%3};"
        : "+f"(c[0]), "+f"(c[1]), "+f"(c[2]), "+f"(c[3])
        : "r"(a[0]), "r"(a[1]), "r"(a[2]), "r"(a[3]), "r"(b[0]), "r"(b[1]));
}

#define PAD 36   // smem row stride in floats (conflict-free fragment LDS)

// ===========================================================================
// Dense GEMM: C[4096,1024] = A[4096,1024] @ W[1024,1024]^T  (both row-major,
// k contiguous -> mma.row.col). BM=BN=128, BK=32. 8 warps: 2(M)x4(N),
// warp tile 64x32 = 4 Mtiles x 4 Ntiles of m16n8.
//   MODE 0: scatter C into [B,H,T,hd]
//   MODE 1: out = res + bias + C (row-major)
// ===========================================================================
template <int MODE>
__global__ __launch_bounds__(256)
void mma_gemm(const float* __restrict__ A, const float* __restrict__ W,
              const float* __restrict__ bias, const float* __restrict__ res,
              float* __restrict__ out) {
    __shared__ uint32_t As[128 * PAD];
    __shared__ uint32_t Bs[128 * PAD];
    int tid = threadIdx.x, lane = tid & 31, warp = tid >> 5;
    int wm = (warp >> 2) * 64, wn = (warp & 3) * 32;
    int g = lane >> 2, t = lane & 3;
    int m0 = blockIdx.y * 128, n0 = blockIdx.x * 128;

    float acc[4][4][4] = {};
    float4 pa[4], pb[4];

    // prime: tile kt=0 -> regs -> smem
#pragma unroll
    for (int i = 0; i < 4; i++) {
        int f = tid + i * 256, row = f >> 3, c4 = (f & 7) * 4;
        pa[i] = *(const float4*)(A + (size_t)(m0 + row) * DD + c4);
        pb[i] = *(const float4*)(W + (size_t)(n0 + row) * DD + c4);
    }
#pragma unroll
    for (int i = 0; i < 4; i++) {
        int f = tid + i * 256, row = f >> 3, c4 = (f & 7) * 4, s = row * PAD + c4;
        As[s] = f2tf(pa[i].x); As[s+1] = f2tf(pa[i].y); As[s+2] = f2tf(pa[i].z); As[s+3] = f2tf(pa[i].w);
        Bs[s] = f2tf(pb[i].x); Bs[s+1] = f2tf(pb[i].y); Bs[s+2] = f2tf(pb[i].z); Bs[s+3] = f2tf(pb[i].w);
    }
    __syncthreads();

    for (int kt = 0; kt < DD / 32; kt++) {
        if (kt + 1 < DD / 32) {
            int k0 = (kt + 1) * 32;
#pragma unroll
            for (int i = 0; i < 4; i++) {
                int f = tid + i * 256, row = f >> 3, c4 = (f & 7) * 4;
                pa[i] = *(const float4*)(A + (size_t)(m0 + row) * DD + k0 + c4);
                pb[i] = *(const float4*)(W + (size_t)(n0 + row) * DD + k0 + c4);
            }
        }
#pragma unroll
        for (int kk = 0; kk < 4; kk++) {
            int kb = kk * 8;
            uint32_t af[4][4], bf[4][2];
#pragma unroll
            for (int i = 0; i < 4; i++) {
                int r = wm + i * 16;
                af[i][0] = As[(r + g) * PAD + kb + t];
                af[i][1] = As[(r + g + 8) * PAD + kb + t];
                af[i][2] = As[(r + g) * PAD + kb + t + 4];
                af[i][3] = As[(r + g + 8) * PAD + kb + t + 4];
            }
#pragma unroll
            for (int j = 0; j < 4; j++) {
                int c = wn + j * 8;
                bf[j][0] = Bs[(c + g) * PAD + kb + t];
                bf[j][1] = Bs[(c + g) * PAD + kb + t + 4];
            }
#pragma unroll
            for (int i = 0; i < 4; i++)
#pragma unroll
                for (int j = 0; j < 4; j++)
                    mma8(acc[i][j], af[i], bf[j]);
        }
        if (kt + 1 < DD / 32) {
            __syncthreads();
#pragma unroll
            for (int i = 0; i < 4; i++) {
                int f = tid + i * 256, row = f >> 3, c4 = (f & 7) * 4, s = row * PAD + c4;
                As[s] = f2tf(pa[i].x); As[s+1] = f2tf(pa[i].y); As[s+2] = f2tf(pa[i].z); As[s+3] = f2tf(pa[i].w);
                Bs[s] = f2tf(pb[i].x); Bs[s+1] = f2tf(pb[i].y); Bs[s+2] = f2tf(pb[i].z); Bs[s+3] = f2tf(pb[i].w);
            }
            __syncthreads();
        }
    }

#pragma unroll
    for (int i = 0; i < 4; i++) {
        int row = m0 + wm + i * 16 + g;
#pragma unroll
        for (int j = 0; j < 4; j++) {
            int col = n0 + wn + j * 8 + 2 * t;
            if (MODE == 0) {
                int b = row >> 11, tt = row & 2047;
                int h = col >> 6, d = col & 63;
                float* d0 = out + (((size_t)(b * HH + h)) * TT + tt) * HD + d;
                float* d1 = out + (((size_t)(b * HH + h)) * TT + tt + 8) * HD + d;
                *(float2*)d0 = make_float2(acc[i][j][0], acc[i][j][1]);
                *(float2*)d1 = make_float2(acc[i][j][2], acc[i][j][3]);
            } else {
                float2 b2 = *(const float2*)(bias + col);
                float2 r0 = *(const float2*)(res + (size_t)row * DD + col);
                float2 r1 = *(const float2*)(res + (size_t)(row + 8) * DD + col);
                *(float2*)(out + (size_t)row * DD + col) =
                    make_float2(acc[i][j][0] + r0.x + b2.x, acc[i][j][1] + r0.y + b2.y);
                *(float2*)(out + (size_t)(row + 8) * DD + col) =
                    make_float2(acc[i][j][2] + r1.x + b2.x, acc[i][j][3] + r1.y + b2.y);
            }
        }
    }
}

// ===========================================================================
// Scores: per (b,h) S = Q @ K^T. M=N=2048, K=64. Same tile shape, 2 K-iters.
// Causal: skip tiles with n0 > m0.
// ===========================================================================
__global__ __launch_bounds__(256)
void mma_scores(const float* __restrict__ Q, const float* __restrict__ Kt,
                float* __restrict__ S) {
    int m0 = blockIdx.y * 128, n0 = blockIdx.x * 128;
    if (n0 > m0) return;
    int bh = blockIdx.z;
    const float* Qb = Q  + (size_t)bh * TT * HD;
    const float* Kb = Kt + (size_t)bh * TT * HD;
    float* Sb = S + (size_t)bh * TT * TT;

    __shared__ uint32_t As[128 * PAD];
    __shared__ uint32_t Bs[128 * PAD];
    int tid = threadIdx.x, lane = tid & 31, warp = tid >> 5;
    int wm = (warp >> 2) * 64, wn = (warp & 3) * 32;
    int g = lane >> 2, t = lane & 3;

    float acc[4][4][4] = {};
    for (int kt = 0; kt < 2; kt++) {
        int k0 = kt * 32;
        if (kt) __syncthreads();
#pragma unroll
        for (int i = 0; i < 4; i++) {
            int f = tid + i * 256, row = f >> 3, c4 = (f & 7) * 4, s = row * PAD + c4;
            float4 av = *(const float4*)(Qb + (size_t)(m0 + row) * HD + k0 + c4);
            float4 bv = *(const float4*)(Kb + (size_t)(n0 + row) * HD + k0 + c4);
            As[s] = f2tf(av.x); As[s+1] = f2tf(av.y); As[s+2] = f2tf(av.z); As[s+3] = f2tf(av.w);
            Bs[s] = f2tf(bv.x); Bs[s+1] = f2tf(bv.y); Bs[s+2] = f2tf(bv.z); Bs[s+3] = f2tf(bv.w);
        }
        __syncthreads();
#pragma unroll
        for (int kk = 0; kk < 4; kk++) {
            int kb = kk * 8;
            uint32_t af[4][4], bf[4][2];
#pragma unroll
            for (int i = 0; i < 4; i++) {
                int r = wm + i * 16;
                af[i][0] = As[(r + g) * PAD + kb + t];
                af[i][1] = As[(r + g + 8) * PAD + kb + t];
                af[i][2] = As[(r + g) * PAD + kb + t + 4];
                af[i][3] = As[(r + g + 8) * PAD + kb + t + 4];
            }
#pragma unroll
            for (int j = 0; j < 4; j++) {
                int c = wn + j * 8;
                bf[j][0] = Bs[(c + g) * PAD + kb + t];
                bf[j][1] = Bs[(c + g) * PAD + kb + t + 4];
            }
#pragma unroll
            for (int i = 0; i < 4; i++)
#pragma unroll
                for (int j = 0; j < 4; j++)
                    mma8(acc[i][j], af[i], bf[j]);
        }
    }
#pragma unroll
    for (int i = 0; i < 4; i++) {
        int row = m0 + wm + i * 16 + g;
#pragma unroll
        for (int j = 0; j < 4; j++) {
            int col = n0 + wn + j * 8 + 2 * t;
            *(float2*)(Sb + (size_t)row * TT + col) = make_float2(acc[i][j][0], acc[i][j][1]);
            *(float2*)(Sb + (size_t)(row + 8) * TT + col) = make_float2(acc[i][j][2], acc[i][j][3]);
        }
    }
}

// ===========================================================================
// Causal softmax (scores/8), zero-fill to 128-tile edge (ctx reads to there)
// ===========================================================================
__global__ void softmax_kernel(float* __restrict__ S) {
    int idx = blockIdx.x;
    int q = idx & (TT - 1);
    int bh = idx >> 11;
    float* row = S + (size_t)bh * TT * TT + (size_t)q * TT;
    int n = q + 1;
    int tid = threadIdx.x;
    __shared__ float sh[128];

    float mx = -1e30f;
    for (int j = tid; j < n; j += 128) mx = fmaxf(mx, row[j] * 0.125f);
    sh[tid] = mx; __syncthreads();
    for (int o = 64; o > 0; o >>= 1) {
        if (tid < o) sh[tid] = fmaxf(sh[tid], sh[tid + o]);
        __syncthreads();
    }
    mx = sh[0];
    __syncthreads();

    float sum = 0.f;
    for (int j = tid; j < n; j += 128) {
        float e = __expf(row[j] * 0.125f - mx);
        row[j] = e;
        sum += e;
    }
    sh[tid] = sum; __syncthreads();
    for (int o = 64; o > 0; o >>= 1) {
        if (tid < o) sh[tid] += sh[tid + o];
        __syncthreads();
    }
    float inv = 1.f / sh[0];
    for (int j = tid; j < n; j += 128) row[j] *= inv;
    int zend = ((q >> 7) + 1) << 7;       // 128-tile edge
    for (int j = n + tid; j < zend; j += 128) row[j] = 0.f;
}

// ===========================================================================
// ctx = attn @ V per (b,h). M=2048, N=64, K<=m0+128 (causal). BM=128, BN=64,
// BK=32. 8 warps: 4(M)x2(N), warp tile 32x32 = 2 Mtiles x 4 Ntiles.
// V is [k][n] row-major (n contiguous) -> transpose into Bs[n][k] on load.
// ===========================================================================
__global__ __launch_bounds__(256)
void mma_ctx(const float* __restrict__ S, const float* __restrict__ V,
             float* __restrict__ C) {
    int bh = blockIdx.z;
    int m0 = blockIdx.y * 128;
    const float* Sb = S + (size_t)bh * TT * TT;
    const float* Vb = V + (size_t)bh * TT * HD;

    __shared__ uint32_t As[128 * PAD];
    __shared__ uint32_t Bs[64 * PAD];
    int tid = threadIdx.x, lane = tid & 31, warp = tid >> 5;
    int wm = (warp >> 1) * 32, wn = (warp & 1) * 32;
    int g = lane >> 2, t = lane & 3;

    float acc[2][4][4] = {};
    int nkt = (m0 + 128) / 32;
    float4 pa[4], pv[2];

    // prime kt=0
#pragma unroll
    for (int i = 0; i < 4; i++) {
        int f = tid + i * 256, row = f >> 3, c4 = (f & 7) * 4;
        pa[i] = *(const float4*)(Sb + (size_t)(m0 + row) * TT + c4);
    }
#pragma unroll
    for (int i = 0; i < 2; i++) {
        int f = tid + i * 256, kr = f >> 4, c4 = (f & 15) * 4;
        pv[i] = *(const float4*)(Vb + (size_t)kr * HD + c4);
    }
#pragma unroll
    for (int i = 0; i < 4; i++) {
        int f = tid + i * 256, row = f >> 3, c4 = (f & 7) * 4, s = row * PAD + c4;
        As[s] = f2tf(pa[i].x); As[s+1] = f2tf(pa[i].y); As[s+2] = f2tf(pa[i].z); As[s+3] = f2tf(pa[i].w);
    }
#pragma unroll
    for (int i = 0; i < 2; i++) {
        int f = tid + i * 256, kr = f >> 4, c4 = (f & 15) * 4;
        Bs[(c4 + 0) * PAD + kr] = f2tf(pv[i].x);
        Bs[(c4 + 1) * PAD + kr] = f2tf(pv[i].y);
        Bs[(c4 + 2) * PAD + kr] = f2tf(pv[i].z);
        Bs[(c4 + 3) * PAD + kr] = f2tf(pv[i].w);
    }
    __syncthreads();

    for (int kt = 0; kt < nkt; kt++) {
        if (kt + 1 < nkt) {
            int k0 = (kt + 1) * 32;
#pragma unroll
            for (int i = 0; i < 4; i++) {
                int f = tid + i * 256, row = f >> 3, c4 = (f & 7) * 4;
                pa[i] = *(const float4*)(Sb + (size_t)(m0 + row) * TT + k0 + c4);
            }
#pragma unroll
            for (int i = 0; i < 2; i++) {
                int f = tid + i * 256, kr = f >> 4, c4 = (f & 15) * 4;
                pv[i] = *(const float4*)(Vb + (size_t)(k0 + kr) * HD + c4);
            }
        }
#pragma unroll
        for (int kk = 0; kk < 4; kk++) {
            int kb = kk * 8;
            uint32_t af[2][4], bf[4][2];
#pragma unroll
            for (int i = 0; i < 2; i++) {
                int r = wm + i * 16;
                af[i][0] = As[(r + g) * PAD + kb + t];
                af[i][1] = As[(r + g + 8) * PAD + kb + t];
                af[i][2] = As[(r + g) * PAD + kb + t + 4];
                af[i][3] = As[(r + g + 8) * PAD + kb + t + 4];
            }
#pragma unroll
            for (int j = 0; j < 4; j++) {
                int c = wn + j * 8;
                bf[j][0] = Bs[(c + g) * PAD + kb + t];
                bf[j][1] = Bs[(c + g) * PAD + kb + t + 4];
            }
#pragma unroll
            for (int i = 0; i < 2; i++)
#pragma unroll
                for (int j = 0; j < 4; j++)
                    mma8(acc[i][j], af[i], bf[j]);
        }
        if (kt + 1 < nkt) {
            __syncthreads();
#pragma unroll
            for (int i = 0; i < 4; i++) {
                int f = tid + i * 256, row = f >> 3, c4 = (f & 7) * 4, s = row * PAD + c4;
                As[s] = f2tf(pa[i].x); As[s+1] = f2tf(pa[i].y); As[s+2] = f2tf(pa[i].z); As[s+3] = f2tf(pa[i].w);
            }
#pragma unroll
            for (int i = 0; i < 2; i++) {
                int f = tid + i * 256, kr = f >> 4, c4 = (f & 15) * 4;
                Bs[(c4 + 0) * PAD + kr] = f2tf(pv[i].x);
                Bs[(c4 + 1) * PAD + kr] = f2tf(pv[i].y);
                Bs[(c4 + 2) * PAD + kr] = f2tf(pv[i].z);
                Bs[(c4 + 3) * PAD + kr] = f2tf(pv[i].w);
            }
            __syncthreads();
        }
    }

    int b = bh >> 4, h = bh & 15;
#pragma unroll
    for (int i = 0; i < 2; i++) {
        int q = m0 + wm + i * 16 + g;
#pragma unroll
        for (int j = 0; j < 4; j++) {
            int col = wn + j * 8 + 2 * t;
            *(float2*)(C + ((size_t)(b * TT + q)) * DD + h * HD + col) =
                make_float2(acc[i][j][0], acc[i][j][1]);
            *(float2*)(C + ((size_t)(b * TT + q + 8)) * DD + h * HD + col) =
                make_float2(acc[i][j][2], acc[i][j][3]);
        }
    }
}

// ---------------------------------------------------------------------------
// LayerNorm (faithful bug: scale * x_norm + scale)
// ---------------------------------------------------------------------------
__global__ void ln_kernel(const float* __restrict__ x,
                          const float* __restrict__ scale,
                          float* __restrict__ y) {
    int row = blockIdx.x;
    const float* xr = x + (size_t)row * DD;
    float* yr = y + (size_t)row * DD;
    int tid = threadIdx.x;
    float v[4];
    float s = 0.f, s2 = 0.f;
#pragma unroll
    for (int i = 0; i < 4; i++) {
        v[i] = xr[tid + 256 * i];
        s  += v[i];
        s2 += v[i] * v[i];
    }
    __shared__ float sh[256], sh2[256];
    sh[tid] = s; sh2[tid] = s2;
    __syncthreads();
    for (int o = 128; o > 0; o >>= 1) {
        if (tid < o) { sh[tid] += sh[tid + o]; sh2[tid] += sh2[tid + o]; }
        __syncthreads();
    }
    float mean = sh[0] * (1.f / DD);
    float var  = sh2[0] * (1.f / DD) - mean * mean;
    float rstd = rsqrtf(var + 1e-5f);
#pragma unroll
    for (int i = 0; i < 4; i++) {
        int c = tid + 256 * i;
        float sc = scale[c];
        yr[c] = sc * ((v[i] - mean) * rstd) + sc;
    }
}

// ---------------------------------------------------------------------------
// Host driver
// ---------------------------------------------------------------------------
static void run_block(const float* x_in, const float* ln_scale,
                      const float* wq, const float* wk, const float* wv,
                      const float* wo, const float* bo,
                      float* lnp, float* qp, float* kp, float* vp,
                      float* sp, float* ctxp, float* out) {
    dim3 gG(DD / 128, (BB * TT) / 128);                 // (8, 32)
    ln_kernel<<<BB * TT, 256>>>(x_in, ln_scale, lnp);
    mma_gemm<0><<<gG, 256>>>(lnp, wq, nullptr, nullptr, qp);
    mma_gemm<0><<<gG, 256>>>(lnp, wk, nullptr, nullptr, kp);
    mma_gemm<0><<<gG, 256>>>(lnp, wv, nullptr, nullptr, vp);
    mma_scores<<<dim3(TT / 128, TT / 128, BB * HH), 256>>>(qp, kp, sp);
    softmax_kernel<<<BB * HH * TT, 128>>>(sp);
    mma_ctx<<<dim3(1, TT / 128, BB * HH), 256>>>(sp, vp, ctxp);
    mma_gemm<1><<<gG, 256>>>(ctxp, wo, bo, x_in, out);
}

extern "C" void kernel_launch(void* const* d_in, const int* in_sizes, int n_in,
                              void* d_out, int out_size) {
    const float* x   = (const float*)d_in[0];
    const float* wq  = (const float*)d_in[1];
    const float* wk  = (const float*)d_in[2];
    const float* wv  = (const float*)d_in[3];
    const float* wo  = (const float*)d_in[4];
    const float* bo  = (const float*)d_in[5];
    const float* ln1 = (const float*)d_in[6];
    const float* ln2 = (const float*)d_in[7];
    float* out = (float*)d_out;

    float *lnp, *qp, *kp, *vp, *sp, *ctxp, *hp;
    cudaGetSymbolAddress((void**)&lnp,  g_ln);
    cudaGetSymbolAddress((void**)&qp,   g_q);
    cudaGetSymbolAddress((void**)&kp,   g_k);
    cudaGetSymbolAddress((void**)&vp,   g_v);
    cudaGetSymbolAddress((void**)&sp,   g_s);
    cudaGetSymbolAddress((void**)&ctxp, g_ctx);
    cudaGetSymbolAddress((void**)&hp,   g_h);

    run_block(x,  ln1, wq, wk, wv, wo, bo, lnp, qp, kp, vp, sp, ctxp, hp);
    run_block(hp, ln2, wq, wk, wv, wo, bo, lnp, qp, kp, vp, sp, ctxp, out);
}

// round 6
// speedup vs baseline: 3.3511x; 1.3622x over previous
#include <cuda_runtime.h>
#include <cstdint>

#define BB 2
#define TT 2048
#define DD 1024
#define HH 16
#define HD 64

// ---- scratch (device globals: allocation-free) ----
__device__ float g_ln [(size_t)BB*TT*DD];
__device__ float g_q  [(size_t)BB*TT*DD];          // [B,H,T,hd]
__device__ float g_k  [(size_t)BB*TT*DD];
__device__ float g_v  [(size_t)BB*TT*DD];
__device__ float g_ctx[(size_t)BB*TT*DD];          // [B,T,D]
__device__ float g_h  [(size_t)BB*TT*DD];

// ===========================================================================
// helpers
// ===========================================================================
__device__ __forceinline__ uint32_t f2tf(float x) {   // round-to-nearest tf32
    uint32_t u;
    asm("cvt.rna.tf32.f32 %0, %1;" : "=r"(u) : "f"(x));
    return u;
}

// D += A(16x8) @ B(8x8), tf32 inputs, f32 accum.
__device__ __forceinline__ void mma8(float* c, const uint32_t* a, const uint32_t* b) {
    asm volatile(
        "mma.sync.aligned.m16n8k8.row.col.f32.tf32.tf32.f32 "
        "{%0,%1,%2,%3}, {%4,%5,%6,%7}, {%8,%9}, {%0,%1,%2,%3};"
        : "+f"(c[0]), "+f"(c[1]), "+f"(c[2]), "+f"(c[3])
        : "r"(a[0]), "r"(a[1]), "r"(a[2]), "r"(a[3]), "r"(b[0]), "r"(b[1]));
}

#define PAD 36    // dense-GEMM smem row stride (BK=32 + 4)
#define KPAD 68   // flash K tile row stride (64 + 4): frag banks g*4+t, bijective
#define VPAD 72   // flash V tile row stride (64 + 8): frag banks t*8+g, bijective
#define FULL 0xffffffffu

// ===========================================================================
// Dense GEMM: C[4096,1024] = A @ W^T. BM=BN=128, BK=32, 8 warps 2x4,
// warp tile 64x32. MODE 0: scatter into [B,H,T,hd]; MODE 1: +res+bias.
// ===========================================================================
template <int MODE>
__global__ __launch_bounds__(256)
void mma_gemm(const float* __restrict__ A, const float* __restrict__ W,
              const float* __restrict__ bias, const float* __restrict__ res,
              float* __restrict__ out) {
    __shared__ uint32_t As[128 * PAD];
    __shared__ uint32_t Bs[128 * PAD];
    int tid = threadIdx.x, lane = tid & 31, warp = tid >> 5;
    int wm = (warp >> 2) * 64, wn = (warp & 3) * 32;
    int g = lane >> 2, t = lane & 3;
    int m0 = blockIdx.y * 128, n0 = blockIdx.x * 128;

    float acc[4][4][4] = {};
    float4 pa[4], pb[4];

#pragma unroll
    for (int i = 0; i < 4; i++) {
        int f = tid + i * 256, row = f >> 3, c4 = (f & 7) * 4;
        pa[i] = *(const float4*)(A + (size_t)(m0 + row) * DD + c4);
        pb[i] = *(const float4*)(W + (size_t)(n0 + row) * DD + c4);
    }
#pragma unroll
    for (int i = 0; i < 4; i++) {
        int f = tid + i * 256, row = f >> 3, c4 = (f & 7) * 4, s = row * PAD + c4;
        As[s] = f2tf(pa[i].x); As[s+1] = f2tf(pa[i].y); As[s+2] = f2tf(pa[i].z); As[s+3] = f2tf(pa[i].w);
        Bs[s] = f2tf(pb[i].x); Bs[s+1] = f2tf(pb[i].y); Bs[s+2] = f2tf(pb[i].z); Bs[s+3] = f2tf(pb[i].w);
    }
    __syncthreads();

    for (int kt = 0; kt < DD / 32; kt++) {
        if (kt + 1 < DD / 32) {
            int k0 = (kt + 1) * 32;
#pragma unroll
            for (int i = 0; i < 4; i++) {
                int f = tid + i * 256, row = f >> 3, c4 = (f & 7) * 4;
                pa[i] = *(const float4*)(A + (size_t)(m0 + row) * DD + k0 + c4);
                pb[i] = *(const float4*)(W + (size_t)(n0 + row) * DD + k0 + c4);
            }
        }
#pragma unroll
        for (int kk = 0; kk < 4; kk++) {
            int kb = kk * 8;
            uint32_t af[4][4], bf[4][2];
#pragma unroll
            for (int i = 0; i < 4; i++) {
                int r = wm + i * 16;
                af[i][0] = As[(r + g) * PAD + kb + t];
                af[i][1] = As[(r + g + 8) * PAD + kb + t];
                af[i][2] = As[(r + g) * PAD + kb + t + 4];
                af[i][3] = As[(r + g + 8) * PAD + kb + t + 4];
            }
#pragma unroll
            for (int j = 0; j < 4; j++) {
                int c = wn + j * 8;
                bf[j][0] = Bs[(c + g) * PAD + kb + t];
                bf[j][1] = Bs[(c + g) * PAD + kb + t + 4];
            }
#pragma unroll
            for (int i = 0; i < 4; i++)
#pragma unroll
                for (int j = 0; j < 4; j++)
                    mma8(acc[i][j], af[i], bf[j]);
        }
        if (kt + 1 < DD / 32) {
            __syncthreads();
#pragma unroll
            for (int i = 0; i < 4; i++) {
                int f = tid + i * 256, row = f >> 3, c4 = (f & 7) * 4, s = row * PAD + c4;
                As[s] = f2tf(pa[i].x); As[s+1] = f2tf(pa[i].y); As[s+2] = f2tf(pa[i].z); As[s+3] = f2tf(pa[i].w);
                Bs[s] = f2tf(pb[i].x); Bs[s+1] = f2tf(pb[i].y); Bs[s+2] = f2tf(pb[i].z); Bs[s+3] = f2tf(pb[i].w);
            }
            __syncthreads();
        }
    }

#pragma unroll
    for (int i = 0; i < 4; i++) {
        int row = m0 + wm + i * 16 + g;
#pragma unroll
        for (int j = 0; j < 4; j++) {
            int col = n0 + wn + j * 8 + 2 * t;
            if (MODE == 0) {
                int b = row >> 11, tt = row & 2047;
                int h = col >> 6, d = col & 63;
                float* d0 = out + (((size_t)(b * HH + h)) * TT + tt) * HD + d;
                float* d1 = out + (((size_t)(b * HH + h)) * TT + tt + 8) * HD + d;
                *(float2*)d0 = make_float2(acc[i][j][0], acc[i][j][1]);
                *(float2*)d1 = make_float2(acc[i][j][2], acc[i][j][3]);
            } else {
                float2 b2 = *(const float2*)(bias + col);
                float2 r0 = *(const float2*)(res + (size_t)row * DD + col);
                float2 r1 = *(const float2*)(res + (size_t)(row + 8) * DD + col);
                *(float2*)(out + (size_t)row * DD + col) =
                    make_float2(acc[i][j][0] + r0.x + b2.x, acc[i][j][1] + r0.y + b2.y);
                *(float2*)(out + (size_t)(row + 8) * DD + col) =
                    make_float2(acc[i][j][2] + r1.x + b2.x, acc[i][j][3] + r1.y + b2.y);
            }
        }
    }
}

// ===========================================================================
// Fused flash attention: per CTA = (q-tile of 128 rows, bh).
// 8 warps x 16 q-rows. KV streamed in 64-token tiles. Online softmax in
// registers (row stats within each quad). P never hits smem: C-frag -> A-frag
// via quad shuffles. Output written to ctx layout [B,T,D]. scale = 0.125.
// ===========================================================================
__global__ __launch_bounds__(256)
void flash_attn(const float* __restrict__ Q, const float* __restrict__ K,
                const float* __restrict__ V, float* __restrict__ C) {
    __shared__ uint32_t Ks[64 * KPAD];   // [token][hd]
    __shared__ uint32_t Vs[64 * VPAD];   // [token][hd]

    int bh = blockIdx.y;
    int m0 = blockIdx.x * 128;
    const float* Qb = Q + (size_t)bh * TT * HD;
    const float* Kb = K + (size_t)bh * TT * HD;
    const float* Vb = V + (size_t)bh * TT * HD;

    int tid = threadIdx.x, lane = tid & 31, warp = tid >> 5;
    int wm = warp * 16;
    int g = lane >> 2, t = lane & 3;
    int row0 = m0 + wm + g, row1 = row0 + 8;

    // Q fragments (16 x 64) in registers: 8 k-steps x 4 regs
    uint32_t qf[8][4];
#pragma unroll
    for (int ks = 0; ks < 8; ks++) {
        int kb = ks * 8;
        qf[ks][0] = f2tf(Qb[(size_t)row0 * HD + kb + t]);
        qf[ks][1] = f2tf(Qb[(size_t)row1 * HD + kb + t]);
        qf[ks][2] = f2tf(Qb[(size_t)row0 * HD + kb + t + 4]);
        qf[ks][3] = f2tf(Qb[(size_t)row1 * HD + kb + t + 4]);
    }

    float o[8][4] = {};
    float rmax0 = -1e30f, rmax1 = -1e30f;
    float rsum0 = 0.f, rsum1 = 0.f;      // per-lane partial (quad-reduced at end)

    int nkv = (m0 + 128) / 64;
    for (int kv = 0; kv < nkv; kv++) {
        int kv0 = kv * 64;
        // ---- load full 64x64 K and V tiles (1024 float4 each) ----
#pragma unroll
        for (int i = 0; i < 4; i++) {
            int f = tid + i * 256;             // 0..1023
            int r = f >> 4, c4 = (f & 15) * 4;
            float4 kvl = *(const float4*)(Kb + (size_t)(kv0 + r) * HD + c4);
            int sk = r * KPAD + c4;
            Ks[sk] = f2tf(kvl.x); Ks[sk+1] = f2tf(kvl.y);
            Ks[sk+2] = f2tf(kvl.z); Ks[sk+3] = f2tf(kvl.w);
            float4 vv = *(const float4*)(Vb + (size_t)(kv0 + r) * HD + c4);
            int sv = r * VPAD + c4;
            Vs[sv] = f2tf(vv.x); Vs[sv+1] = f2tf(vv.y);
            Vs[sv+2] = f2tf(vv.z); Vs[sv+3] = f2tf(vv.w);
        }
        __syncthreads();

        // ---- S = Q @ K^T (16 x 64) ----
        float s[8][4];
#pragma unroll
        for (int j = 0; j < 8; j++) { s[j][0]=0.f; s[j][1]=0.f; s[j][2]=0.f; s[j][3]=0.f; }
#pragma unroll
        for (int ks = 0; ks < 8; ks++) {
            int kb = ks * 8;
#pragma unroll
            for (int j = 0; j < 8; j++) {
                uint32_t bf[2];
                bf[0] = Ks[(j * 8 + g) * KPAD + kb + t];
                bf[1] = Ks[(j * 8 + g) * KPAD + kb + t + 4];
                mma8(s[j], qf[ks], bf);
            }
        }

        // ---- scale + causal mask ----
        bool need_mask = (kv0 + 64 > m0);
#pragma unroll
        for (int j = 0; j < 8; j++) {
            int c0 = kv0 + j * 8 + 2 * t, c1 = c0 + 1;
            s[j][0] *= 0.125f; s[j][1] *= 0.125f; s[j][2] *= 0.125f; s[j][3] *= 0.125f;
            if (need_mask) {
                if (c0 > row0) s[j][0] = -1e30f;
                if (c1 > row0) s[j][1] = -1e30f;
                if (c0 > row1) s[j][2] = -1e30f;
                if (c1 > row1) s[j][3] = -1e30f;
            }
        }

        // ---- online softmax ----
        float m0l = -1e30f, m1l = -1e30f;
#pragma unroll
        for (int j = 0; j < 8; j++) {
            m0l = fmaxf(m0l, fmaxf(s[j][0], s[j][1]));
            m1l = fmaxf(m1l, fmaxf(s[j][2], s[j][3]));
        }
        m0l = fmaxf(m0l, __shfl_xor_sync(FULL, m0l, 1));
        m0l = fmaxf(m0l, __shfl_xor_sync(FULL, m0l, 2));
        m1l = fmaxf(m1l, __shfl_xor_sync(FULL, m1l, 1));
        m1l = fmaxf(m1l, __shfl_xor_sync(FULL, m1l, 2));
        float mn0 = fmaxf(rmax0, m0l), mn1 = fmaxf(rmax1, m1l);
        float cr0 = __expf(rmax0 - mn0), cr1 = __expf(rmax1 - mn1);
        rmax0 = mn0; rmax1 = mn1;
        rsum0 *= cr0; rsum1 *= cr1;
#pragma unroll
        for (int j = 0; j < 8; j++) {
            o[j][0] *= cr0; o[j][1] *= cr0; o[j][2] *= cr1; o[j][3] *= cr1;
        }
        float ps0 = 0.f, ps1 = 0.f;
#pragma unroll
        for (int j = 0; j < 8; j++) {
            s[j][0] = __expf(s[j][0] - mn0); ps0 += s[j][0];
            s[j][1] = __expf(s[j][1] - mn0); ps0 += s[j][1];
            s[j][2] = __expf(s[j][2] - mn1); ps1 += s[j][2];
            s[j][3] = __expf(s[j][3] - mn1); ps1 += s[j][3];
        }
        rsum0 += ps0; rsum1 += ps1;

        // ---- P C-frag -> A-frag via quad shuffles ----
        uint32_t pa[8][4];
        int L0 = (lane & ~3) | (t >> 1);
        int L2 = L0 + 2;
        bool odd = (t & 1);
#pragma unroll
        for (int j = 0; j < 8; j++) {
            float x00 = __shfl_sync(FULL, s[j][0], L0);
            float x01 = __shfl_sync(FULL, s[j][1], L0);
            float x20 = __shfl_sync(FULL, s[j][2], L0);
            float x21 = __shfl_sync(FULL, s[j][3], L0);
            float y00 = __shfl_sync(FULL, s[j][0], L2);
            float y01 = __shfl_sync(FULL, s[j][1], L2);
            float y20 = __shfl_sync(FULL, s[j][2], L2);
            float y21 = __shfl_sync(FULL, s[j][3], L2);
            pa[j][0] = f2tf(odd ? x01 : x00);
            pa[j][1] = f2tf(odd ? x21 : x20);
            pa[j][2] = f2tf(odd ? y01 : y00);
            pa[j][3] = f2tf(odd ? y21 : y20);
        }

        // ---- O += P @ V ----
#pragma unroll
        for (int ks = 0; ks < 8; ks++) {
            int kb = ks * 8;
#pragma unroll
            for (int j = 0; j < 8; j++) {
                uint32_t bf[2];
                bf[0] = Vs[(kb + t) * VPAD + j * 8 + g];
                bf[1] = Vs[(kb + t + 4) * VPAD + j * 8 + g];
                mma8(o[j], pa[ks], bf);
            }
        }
        __syncthreads();
    }

    // ---- epilogue: normalize + write ctx [B,T,D] ----
    rsum0 += __shfl_xor_sync(FULL, rsum0, 1);
    rsum0 += __shfl_xor_sync(FULL, rsum0, 2);
    rsum1 += __shfl_xor_sync(FULL, rsum1, 1);
    rsum1 += __shfl_xor_sync(FULL, rsum1, 2);
    float i0 = 1.f / rsum0, i1 = 1.f / rsum1;

    int b = bh >> 4, h = bh & 15;
#pragma unroll
    for (int j = 0; j < 8; j++) {
        int col = j * 8 + 2 * t;
        *(float2*)(C + ((size_t)(b * TT + row0)) * DD + h * HD + col) =
            make_float2(o[j][0] * i0, o[j][1] * i0);
        *(float2*)(C + ((size_t)(b * TT + row1)) * DD + h * HD + col) =
            make_float2(o[j][2] * i1, o[j][3] * i1);
    }
}

// ---------------------------------------------------------------------------
// LayerNorm (faithful bug: scale * x_norm + scale)
// ---------------------------------------------------------------------------
__global__ void ln_kernel(const float* __restrict__ x,
                          const float* __restrict__ scale,
                          float* __restrict__ y) {
    int row = blockIdx.x;
    const float* xr = x + (size_t)row * DD;
    float* yr = y + (size_t)row * DD;
    int tid = threadIdx.x;
    float v[4];
    float s = 0.f, s2 = 0.f;
#pragma unroll
    for (int i = 0; i < 4; i++) {
        v[i] = xr[tid + 256 * i];
        s  += v[i];
        s2 += v[i] * v[i];
    }
    __shared__ float sh[256], sh2[256];
    sh[tid] = s; sh2[tid] = s2;
    __syncthreads();
    for (int o = 128; o > 0; o >>= 1) {
        if (tid < o) { sh[tid] += sh[tid + o]; sh2[tid] += sh2[tid + o]; }
        __syncthreads();
    }
    float mean = sh[0] * (1.f / DD);
    float var  = sh2[0] * (1.f / DD) - mean * mean;
    float rstd = rsqrtf(var + 1e-5f);
#pragma unroll
    for (int i = 0; i < 4; i++) {
        int c = tid + 256 * i;
        float sc = scale[c];
        yr[c] = sc * ((v[i] - mean) * rstd) + sc;
    }
}

// ---------------------------------------------------------------------------
// Host driver
// ---------------------------------------------------------------------------
static void run_block(const float* x_in, const float* ln_scale,
                      const float* wq, const float* wk, const float* wv,
                      const float* wo, const float* bo,
                      float* lnp, float* qp, float* kp, float* vp,
                      float* ctxp, float* out) {
    dim3 gG(DD / 128, (BB * TT) / 128);                 // (8, 32)
    ln_kernel<<<BB * TT, 256>>>(x_in, ln_scale, lnp);
    mma_gemm<0><<<gG, 256>>>(lnp, wq, nullptr, nullptr, qp);
    mma_gemm<0><<<gG, 256>>>(lnp, wk, nullptr, nullptr, kp);
    mma_gemm<0><<<gG, 256>>>(lnp, wv, nullptr, nullptr, vp);
    flash_attn<<<dim3(TT / 128, BB * HH), 256>>>(qp, kp, vp, ctxp);
    mma_gemm<1><<<gG, 256>>>(ctxp, wo, bo, x_in, out);
}

extern "C" void kernel_launch(void* const* d_in, const int* in_sizes, int n_in,
                              void* d_out, int out_size) {
    const float* x   = (const float*)d_in[0];
    const float* wq  = (const float*)d_in[1];
    const float* wk  = (const float*)d_in[2];
    const float* wv  = (const float*)d_in[3];
    const float* wo  = (const float*)d_in[4];
    const float* bo  = (const float*)d_in[5];
    const float* ln1 = (const float*)d_in[6];
    const float* ln2 = (const float*)d_in[7];
    float* out = (float*)d_out;

    float *lnp, *qp, *kp, *vp, *ctxp, *hp;
    cudaGetSymbolAddress((void**)&lnp,  g_ln);
    cudaGetSymbolAddress((void**)&qp,   g_q);
    cudaGetSymbolAddress((void**)&kp,   g_k);
    cudaGetSymbolAddress((void**)&vp,   g_v);
    cudaGetSymbolAddress((void**)&ctxp, g_ctx);
    cudaGetSymbolAddress((void**)&hp,   g_h);

    run_block(x,  ln1, wq, wk, wv, wo, bo, lnp, qp, kp, vp, ctxp, hp);
    run_block(hp, ln2, wq, wk, wv, wo, bo, lnp, qp, kp, vp, ctxp, out);
}

// round 7
// speedup vs baseline: 3.6515x; 1.0897x over previous
#include <cuda_runtime.h>
#include <cstdint>

#define BB 2
#define TT 2048
#define DD 1024
#define HH 16
#define HD 64

// ---- scratch (device globals: allocation-free). tf32 payloads as uint32 ----
__device__ uint32_t g_ln [(size_t)BB*TT*DD];
__device__ uint32_t g_q  [(size_t)BB*TT*DD];       // [B,H,T,hd] tf32
__device__ uint32_t g_k  [(size_t)BB*TT*DD];
__device__ uint32_t g_v  [(size_t)BB*TT*DD];
__device__ uint32_t g_ctx[(size_t)BB*TT*DD];       // [B,T,D] tf32
__device__ float    g_h  [(size_t)BB*TT*DD];       // block-1 output (fp32)
__device__ uint32_t g_w  [4][(size_t)DD*DD];       // wq,wk,wv,wo tf32

// ===========================================================================
// helpers
// ===========================================================================
__device__ __forceinline__ uint32_t f2tf(float x) {
    uint32_t u;
    asm("cvt.rna.tf32.f32 %0, %1;" : "=r"(u) : "f"(x));
    return u;
}
__device__ __forceinline__ void mma8(float* c, const uint32_t* a, const uint32_t* b) {
    asm volatile(
        "mma.sync.aligned.m16n8k8.row.col.f32.tf32.tf32.f32 "
        "{%0,%1,%2,%3}, {%4,%5,%6,%7}, {%8,%9}, {%0,%1,%2,%3};"
        : "+f"(c[0]), "+f"(c[1]), "+f"(c[2]), "+f"(c[3])
        : "r"(a[0]), "r"(a[1]), "r"(a[2]), "r"(a[3]), "r"(b[0]), "r"(b[1]));
}
__device__ __forceinline__ void ldsm4(uint32_t& r0, uint32_t& r1,
                                      uint32_t& r2, uint32_t& r3, uint32_t addr) {
    asm volatile("ldmatrix.sync.aligned.m8n8.x4.shared.b16 {%0,%1,%2,%3}, [%4];"
        : "=r"(r0), "=r"(r1), "=r"(r2), "=r"(r3) : "r"(addr));
}
__device__ __forceinline__ uint32_t s2u(const void* p) {
    return (uint32_t)__cvta_generic_to_shared(p);
}

#define PAD 36    // dense-GEMM smem row stride (words)
#define KPAD 68   // flash K tile row stride
#define VPAD 72   // flash V tile row stride
#define FULL 0xffffffffu

// ===========================================================================
// weight converter: fp32 -> tf32 (once per launch)
// ===========================================================================
__global__ void cvt_tf32(const float4* __restrict__ in, uint4* __restrict__ out) {
    int i = blockIdx.x * 256 + threadIdx.x;
    float4 v = in[i];
    out[i] = make_uint4(f2tf(v.x), f2tf(v.y), f2tf(v.z), f2tf(v.w));
}

// ===========================================================================
// Dense GEMM: C[4096,1024] = A @ W^T, A/W pre-converted tf32.
// BM=BN=128, BK=32, 8 warps 2x4, warp tile 64x32, ldmatrix fragment loads.
//   MODE 0: emit tf32 into [B,H,T,hd]; MODE 1: fp32 out = res + bias + C.
// ===========================================================================
template <int MODE>
__global__ __launch_bounds__(256)
void mma_gemm(const uint32_t* __restrict__ A, const uint32_t* __restrict__ W,
              const float* __restrict__ bias, const float* __restrict__ res,
              void* __restrict__ outv) {
    __shared__ uint32_t As[128 * PAD];
    __shared__ uint32_t Bs[128 * PAD];
    int tid = threadIdx.x, lane = tid & 31, warp = tid >> 5;
    int wm = (warp >> 2) * 64, wn = (warp & 3) * 32;
    int g = lane >> 2, t = lane & 3;
    int m0 = blockIdx.y * 128, n0 = blockIdx.x * 128;

    // ldmatrix per-lane addresses
    int lr = lane & 15, lcol = (lane >> 4) * 4;
    int br = (lane & 7) + ((lane & 16) >> 1);
    int bcol = (lane & 8) >> 1;
    uint32_t asb = s2u(As), bsb = s2u(Bs);
    uint32_t aA[4], bA[2];
#pragma unroll
    for (int i = 0; i < 4; i++) aA[i] = asb + 4 * ((wm + i * 16 + lr) * PAD + lcol);
#pragma unroll
    for (int jp = 0; jp < 2; jp++) bA[jp] = bsb + 4 * ((wn + jp * 16 + br) * PAD + bcol);

    float acc[4][4][4] = {};
    uint4 pa[4], pb[4];

#pragma unroll
    for (int i = 0; i < 4; i++) {
        int f = tid + i * 256, row = f >> 3, c4 = (f & 7) * 4;
        pa[i] = *(const uint4*)(A + (size_t)(m0 + row) * DD + c4);
        pb[i] = *(const uint4*)(W + (size_t)(n0 + row) * DD + c4);
    }
#pragma unroll
    for (int i = 0; i < 4; i++) {
        int f = tid + i * 256, row = f >> 3, c4 = (f & 7) * 4, s = row * PAD + c4;
        *(uint4*)(As + s) = pa[i];
        *(uint4*)(Bs + s) = pb[i];
    }
    __syncthreads();

    for (int kt = 0; kt < DD / 32; kt++) {
        if (kt + 1 < DD / 32) {
            int k0 = (kt + 1) * 32;
#pragma unroll
            for (int i = 0; i < 4; i++) {
                int f = tid + i * 256, row = f >> 3, c4 = (f & 7) * 4;
                pa[i] = *(const uint4*)(A + (size_t)(m0 + row) * DD + k0 + c4);
                pb[i] = *(const uint4*)(W + (size_t)(n0 + row) * DD + k0 + c4);
            }
        }
#pragma unroll
        for (int kk = 0; kk < 4; kk++) {
            int ko = kk * 32;                   // byte offset of k-block
            uint32_t af[4][4], bf[4][2];
#pragma unroll
            for (int i = 0; i < 4; i++)
                ldsm4(af[i][0], af[i][1], af[i][2], af[i][3], aA[i] + ko);
#pragma unroll
            for (int jp = 0; jp < 2; jp++)
                ldsm4(bf[2*jp][0], bf[2*jp][1], bf[2*jp+1][0], bf[2*jp+1][1], bA[jp] + ko);
#pragma unroll
            for (int i = 0; i < 4; i++)
#pragma unroll
                for (int j = 0; j < 4; j++)
                    mma8(acc[i][j], af[i], bf[j]);
        }
        if (kt + 1 < DD / 32) {
            __syncthreads();
#pragma unroll
            for (int i = 0; i < 4; i++) {
                int f = tid + i * 256, row = f >> 3, c4 = (f & 7) * 4, s = row * PAD + c4;
                *(uint4*)(As + s) = pa[i];
                *(uint4*)(Bs + s) = pb[i];
            }
            __syncthreads();
        }
    }

#pragma unroll
    for (int i = 0; i < 4; i++) {
        int row = m0 + wm + i * 16 + g;
#pragma unroll
        for (int j = 0; j < 4; j++) {
            int col = n0 + wn + j * 8 + 2 * t;
            if (MODE == 0) {
                uint32_t* out = (uint32_t*)outv;
                int b = row >> 11, tt = row & 2047;
                int h = col >> 6, d = col & 63;
                uint32_t* d0 = out + (((size_t)(b * HH + h)) * TT + tt) * HD + d;
                uint32_t* d1 = out + (((size_t)(b * HH + h)) * TT + tt + 8) * HD + d;
                *(uint2*)d0 = make_uint2(f2tf(acc[i][j][0]), f2tf(acc[i][j][1]));
                *(uint2*)d1 = make_uint2(f2tf(acc[i][j][2]), f2tf(acc[i][j][3]));
            } else {
                float* out = (float*)outv;
                float2 b2 = *(const float2*)(bias + col);
                float2 r0 = *(const float2*)(res + (size_t)row * DD + col);
                float2 r1 = *(const float2*)(res + (size_t)(row + 8) * DD + col);
                *(float2*)(out + (size_t)row * DD + col) =
                    make_float2(acc[i][j][0] + r0.x + b2.x, acc[i][j][1] + r0.y + b2.y);
                *(float2*)(out + (size_t)(row + 8) * DD + col) =
                    make_float2(acc[i][j][2] + r1.x + b2.x, acc[i][j][3] + r1.y + b2.y);
            }
        }
    }
}

// ===========================================================================
// Fused flash attention (tf32 in/out). Per CTA: 128 q-rows x one bh.
// 8 warps x 16 rows; KV in 64-token smem tiles; K-frags via ldmatrix;
// online softmax in registers; P transposed C->A via quad shuffles.
// ===========================================================================
__global__ __launch_bounds__(256)
void flash_attn(const uint32_t* __restrict__ Q, const uint32_t* __restrict__ K,
                const uint32_t* __restrict__ V, uint32_t* __restrict__ C) {
    __shared__ uint32_t Ks[64 * KPAD];
    __shared__ uint32_t Vs[64 * VPAD];

    int bh = blockIdx.y;
    int m0 = blockIdx.x * 128;
    const uint32_t* Qb = Q + (size_t)bh * TT * HD;
    const uint32_t* Kb = K + (size_t)bh * TT * HD;
    const uint32_t* Vb = V + (size_t)bh * TT * HD;

    int tid = threadIdx.x, lane = tid & 31, warp = tid >> 5;
    int wm = warp * 16;
    int g = lane >> 2, t = lane & 3;
    int row0 = m0 + wm + g, row1 = row0 + 8;

    // K ldmatrix lane addresses (4 j-pairs covering 64 tokens)
    int br = (lane & 7) + ((lane & 16) >> 1);
    int bcol = (lane & 8) >> 1;
    uint32_t ksb = s2u(Ks);
    uint32_t kA[4];
#pragma unroll
    for (int jp = 0; jp < 4; jp++) kA[jp] = ksb + 4 * ((jp * 16 + br) * KPAD + bcol);

    uint32_t qf[8][4];
#pragma unroll
    for (int ks = 0; ks < 8; ks++) {
        int kb = ks * 8;
        qf[ks][0] = Qb[(size_t)row0 * HD + kb + t];
        qf[ks][1] = Qb[(size_t)row1 * HD + kb + t];
        qf[ks][2] = Qb[(size_t)row0 * HD + kb + t + 4];
        qf[ks][3] = Qb[(size_t)row1 * HD + kb + t + 4];
    }

    float o[8][4] = {};
    float rmax0 = -1e30f, rmax1 = -1e30f;
    float rsum0 = 0.f, rsum1 = 0.f;

    int nkv = (m0 + 128) / 64;
    for (int kv = 0; kv < nkv; kv++) {
        int kv0 = kv * 64;
#pragma unroll
        for (int i = 0; i < 4; i++) {
            int f = tid + i * 256;
            int r = f >> 4, c4 = (f & 15) * 4;
            *(uint4*)(Ks + r * KPAD + c4) = *(const uint4*)(Kb + (size_t)(kv0 + r) * HD + c4);
            *(uint4*)(Vs + r * VPAD + c4) = *(const uint4*)(Vb + (size_t)(kv0 + r) * HD + c4);
        }
        __syncthreads();

        // ---- S = Q @ K^T ----
        float s[8][4];
#pragma unroll
        for (int j = 0; j < 8; j++) { s[j][0]=0.f; s[j][1]=0.f; s[j][2]=0.f; s[j][3]=0.f; }
#pragma unroll
        for (int ks = 0; ks < 8; ks++) {
            int ko = ks * 32;
            uint32_t kf[8][2];
#pragma unroll
            for (int jp = 0; jp < 4; jp++)
                ldsm4(kf[2*jp][0], kf[2*jp][1], kf[2*jp+1][0], kf[2*jp+1][1], kA[jp] + ko);
#pragma unroll
            for (int j = 0; j < 8; j++)
                mma8(s[j], qf[ks], kf[j]);
        }

        // ---- scale + causal mask ----
        bool need_mask = (kv0 + 64 > m0);
#pragma unroll
        for (int j = 0; j < 8; j++) {
            int c0 = kv0 + j * 8 + 2 * t, c1 = c0 + 1;
            s[j][0] *= 0.125f; s[j][1] *= 0.125f; s[j][2] *= 0.125f; s[j][3] *= 0.125f;
            if (need_mask) {
                if (c0 > row0) s[j][0] = -1e30f;
                if (c1 > row0) s[j][1] = -1e30f;
                if (c0 > row1) s[j][2] = -1e30f;
                if (c1 > row1) s[j][3] = -1e30f;
            }
        }

        // ---- online softmax ----
        float m0l = -1e30f, m1l = -1e30f;
#pragma unroll
        for (int j = 0; j < 8; j++) {
            m0l = fmaxf(m0l, fmaxf(s[j][0], s[j][1]));
            m1l = fmaxf(m1l, fmaxf(s[j][2], s[j][3]));
        }
        m0l = fmaxf(m0l, __shfl_xor_sync(FULL, m0l, 1));
        m0l = fmaxf(m0l, __shfl_xor_sync(FULL, m0l, 2));
        m1l = fmaxf(m1l, __shfl_xor_sync(FULL, m1l, 1));
        m1l = fmaxf(m1l, __shfl_xor_sync(FULL, m1l, 2));
        float mn0 = fmaxf(rmax0, m0l), mn1 = fmaxf(rmax1, m1l);
        float cr0 = __expf(rmax0 - mn0), cr1 = __expf(rmax1 - mn1);
        rmax0 = mn0; rmax1 = mn1;
        rsum0 *= cr0; rsum1 *= cr1;
#pragma unroll
        for (int j = 0; j < 8; j++) {
            o[j][0] *= cr0; o[j][1] *= cr0; o[j][2] *= cr1; o[j][3] *= cr1;
        }
        float ps0 = 0.f, ps1 = 0.f;
#pragma unroll
        for (int j = 0; j < 8; j++) {
            s[j][0] = __expf(s[j][0] - mn0); ps0 += s[j][0];
            s[j][1] = __expf(s[j][1] - mn0); ps0 += s[j][1];
            s[j][2] = __expf(s[j][2] - mn1); ps1 += s[j][2];
            s[j][3] = __expf(s[j][3] - mn1); ps1 += s[j][3];
        }
        rsum0 += ps0; rsum1 += ps1;

        // ---- P C-frag -> A-frag via quad shuffles ----
        uint32_t pa[8][4];
        int L0 = (lane & ~3) | (t >> 1);
        int L2 = L0 + 2;
        bool odd = (t & 1);
#pragma unroll
        for (int j = 0; j < 8; j++) {
            float x00 = __shfl_sync(FULL, s[j][0], L0);
            float x01 = __shfl_sync(FULL, s[j][1], L0);
            float x20 = __shfl_sync(FULL, s[j][2], L0);
            float x21 = __shfl_sync(FULL, s[j][3], L0);
            float y00 = __shfl_sync(FULL, s[j][0], L2);
            float y01 = __shfl_sync(FULL, s[j][1], L2);
            float y20 = __shfl_sync(FULL, s[j][2], L2);
            float y21 = __shfl_sync(FULL, s[j][3], L2);
            pa[j][0] = f2tf(odd ? x01 : x00);
            pa[j][1] = f2tf(odd ? x21 : x20);
            pa[j][2] = f2tf(odd ? y01 : y00);
            pa[j][3] = f2tf(odd ? y21 : y20);
        }

        // ---- O += P @ V ----
#pragma unroll
        for (int ks = 0; ks < 8; ks++) {
            int kb = ks * 8;
#pragma unroll
            for (int j = 0; j < 8; j++) {
                uint32_t bf[2];
                bf[0] = Vs[(kb + t) * VPAD + j * 8 + g];
                bf[1] = Vs[(kb + t + 4) * VPAD + j * 8 + g];
                mma8(o[j], pa[ks], bf);
            }
        }
        __syncthreads();
    }

    // ---- epilogue: normalize + write ctx [B,T,D] as tf32 ----
    rsum0 += __shfl_xor_sync(FULL, rsum0, 1);
    rsum0 += __shfl_xor_sync(FULL, rsum0, 2);
    rsum1 += __shfl_xor_sync(FULL, rsum1, 1);
    rsum1 += __shfl_xor_sync(FULL, rsum1, 2);
    float i0 = 1.f / rsum0, i1 = 1.f / rsum1;

    int b = bh >> 4, h = bh & 15;
#pragma unroll
    for (int j = 0; j < 8; j++) {
        int col = j * 8 + 2 * t;
        *(uint2*)(C + ((size_t)(b * TT + row0)) * DD + h * HD + col) =
            make_uint2(f2tf(o[j][0] * i0), f2tf(o[j][1] * i0));
        *(uint2*)(C + ((size_t)(b * TT + row1)) * DD + h * HD + col) =
            make_uint2(f2tf(o[j][2] * i1), f2tf(o[j][3] * i1));
    }
}

// ---------------------------------------------------------------------------
// LayerNorm (faithful bug: scale * x_norm + scale), emits tf32
// ---------------------------------------------------------------------------
__global__ void ln_kernel(const float* __restrict__ x,
                          const float* __restrict__ scale,
                          uint32_t* __restrict__ y) {
    int row = blockIdx.x;
    const float* xr = x + (size_t)row * DD;
    uint32_t* yr = y + (size_t)row * DD;
    int tid = threadIdx.x;
    float v[4];
    float s = 0.f, s2 = 0.f;
#pragma unroll
    for (int i = 0; i < 4; i++) {
        v[i] = xr[tid + 256 * i];
        s  += v[i];
        s2 += v[i] * v[i];
    }
    __shared__ float sh[256], sh2[256];
    sh[tid] = s; sh2[tid] = s2;
    __syncthreads();
    for (int o = 128; o > 0; o >>= 1) {
        if (tid < o) { sh[tid] += sh[tid + o]; sh2[tid] += sh2[tid + o]; }
        __syncthreads();
    }
    float mean = sh[0] * (1.f / DD);
    float var  = sh2[0] * (1.f / DD) - mean * mean;
    float rstd = rsqrtf(var + 1e-5f);
#pragma unroll
    for (int i = 0; i < 4; i++) {
        int c = tid + 256 * i;
        float sc = scale[c];
        yr[c] = f2tf(sc * ((v[i] - mean) * rstd) + sc);
    }
}

// ---------------------------------------------------------------------------
// Host driver
// ---------------------------------------------------------------------------
static void run_block(const float* x_in, const float* ln_scale,
                      const uint32_t* wq, const uint32_t* wk, const uint32_t* wv,
                      const uint32_t* wo, const float* bo,
                      uint32_t* lnp, uint32_t* qp, uint32_t* kp, uint32_t* vp,
                      uint32_t* ctxp, float* out) {
    dim3 gG(DD / 128, (BB * TT) / 128);                 // (8, 32)
    ln_kernel<<<BB * TT, 256>>>(x_in, ln_scale, lnp);
    mma_gemm<0><<<gG, 256>>>(lnp, wq, nullptr, nullptr, qp);
    mma_gemm<0><<<gG, 256>>>(lnp, wk, nullptr, nullptr, kp);
    mma_gemm<0><<<gG, 256>>>(lnp, wv, nullptr, nullptr, vp);
    flash_attn<<<dim3(TT / 128, BB * HH), 256>>>(qp, kp, vp, ctxp);
    mma_gemm<1><<<gG, 256>>>(ctxp, wo, bo, x_in, out);
}

extern "C" void kernel_launch(void* const* d_in, const int* in_sizes, int n_in,
                              void* d_out, int out_size) {
    const float* x   = (const float*)d_in[0];
    const float* bo  = (const float*)d_in[5];
    const float* ln1 = (const float*)d_in[6];
    const float* ln2 = (const float*)d_in[7];
    float* out = (float*)d_out;

    uint32_t *lnp, *qp, *kp, *vp, *ctxp, *wt;
    float* hp;
    cudaGetSymbolAddress((void**)&lnp,  g_ln);
    cudaGetSymbolAddress((void**)&qp,   g_q);
    cudaGetSymbolAddress((void**)&kp,   g_k);
    cudaGetSymbolAddress((void**)&vp,   g_v);
    cudaGetSymbolAddress((void**)&ctxp, g_ctx);
    cudaGetSymbolAddress((void**)&hp,   g_h);
    cudaGetSymbolAddress((void**)&wt,   g_w);

    // convert weights (wq,wk,wv,wo = d_in[1..4]) to tf32 once
    for (int w = 0; w < 4; w++)
        cvt_tf32<<<(DD * DD / 4) / 256, 256>>>((const float4*)d_in[1 + w],
                                               (uint4*)(wt + (size_t)w * DD * DD));
    const uint32_t* wq = wt;
    const uint32_t* wk = wt + (size_t)1 * DD * DD;
    const uint32_t* wv = wt + (size_t)2 * DD * DD;
    const uint32_t* wo = wt + (size_t)3 * DD * DD;

    run_block(x,  ln1, wq, wk, wv, wo, bo, lnp, qp, kp, vp, ctxp, hp);
    run_block(hp, ln2, wq, wk, wv, wo, bo, lnp, qp, kp, vp, ctxp, out);
}

// round 8
// speedup vs baseline: 6.4995x; 1.7799x over previous
#include <cuda_runtime.h>
#include <cuda_fp16.h>
#include <cstdint>

#define BB 2
#define TT 2048
#define DD 1024
#define HH 16
#define HD 64

// ---- scratch (device globals: allocation-free) ----
__device__ __half g_ln [(size_t)BB*TT*DD];
__device__ __half g_q  [(size_t)BB*TT*DD];         // [B,H,T,hd] fp16
__device__ __half g_k  [(size_t)BB*TT*DD];
__device__ __half g_v  [(size_t)BB*TT*DD];
__device__ __half g_ctx[(size_t)BB*TT*DD];         // [B,T,D] fp16
__device__ float  g_h  [(size_t)BB*TT*DD];         // block-1 output (fp32)
__device__ __half g_w  [4][(size_t)DD*DD];         // wq,wk,wv,wo fp16

// ===========================================================================
// helpers
// ===========================================================================
__device__ __forceinline__ void mma16(float* c, const uint32_t* a, const uint32_t* b) {
    asm volatile(
        "mma.sync.aligned.m16n8k16.row.col.f32.f16.f16.f32 "
        "{%0,%1,%2,%3}, {%4,%5,%6,%7}, {%8,%9}, {%0,%1,%2,%3};"
        : "+f"(c[0]), "+f"(c[1]), "+f"(c[2]), "+f"(c[3])
        : "r"(a[0]), "r"(a[1]), "r"(a[2]), "r"(a[3]), "r"(b[0]), "r"(b[1]));
}
__device__ __forceinline__ void ldsm4(uint32_t& r0, uint32_t& r1,
                                      uint32_t& r2, uint32_t& r3, uint32_t addr) {
    asm volatile("ldmatrix.sync.aligned.m8n8.x4.shared.b16 {%0,%1,%2,%3}, [%4];"
        : "=r"(r0), "=r"(r1), "=r"(r2), "=r"(r3) : "r"(addr));
}
__device__ __forceinline__ void ldsm4t(uint32_t& r0, uint32_t& r1,
                                       uint32_t& r2, uint32_t& r3, uint32_t addr) {
    asm volatile("ldmatrix.sync.aligned.m8n8.x4.trans.shared.b16 {%0,%1,%2,%3}, [%4];"
        : "=r"(r0), "=r"(r1), "=r"(r2), "=r"(r3) : "r"(addr));
}
__device__ __forceinline__ uint32_t s2u(const void* p) {
    return (uint32_t)__cvta_generic_to_shared(p);
}
__device__ __forceinline__ uint32_t packh2(float lo, float hi) {
    __half2 h = __floats2half2_rn(lo, hi);
    return *(uint32_t*)&h;
}

#define PADW 40   // dense smem row stride (halves): 80B -> 20-word offsets, conflict-free
#define KP   72   // flash K/V row stride (halves): 144B -> 36-word offsets, conflict-free
#define VP   72
#define FULL 0xffffffffu

// ===========================================================================
// weight converter: fp32 -> fp16 (once per launch)
// ===========================================================================
__global__ void cvt_h(const float4* __restrict__ in, __half2* __restrict__ out) {
    int i = blockIdx.x * 256 + threadIdx.x;
    float4 v = in[i];
    out[2 * i]     = __floats2half2_rn(v.x, v.y);
    out[2 * i + 1] = __floats2half2_rn(v.z, v.w);
}

// ===========================================================================
// Dense GEMM: C[4096,1024] = A @ W^T, fp16 inputs, fp32 accum.
// BM=BN=128, BK=32, 8 warps 2x4, warp tile 64x32, m16n8k16 + ldmatrix.
//   MODE 0: emit fp16 into [B,H,T,hd]; MODE 1: fp32 out = res + bias + C.
// ===========================================================================
template <int MODE>
__global__ __launch_bounds__(256)
void mma_gemm(const __half* __restrict__ A, const __half* __restrict__ W,
              const float* __restrict__ bias, const float* __restrict__ res,
              void* __restrict__ outv) {
    __shared__ __half As[128 * PADW];
    __shared__ __half Bs[128 * PADW];
    int tid = threadIdx.x, lane = tid & 31, warp = tid >> 5;
    int wm = (warp >> 2) * 64, wn = (warp & 3) * 32;
    int g = lane >> 2, t = lane & 3;
    int m0 = blockIdx.y * 128, n0 = blockIdx.x * 128;

    // ldmatrix lane addresses
    uint32_t asb = s2u(As), bsb = s2u(Bs);
    int lr = lane & 15, lch = (lane >> 4) * 8;            // A frag
    int brow = (lane & 7) + ((lane & 16) >> 1);           // B frag
    int bch = (lane & 8);
    uint32_t aA[4], bA[2];
#pragma unroll
    for (int i = 0; i < 4; i++)
        aA[i] = asb + ((wm + i * 16 + lr) * PADW + lch) * 2;
#pragma unroll
    for (int jp = 0; jp < 2; jp++)
        bA[jp] = bsb + ((wn + jp * 16 + brow) * PADW + bch) * 2;

    float acc[4][4][4] = {};
    uint4 pa[2], pb[2];

#pragma unroll
    for (int i = 0; i < 2; i++) {
        int f = tid + i * 256, row = f >> 2, c8 = (f & 3) * 8;
        pa[i] = *(const uint4*)(A + (size_t)(m0 + row) * DD + c8);
        pb[i] = *(const uint4*)(W + (size_t)(n0 + row) * DD + c8);
    }
#pragma unroll
    for (int i = 0; i < 2; i++) {
        int f = tid + i * 256, row = f >> 2, c8 = (f & 3) * 8;
        *(uint4*)(As + row * PADW + c8) = pa[i];
        *(uint4*)(Bs + row * PADW + c8) = pb[i];
    }
    __syncthreads();

    for (int kt = 0; kt < DD / 32; kt++) {
        if (kt + 1 < DD / 32) {
            int k0 = (kt + 1) * 32;
#pragma unroll
            for (int i = 0; i < 2; i++) {
                int f = tid + i * 256, row = f >> 2, c8 = (f & 3) * 8;
                pa[i] = *(const uint4*)(A + (size_t)(m0 + row) * DD + k0 + c8);
                pb[i] = *(const uint4*)(W + (size_t)(n0 + row) * DD + k0 + c8);
            }
        }
#pragma unroll
        for (int kk = 0; kk < 2; kk++) {
            int ko = kk * 32;                     // bytes (16 halves)
            uint32_t af[4][4], bf[4][2];
#pragma unroll
            for (int i = 0; i < 4; i++)
                ldsm4(af[i][0], af[i][1], af[i][2], af[i][3], aA[i] + ko);
#pragma unroll
            for (int jp = 0; jp < 2; jp++)
                ldsm4(bf[2*jp][0], bf[2*jp][1], bf[2*jp+1][0], bf[2*jp+1][1], bA[jp] + ko);
#pragma unroll
            for (int i = 0; i < 4; i++)
#pragma unroll
                for (int j = 0; j < 4; j++)
                    mma16(acc[i][j], af[i], bf[j]);
        }
        if (kt + 1 < DD / 32) {
            __syncthreads();
#pragma unroll
            for (int i = 0; i < 2; i++) {
                int f = tid + i * 256, row = f >> 2, c8 = (f & 3) * 8;
                *(uint4*)(As + row * PADW + c8) = pa[i];
                *(uint4*)(Bs + row * PADW + c8) = pb[i];
            }
            __syncthreads();
        }
    }

#pragma unroll
    for (int i = 0; i < 4; i++) {
        int row = m0 + wm + i * 16 + g;
#pragma unroll
        for (int j = 0; j < 4; j++) {
            int col = n0 + wn + j * 8 + 2 * t;
            if (MODE == 0) {
                __half* out = (__half*)outv;
                int b = row >> 11, tt = row & 2047;
                int h = col >> 6, d = col & 63;
                __half* d0 = out + (((size_t)(b * HH + h)) * TT + tt) * HD + d;
                __half* d1 = out + (((size_t)(b * HH + h)) * TT + tt + 8) * HD + d;
                *(__half2*)d0 = __floats2half2_rn(acc[i][j][0], acc[i][j][1]);
                *(__half2*)d1 = __floats2half2_rn(acc[i][j][2], acc[i][j][3]);
            } else {
                float* out = (float*)outv;
                float2 b2 = *(const float2*)(bias + col);
                float2 r0 = *(const float2*)(res + (size_t)row * DD + col);
                float2 r1 = *(const float2*)(res + (size_t)(row + 8) * DD + col);
                *(float2*)(out + (size_t)row * DD + col) =
                    make_float2(acc[i][j][0] + r0.x + b2.x, acc[i][j][1] + r0.y + b2.y);
                *(float2*)(out + (size_t)(row + 8) * DD + col) =
                    make_float2(acc[i][j][2] + r1.x + b2.x, acc[i][j][3] + r1.y + b2.y);
            }
        }
    }
}

// ===========================================================================
// Fused flash attention (fp16 in/out, fp32 softmax/accum).
// Per CTA: 128 q-rows x one bh; 8 warps x 16 rows; 64-token KV tiles.
// m16n8k16; K frags via ldmatrix; V frags via ldmatrix.trans;
// P C-frag == A-frag layout (fp16) -> pure register half2 packing.
// ===========================================================================
__global__ __launch_bounds__(256)
void flash_attn(const __half* __restrict__ Q, const __half* __restrict__ K,
                const __half* __restrict__ V, __half* __restrict__ C) {
    __shared__ __half Ks[64 * KP];
    __shared__ __half Vs[64 * VP];

    int bh = blockIdx.y;
    int m0 = blockIdx.x * 128;
    const __half* Qb = Q + (size_t)bh * TT * HD;
    const __half* Kb = K + (size_t)bh * TT * HD;
    const __half* Vb = V + (size_t)bh * TT * HD;

    int tid = threadIdx.x, lane = tid & 31, warp = tid >> 5;
    int wm = warp * 16;
    int g = lane >> 2, t = lane & 3;
    int row0 = m0 + wm + g, row1 = row0 + 8;

    // K ldmatrix addresses: jp covers token-pairs (2jp, 2jp+1) of n8 tiles
    uint32_t ksb = s2u(Ks), vsb = s2u(Vs);
    int krow = (lane & 7) + ((lane & 16) >> 1);
    int kch = (lane & 8);
    uint32_t kA[4];
#pragma unroll
    for (int jp = 0; jp < 4; jp++)
        kA[jp] = ksb + ((jp * 16 + krow) * KP + kch) * 2;
    // V trans addresses
    uint32_t vA = vsb + (((lane & 7) + (lane & 8)) * VP + ((lane & 16) >> 1)) * 2;

    // Q fragments: 4 k16-blocks x 4 regs
    uint32_t qf[4][4];
#pragma unroll
    for (int ks = 0; ks < 4; ks++) {
        int kb = ks * 16;
        qf[ks][0] = *(const uint32_t*)(Qb + (size_t)row0 * HD + kb + 2 * t);
        qf[ks][1] = *(const uint32_t*)(Qb + (size_t)row1 * HD + kb + 2 * t);
        qf[ks][2] = *(const uint32_t*)(Qb + (size_t)row0 * HD + kb + 8 + 2 * t);
        qf[ks][3] = *(const uint32_t*)(Qb + (size_t)row1 * HD + kb + 8 + 2 * t);
    }

    float o[8][4] = {};
    float rmax0 = -1e30f, rmax1 = -1e30f;
    float rsum0 = 0.f, rsum1 = 0.f;

    int nkv = (m0 + 128) / 64;
    for (int kv = 0; kv < nkv; kv++) {
        int kv0 = kv * 64;
#pragma unroll
        for (int i = 0; i < 2; i++) {
            int f = tid + i * 256;
            int r = f >> 3, c8 = (f & 7) * 8;
            *(uint4*)(Ks + r * KP + c8) = *(const uint4*)(Kb + (size_t)(kv0 + r) * HD + c8);
            *(uint4*)(Vs + r * VP + c8) = *(const uint4*)(Vb + (size_t)(kv0 + r) * HD + c8);
        }
        __syncthreads();

        // ---- S = Q @ K^T (16 x 64) ----
        float s[8][4];
#pragma unroll
        for (int j = 0; j < 8; j++) { s[j][0]=0.f; s[j][1]=0.f; s[j][2]=0.f; s[j][3]=0.f; }
#pragma unroll
        for (int ks = 0; ks < 4; ks++) {
            int ko = ks * 32;                     // bytes
            uint32_t kf[8][2];
#pragma unroll
            for (int jp = 0; jp < 4; jp++)
                ldsm4(kf[2*jp][0], kf[2*jp][1], kf[2*jp+1][0], kf[2*jp+1][1], kA[jp] + ko);
#pragma unroll
            for (int j = 0; j < 8; j++)
                mma16(s[j], qf[ks], kf[j]);
        }

        // ---- scale + causal mask ----
        bool need_mask = (kv0 + 64 > m0);
#pragma unroll
        for (int j = 0; j < 8; j++) {
            int c0 = kv0 + j * 8 + 2 * t, c1 = c0 + 1;
            s[j][0] *= 0.125f; s[j][1] *= 0.125f; s[j][2] *= 0.125f; s[j][3] *= 0.125f;
            if (need_mask) {
                if (c0 > row0) s[j][0] = -1e30f;
                if (c1 > row0) s[j][1] = -1e30f;
                if (c0 > row1) s[j][2] = -1e30f;
                if (c1 > row1) s[j][3] = -1e30f;
            }
        }

        // ---- online softmax ----
        float m0l = -1e30f, m1l = -1e30f;
#pragma unroll
        for (int j = 0; j < 8; j++) {
            m0l = fmaxf(m0l, fmaxf(s[j][0], s[j][1]));
            m1l = fmaxf(m1l, fmaxf(s[j][2], s[j][3]));
        }
        m0l = fmaxf(m0l, __shfl_xor_sync(FULL, m0l, 1));
        m0l = fmaxf(m0l, __shfl_xor_sync(FULL, m0l, 2));
        m1l = fmaxf(m1l, __shfl_xor_sync(FULL, m1l, 1));
        m1l = fmaxf(m1l, __shfl_xor_sync(FULL, m1l, 2));
        float mn0 = fmaxf(rmax0, m0l), mn1 = fmaxf(rmax1, m1l);
        float cr0 = __expf(rmax0 - mn0), cr1 = __expf(rmax1 - mn1);
        rmax0 = mn0; rmax1 = mn1;
        rsum0 *= cr0; rsum1 *= cr1;
#pragma unroll
        for (int j = 0; j < 8; j++) {
            o[j][0] *= cr0; o[j][1] *= cr0; o[j][2] *= cr1; o[j][3] *= cr1;
        }
        float ps0 = 0.f, ps1 = 0.f;
#pragma unroll
        for (int j = 0; j < 8; j++) {
            s[j][0] = __expf(s[j][0] - mn0); ps0 += s[j][0];
            s[j][1] = __expf(s[j][1] - mn0); ps0 += s[j][1];
            s[j][2] = __expf(s[j][2] - mn1); ps1 += s[j][2];
            s[j][3] = __expf(s[j][3] - mn1); ps1 += s[j][3];
        }
        rsum0 += ps0; rsum1 += ps1;

        // ---- P C-frag -> fp16 A-frag: pure register packing, no shuffles ----
        uint32_t pan[4][4];
#pragma unroll
        for (int kb2 = 0; kb2 < 4; kb2++) {
            pan[kb2][0] = packh2(s[2*kb2][0],   s[2*kb2][1]);
            pan[kb2][1] = packh2(s[2*kb2][2],   s[2*kb2][3]);
            pan[kb2][2] = packh2(s[2*kb2+1][0], s[2*kb2+1][1]);
            pan[kb2][3] = packh2(s[2*kb2+1][2], s[2*kb2+1][3]);
        }

        // ---- O += P @ V (V via ldmatrix.trans) ----
#pragma unroll
        for (int kb2 = 0; kb2 < 4; kb2++) {
            uint32_t vf[8][2];
#pragma unroll
            for (int jp = 0; jp < 4; jp++)
                ldsm4t(vf[2*jp][0], vf[2*jp][1], vf[2*jp+1][0], vf[2*jp+1][1],
                       vA + (kb2 * 16 * VP + jp * 16) * 2);
#pragma unroll
            for (int j = 0; j < 8; j++)
                mma16(o[j], pan[kb2], vf[j]);
        }
        __syncthreads();
    }

    // ---- epilogue: normalize + write ctx [B,T,D] fp16 ----
    rsum0 += __shfl_xor_sync(FULL, rsum0, 1);
    rsum0 += __shfl_xor_sync(FULL, rsum0, 2);
    rsum1 += __shfl_xor_sync(FULL, rsum1, 1);
    rsum1 += __shfl_xor_sync(FULL, rsum1, 2);
    float i0 = 1.f / rsum0, i1 = 1.f / rsum1;

    int b = bh >> 4, h = bh & 15;
#pragma unroll
    for (int j = 0; j < 8; j++) {
        int col = j * 8 + 2 * t;
        *(__half2*)(C + ((size_t)(b * TT + row0)) * DD + h * HD + col) =
            __floats2half2_rn(o[j][0] * i0, o[j][1] * i0);
        *(__half2*)(C + ((size_t)(b * TT + row1)) * DD + h * HD + col) =
            __floats2half2_rn(o[j][2] * i1, o[j][3] * i1);
    }
}

// ---------------------------------------------------------------------------
// LayerNorm (faithful bug: scale * x_norm + scale), emits fp16
// ---------------------------------------------------------------------------
__global__ void ln_kernel(const float* __restrict__ x,
                          const float* __restrict__ scale,
                          __half* __restrict__ y) {
    int row = blockIdx.x;
    const float* xr = x + (size_t)row * DD;
    __half* yr = y + (size_t)row * DD;
    int tid = threadIdx.x;
    float v[4];
    float s = 0.f, s2 = 0.f;
#pragma unroll
    for (int i = 0; i < 4; i++) {
        v[i] = xr[tid + 256 * i];
        s  += v[i];
        s2 += v[i] * v[i];
    }
    __shared__ float sh[256], sh2[256];
    sh[tid] = s; sh2[tid] = s2;
    __syncthreads();
    for (int o = 128; o > 0; o >>= 1) {
        if (tid < o) { sh[tid] += sh[tid + o]; sh2[tid] += sh2[tid + o]; }
        __syncthreads();
    }
    float mean = sh[0] * (1.f / DD);
    float var  = sh2[0] * (1.f / DD) - mean * mean;
    float rstd = rsqrtf(var + 1e-5f);
#pragma unroll
    for (int i = 0; i < 4; i++) {
        int c = tid + 256 * i;
        float sc = scale[c];
        yr[c] = __float2half(sc * ((v[i] - mean) * rstd) + sc);
    }
}

// ---------------------------------------------------------------------------
// Host driver
// ---------------------------------------------------------------------------
static void run_block(const float* x_in, const float* ln_scale,
                      const __half* wq, const __half* wk, const __half* wv,
                      const __half* wo, const float* bo,
                      __half* lnp, __half* qp, __half* kp, __half* vp,
                      __half* ctxp, float* out) {
    dim3 gG(DD / 128, (BB * TT) / 128);                 // (8, 32)
    ln_kernel<<<BB * TT, 256>>>(x_in, ln_scale, lnp);
    mma_gemm<0><<<gG, 256>>>(lnp, wq, nullptr, nullptr, qp);
    mma_gemm<0><<<gG, 256>>>(lnp, wk, nullptr, nullptr, kp);
    mma_gemm<0><<<gG, 256>>>(lnp, wv, nullptr, nullptr, vp);
    flash_attn<<<dim3(TT / 128, BB * HH), 256>>>(qp, kp, vp, ctxp);
    mma_gemm<1><<<gG, 256>>>(ctxp, wo, bo, x_in, out);
}

extern "C" void kernel_launch(void* const* d_in, const int* in_sizes, int n_in,
                              void* d_out, int out_size) {
    const float* x   = (const float*)d_in[0];
    const float* bo  = (const float*)d_in[5];
    const float* ln1 = (const float*)d_in[6];
    const float* ln2 = (const float*)d_in[7];
    float* out = (float*)d_out;

    __half *lnp, *qp, *kp, *vp, *ctxp, *wt;
    float* hp;
    cudaGetSymbolAddress((void**)&lnp,  g_ln);
    cudaGetSymbolAddress((void**)&qp,   g_q);
    cudaGetSymbolAddress((void**)&kp,   g_k);
    cudaGetSymbolAddress((void**)&vp,   g_v);
    cudaGetSymbolAddress((void**)&ctxp, g_ctx);
    cudaGetSymbolAddress((void**)&hp,   g_h);
    cudaGetSymbolAddress((void**)&wt,   g_w);

    // convert weights (wq,wk,wv,wo = d_in[1..4]) to fp16 once
    for (int w = 0; w < 4; w++)
        cvt_h<<<(DD * DD / 4) / 256, 256>>>((const float4*)d_in[1 + w],
                                            (__half2*)(wt + (size_t)w * DD * DD));
    const __half* wq = wt;
    const __half* wk = wt + (size_t)1 * DD * DD;
    const __half* wv = wt + (size_t)2 * DD * DD;
    const __half* wo = wt + (size_t)3 * DD * DD;

    run_block(x,  ln1, wq, wk, wv, wo, bo, lnp, qp, kp, vp, ctxp, hp);
    run_block(hp, ln2, wq, wk, wv, wo, bo, lnp, qp, kp, vp, ctxp, out);
}

// round 9
// speedup vs baseline: 6.7399x; 1.0370x over previous
#include <cuda_runtime.h>
#include <cuda_fp16.h>
#include <cstdint>

#define BB 2
#define TT 2048
#define DD 1024
#define HH 16
#define HD 64
#define BTD ((size_t)BB*TT*DD)

// ---- scratch (device globals: allocation-free) ----
__device__ __half g_ln  [BTD];
__device__ __half g_qkv [3 * BTD];                 // q,k,v [B,H,T,hd] fp16
__device__ __half g_ctx [BTD];                     // [B,T,D] fp16
__device__ float  g_h   [BTD];                     // block-1 output (fp32)
__device__ __half g_w   [4][(size_t)DD*DD];        // wq,wk,wv,wo fp16 (qkv rows contiguous)

// ===========================================================================
// helpers
// ===========================================================================
__device__ __forceinline__ void mma16(float* c, const uint32_t* a, const uint32_t* b) {
    asm volatile(
        "mma.sync.aligned.m16n8k16.row.col.f32.f16.f16.f32 "
        "{%0,%1,%2,%3}, {%4,%5,%6,%7}, {%8,%9}, {%0,%1,%2,%3};"
        : "+f"(c[0]), "+f"(c[1]), "+f"(c[2]), "+f"(c[3])
        : "r"(a[0]), "r"(a[1]), "r"(a[2]), "r"(a[3]), "r"(b[0]), "r"(b[1]));
}
__device__ __forceinline__ void ldsm4(uint32_t& r0, uint32_t& r1,
                                      uint32_t& r2, uint32_t& r3, uint32_t addr) {
    asm volatile("ldmatrix.sync.aligned.m8n8.x4.shared.b16 {%0,%1,%2,%3}, [%4];"
        : "=r"(r0), "=r"(r1), "=r"(r2), "=r"(r3) : "r"(addr));
}
__device__ __forceinline__ void ldsm4t(uint32_t& r0, uint32_t& r1,
                                       uint32_t& r2, uint32_t& r3, uint32_t addr) {
    asm volatile("ldmatrix.sync.aligned.m8n8.x4.trans.shared.b16 {%0,%1,%2,%3}, [%4];"
        : "=r"(r0), "=r"(r1), "=r"(r2), "=r"(r3) : "r"(addr));
}
__device__ __forceinline__ uint32_t s2u(const void* p) {
    return (uint32_t)__cvta_generic_to_shared(p);
}
__device__ __forceinline__ uint32_t packh2(float lo, float hi) {
    __half2 h = __floats2half2_rn(lo, hi);
    return *(uint32_t*)&h;
}
__device__ __forceinline__ void cpa16(uint32_t dst, const void* src) {
    asm volatile("cp.async.ca.shared.global [%0], [%1], 16;" :: "r"(dst), "l"(src));
}
__device__ __forceinline__ void cp_commit() {
    asm volatile("cp.async.commit_group;" ::: "memory");
}
template <int N>
__device__ __forceinline__ void cp_wait() {
    asm volatile("cp.async.wait_group %0;" :: "n"(N) : "memory");
}

#define PADW 40          // dense smem row stride (halves); 80B rows
#define KP   72          // flash K/V row stride (halves); 144B rows
#define VP   72
#define FULL 0xffffffffu
#define GSTG (128 * PADW * 2)   // dense stage bytes
#define KSTG (64 * KP * 2)      // flash K/V stage bytes

// ===========================================================================
// weight converter: fp32 -> fp16, all 4 matrices in one launch
// ===========================================================================
__global__ void cvt_h4(const float4* __restrict__ w0, const float4* __restrict__ w1,
                       const float4* __restrict__ w2, const float4* __restrict__ w3,
                       __half2* __restrict__ out) {
    int m = blockIdx.y;
    const float4* in = (m == 0) ? w0 : (m == 1) ? w1 : (m == 2) ? w2 : w3;
    size_t base = (size_t)m * (DD * DD / 2);
    int i = blockIdx.x * 256 + threadIdx.x;
    float4 v = in[i];
    out[base + 2 * i]     = __floats2half2_rn(v.x, v.y);
    out[base + 2 * i + 1] = __floats2half2_rn(v.z, v.w);
}

// ===========================================================================
// Dense GEMM: C[4096, N] = A[4096,1024] @ W[N,1024]^T, fp16 in, fp32 accum.
// BM=BN=128, BK=32, 8 warps 2x4, warp tile 64x32, m16n8k16, ldmatrix,
// cp.async 2-stage double buffer.
//   MODE 0 (N=3072, fused QKV): emit fp16 into g_qkv[mat][B,H,T,hd]
//   MODE 1 (N=1024, out-proj):  fp32 out = res + bias + C
// ===========================================================================
template <int MODE>
__global__ __launch_bounds__(256)
void mma_gemm(const __half* __restrict__ A, const __half* __restrict__ W,
              const float* __restrict__ bias, const float* __restrict__ res,
              void* __restrict__ outv) {
    __shared__ __align__(16) __half As[2][128 * PADW];
    __shared__ __align__(16) __half Bs[2][128 * PADW];
    int tid = threadIdx.x, lane = tid & 31, warp = tid >> 5;
    int wm = (warp >> 2) * 64, wn = (warp & 3) * 32;
    int g = lane >> 2, t = lane & 3;
    int m0 = blockIdx.y * 128, n0 = blockIdx.x * 128;

    // cp.async load geometry: thread handles 2 chunks per matrix
    int lrow = tid >> 2, lc8 = (tid & 3) * 8;       // chunk0 row, half-col
    const __half* Ag0 = A + (size_t)(m0 + lrow) * DD + lc8;
    const __half* Ag1 = A + (size_t)(m0 + lrow + 64) * DD + lc8;
    const __half* Wg0 = W + (size_t)(n0 + lrow) * DD + lc8;
    const __half* Wg1 = W + (size_t)(n0 + lrow + 64) * DD + lc8;
    uint32_t aS = s2u(As) + (lrow * PADW + lc8) * 2;
    uint32_t bS = s2u(Bs) + (lrow * PADW + lc8) * 2;
    const uint32_t CH = 64 * PADW * 2;              // chunk1 smem offset

    // ldmatrix lane addresses (stage 0)
    uint32_t asb = s2u(As), bsb = s2u(Bs);
    int lr = lane & 15, lch = (lane >> 4) * 8;
    int brow = (lane & 7) + ((lane & 16) >> 1);
    int bch = (lane & 8);
    uint32_t aA[4], bA[2];
#pragma unroll
    for (int i = 0; i < 4; i++)
        aA[i] = asb + ((wm + i * 16 + lr) * PADW + lch) * 2;
#pragma unroll
    for (int jp = 0; jp < 2; jp++)
        bA[jp] = bsb + ((wn + jp * 16 + brow) * PADW + bch) * 2;

    float acc[4][4][4] = {};

    // prologue: stage 0 <- k-tile 0
    cpa16(aS, Ag0); cpa16(aS + CH, Ag1);
    cpa16(bS, Wg0); cpa16(bS + CH, Wg1);
    cp_commit();

    const int NKT = DD / 32;
    for (int kt = 0; kt < NKT; kt++) {
        int st = kt & 1;
        if (kt + 1 < NKT) {
            int k0 = (kt + 1) * 32;
            uint32_t so = (st ^ 1) * (uint32_t)GSTG;
            cpa16(aS + so, Ag0 + k0); cpa16(aS + so + CH, Ag1 + k0);
            cpa16(bS + so, Wg0 + k0); cpa16(bS + so + CH, Wg1 + k0);
            cp_commit();
            cp_wait<1>();
        } else {
            cp_wait<0>();
        }
        __syncthreads();

        uint32_t so = st * (uint32_t)GSTG;
#pragma unroll
        for (int kk = 0; kk < 2; kk++) {
            int ko = kk * 32;                       // bytes (16 halves)
            uint32_t af[4][4], bf[4][2];
#pragma unroll
            for (int i = 0; i < 4; i++)
                ldsm4(af[i][0], af[i][1], af[i][2], af[i][3], aA[i] + so + ko);
#pragma unroll
            for (int jp = 0; jp < 2; jp++)
                ldsm4(bf[2*jp][0], bf[2*jp][1], bf[2*jp+1][0], bf[2*jp+1][1],
                      bA[jp] + so + ko);
#pragma unroll
            for (int i = 0; i < 4; i++)
#pragma unroll
                for (int j = 0; j < 4; j++)
                    mma16(acc[i][j], af[i], bf[j]);
        }
        __syncthreads();
    }

    if (MODE == 0) {
        __half* out = (__half*)outv + (size_t)(n0 >> 10) * BTD;   // q/k/v select
#pragma unroll
        for (int i = 0; i < 4; i++) {
            int row = m0 + wm + i * 16 + g;
            int b = row >> 11, tt = row & 2047;
#pragma unroll
            for (int j = 0; j < 4; j++) {
                int col = (n0 & 1023) + wn + j * 8 + 2 * t;
                int h = col >> 6, d = col & 63;
                __half* d0 = out + (((size_t)(b * HH + h)) * TT + tt) * HD + d;
                __half* d1 = out + (((size_t)(b * HH + h)) * TT + tt + 8) * HD + d;
                *(__half2*)d0 = __floats2half2_rn(acc[i][j][0], acc[i][j][1]);
                *(__half2*)d1 = __floats2half2_rn(acc[i][j][2], acc[i][j][3]);
            }
        }
    } else {
        float* out = (float*)outv;
#pragma unroll
        for (int i = 0; i < 4; i++) {
            int row = m0 + wm + i * 16 + g;
#pragma unroll
            for (int j = 0; j < 4; j++) {
                int col = n0 + wn + j * 8 + 2 * t;
                float2 b2 = *(const float2*)(bias + col);
                float2 r0 = *(const float2*)(res + (size_t)row * DD + col);
                float2 r1 = *(const float2*)(res + (size_t)(row + 8) * DD + col);
                *(float2*)(out + (size_t)row * DD + col) =
                    make_float2(acc[i][j][0] + r0.x + b2.x, acc[i][j][1] + r0.y + b2.y);
                *(float2*)(out + (size_t)(row + 8) * DD + col) =
                    make_float2(acc[i][j][2] + r1.x + b2.x, acc[i][j][3] + r1.y + b2.y);
            }
        }
    }
}

// ===========================================================================
// Fused flash attention (fp16 in/out, fp32 softmax/accum), cp.async 2-stage
// KV pipeline. Per CTA: 128 q-rows x one bh; heaviest q-tiles scheduled first.
// ===========================================================================
__global__ __launch_bounds__(256)
void flash_attn(const __half* __restrict__ Q, const __half* __restrict__ K,
                const __half* __restrict__ V, __half* __restrict__ C) {
    __shared__ __align__(16) __half Ks[2][64 * KP];
    __shared__ __align__(16) __half Vs[2][64 * VP];

    int bh = blockIdx.y;
    int m0 = (gridDim.x - 1 - blockIdx.x) * 128;    // heaviest first
    const __half* Qb = Q + (size_t)bh * TT * HD;
    const __half* Kb = K + (size_t)bh * TT * HD;
    const __half* Vb = V + (size_t)bh * TT * HD;

    int tid = threadIdx.x, lane = tid & 31, warp = tid >> 5;
    int wm = warp * 16;
    int g = lane >> 2, t = lane & 3;
    int row0 = m0 + wm + g, row1 = row0 + 8;

    // cp.async load geometry: 2 chunks each for K and V
    int lrow = tid >> 3, lc8 = (tid & 7) * 8;       // chunk0: rows 0..31
    const __half* Kg0 = Kb + (size_t)lrow * HD + lc8;
    const __half* Kg1 = Kb + (size_t)(lrow + 32) * HD + lc8;
    const __half* Vg0 = Vb + (size_t)lrow * HD + lc8;
    const __half* Vg1 = Vb + (size_t)(lrow + 32) * HD + lc8;
    uint32_t kS = s2u(Ks) + (lrow * KP + lc8) * 2;
    uint32_t vS = s2u(Vs) + (lrow * VP + lc8) * 2;
    const uint32_t CHK = 32 * KP * 2, CHV = 32 * VP * 2;

    // ldmatrix lane addresses (stage 0)
    uint32_t ksb = s2u(Ks), vsb = s2u(Vs);
    int krow = (lane & 7) + ((lane & 16) >> 1);
    int kch = (lane & 8);
    uint32_t kA[4];
#pragma unroll
    for (int jp = 0; jp < 4; jp++)
        kA[jp] = ksb + ((jp * 16 + krow) * KP + kch) * 2;
    uint32_t vA = vsb + (((lane & 7) + (lane & 8)) * VP + ((lane & 16) >> 1)) * 2;

    // Q fragments
    uint32_t qf[4][4];
#pragma unroll
    for (int ks = 0; ks < 4; ks++) {
        int kb = ks * 16;
        qf[ks][0] = *(const uint32_t*)(Qb + (size_t)row0 * HD + kb + 2 * t);
        qf[ks][1] = *(const uint32_t*)(Qb + (size_t)row1 * HD + kb + 2 * t);
        qf[ks][2] = *(const uint32_t*)(Qb + (size_t)row0 * HD + kb + 8 + 2 * t);
        qf[ks][3] = *(const uint32_t*)(Qb + (size_t)row1 * HD + kb + 8 + 2 * t);
    }

    float o[8][4] = {};
    float rmax0 = -1e30f, rmax1 = -1e30f;
    float rsum0 = 0.f, rsum1 = 0.f;

    int nkv = (m0 + 128) / 64;
    // prologue: stage 0 <- kv tile 0
    cpa16(kS, Kg0); cpa16(kS + CHK, Kg1);
    cpa16(vS, Vg0); cpa16(vS + CHV, Vg1);
    cp_commit();

    for (int kv = 0; kv < nkv; kv++) {
        int st = kv & 1;
        if (kv + 1 < nkv) {
            size_t go = (size_t)(kv + 1) * 64 * HD;
            uint32_t sk = (st ^ 1) * (uint32_t)KSTG;
            cpa16(kS + sk, Kg0 + go); cpa16(kS + sk + CHK, Kg1 + go);
            cpa16(vS + sk, Vg0 + go); cpa16(vS + sk + CHV, Vg1 + go);
            cp_commit();
            cp_wait<1>();
        } else {
            cp_wait<0>();
        }
        __syncthreads();
        int kv0 = kv * 64;
        uint32_t so = st * (uint32_t)KSTG;

        // ---- S = Q @ K^T (16 x 64) ----
        float s[8][4];
#pragma unroll
        for (int j = 0; j < 8; j++) { s[j][0]=0.f; s[j][1]=0.f; s[j][2]=0.f; s[j][3]=0.f; }
#pragma unroll
        for (int ks = 0; ks < 4; ks++) {
            int ko = ks * 32;
            uint32_t kf[8][2];
#pragma unroll
            for (int jp = 0; jp < 4; jp++)
                ldsm4(kf[2*jp][0], kf[2*jp][1], kf[2*jp+1][0], kf[2*jp+1][1],
                      kA[jp] + so + ko);
#pragma unroll
            for (int j = 0; j < 8; j++)
                mma16(s[j], qf[ks], kf[j]);
        }

        // ---- scale + causal mask ----
        bool need_mask = (kv0 + 64 > m0);
#pragma unroll
        for (int j = 0; j < 8; j++) {
            int c0 = kv0 + j * 8 + 2 * t, c1 = c0 + 1;
            s[j][0] *= 0.125f; s[j][1] *= 0.125f; s[j][2] *= 0.125f; s[j][3] *= 0.125f;
            if (need_mask) {
                if (c0 > row0) s[j][0] = -1e30f;
                if (c1 > row0) s[j][1] = -1e30f;
                if (c0 > row1) s[j][2] = -1e30f;
                if (c1 > row1) s[j][3] = -1e30f;
            }
        }

        // ---- online softmax ----
        float m0l = -1e30f, m1l = -1e30f;
#pragma unroll
        for (int j = 0; j < 8; j++) {
            m0l = fmaxf(m0l, fmaxf(s[j][0], s[j][1]));
            m1l = fmaxf(m1l, fmaxf(s[j][2], s[j][3]));
        }
        m0l = fmaxf(m0l, __shfl_xor_sync(FULL, m0l, 1));
        m0l = fmaxf(m0l, __shfl_xor_sync(FULL, m0l, 2));
        m1l = fmaxf(m1l, __shfl_xor_sync(FULL, m1l, 1));
        m1l = fmaxf(m1l, __shfl_xor_sync(FULL, m1l, 2));
        float mn0 = fmaxf(rmax0, m0l), mn1 = fmaxf(rmax1, m1l);
        float cr0 = __expf(rmax0 - mn0), cr1 = __expf(rmax1 - mn1);
        rmax0 = mn0; rmax1 = mn1;
        rsum0 *= cr0; rsum1 *= cr1;
#pragma unroll
        for (int j = 0; j < 8; j++) {
            o[j][0] *= cr0; o[j][1] *= cr0; o[j][2] *= cr1; o[j][3] *= cr1;
        }
        float ps0 = 0.f, ps1 = 0.f;
#pragma unroll
        for (int j = 0; j < 8; j++) {
            s[j][0] = __expf(s[j][0] - mn0); ps0 += s[j][0];
            s[j][1] = __expf(s[j][1] - mn0); ps0 += s[j][1];
            s[j][2] = __expf(s[j][2] - mn1); ps1 += s[j][2];
            s[j][3] = __expf(s[j][3] - mn1); ps1 += s[j][3];
        }
        rsum0 += ps0; rsum1 += ps1;

        // ---- P C-frag -> fp16 A-frag (pure register packing) ----
        uint32_t pan[4][4];
#pragma unroll
        for (int kb2 = 0; kb2 < 4; kb2++) {
            pan[kb2][0] = packh2(s[2*kb2][0],   s[2*kb2][1]);
            pan[kb2][1] = packh2(s[2*kb2][2],   s[2*kb2][3]);
            pan[kb2][2] = packh2(s[2*kb2+1][0], s[2*kb2+1][1]);
            pan[kb2][3] = packh2(s[2*kb2+1][2], s[2*kb2+1][3]);
        }

        // ---- O += P @ V (V via ldmatrix.trans) ----
#pragma unroll
        for (int kb2 = 0; kb2 < 4; kb2++) {
            uint32_t vf[8][2];
#pragma unroll
            for (int jp = 0; jp < 4; jp++)
                ldsm4t(vf[2*jp][0], vf[2*jp][1], vf[2*jp+1][0], vf[2*jp+1][1],
                       vA + so + (kb2 * 16 * VP + jp * 16) * 2);
#pragma unroll
            for (int j = 0; j < 8; j++)
                mma16(o[j], pan[kb2], vf[j]);
        }
        __syncthreads();
    }

    // ---- epilogue: normalize + write ctx [B,T,D] fp16 ----
    rsum0 += __shfl_xor_sync(FULL, rsum0, 1);
    rsum0 += __shfl_xor_sync(FULL, rsum0, 2);
    rsum1 += __shfl_xor_sync(FULL, rsum1, 1);
    rsum1 += __shfl_xor_sync(FULL, rsum1, 2);
    float i0 = 1.f / rsum0, i1 = 1.f / rsum1;

    int b = bh >> 4, h = bh & 15;
#pragma unroll
    for (int j = 0; j < 8; j++) {
        int col = j * 8 + 2 * t;
        *(__half2*)(C + ((size_t)(b * TT + row0)) * DD + h * HD + col) =
            __floats2half2_rn(o[j][0] * i0, o[j][1] * i0);
        *(__half2*)(C + ((size_t)(b * TT + row1)) * DD + h * HD + col) =
            __floats2half2_rn(o[j][2] * i1, o[j][3] * i1);
    }
}

// ---------------------------------------------------------------------------
// LayerNorm (faithful bug: scale * x_norm + scale), emits fp16
// ---------------------------------------------------------------------------
__global__ void ln_kernel(const float* __restrict__ x,
                          const float* __restrict__ scale,
                          __half* __restrict__ y) {
    int row = blockIdx.x;
    const float* xr = x + (size_t)row * DD;
    __half* yr = y + (size_t)row * DD;
    int tid = threadIdx.x;
    float v[4];
    float s = 0.f, s2 = 0.f;
#pragma unroll
    for (int i = 0; i < 4; i++) {
        v[i] = xr[tid + 256 * i];
        s  += v[i];
        s2 += v[i] * v[i];
    }
    __shared__ float sh[256], sh2[256];
    sh[tid] = s; sh2[tid] = s2;
    __syncthreads();
    for (int o = 128; o > 0; o >>= 1) {
        if (tid < o) { sh[tid] += sh[tid + o]; sh2[tid] += sh2[tid + o]; }
        __syncthreads();
    }
    float mean = sh[0] * (1.f / DD);
    float var  = sh2[0] * (1.f / DD) - mean * mean;
    float rstd = rsqrtf(var + 1e-5f);
#pragma unroll
    for (int i = 0; i < 4; i++) {
        int c = tid + 256 * i;
        float sc = scale[c];
        yr[c] = __float2half(sc * ((v[i] - mean) * rstd) + sc);
    }
}

// ---------------------------------------------------------------------------
// Host driver
// ---------------------------------------------------------------------------
static void run_block(const float* x_in, const float* ln_scale,
                      const __half* wqkv, const __half* wo, const float* bo,
                      __half* lnp, __half* qkvp, __half* ctxp, float* out) {
    ln_kernel<<<BB * TT, 256>>>(x_in, ln_scale, lnp);
    mma_gemm<0><<<dim3(3 * DD / 128, (BB * TT) / 128), 256>>>(
        lnp, wqkv, nullptr, nullptr, qkvp);
    flash_attn<<<dim3(TT / 128, BB * HH), 256>>>(
        qkvp, qkvp + BTD, qkvp + 2 * BTD, ctxp);
    mma_gemm<1><<<dim3(DD / 128, (BB * TT) / 128), 256>>>(
        ctxp, wo, bo, x_in, out);
}

extern "C" void kernel_launch(void* const* d_in, const int* in_sizes, int n_in,
                              void* d_out, int out_size) {
    const float* x   = (const float*)d_in[0];
    const float* bo  = (const float*)d_in[5];
    const float* ln1 = (const float*)d_in[6];
    const float* ln2 = (const float*)d_in[7];
    float* out = (float*)d_out;

    __half *lnp, *qkvp, *ctxp, *wt;
    float* hp;
    cudaGetSymbolAddress((void**)&lnp,  g_ln);
    cudaGetSymbolAddress((void**)&qkvp, g_qkv);
    cudaGetSymbolAddress((void**)&ctxp, g_ctx);
    cudaGetSymbolAddress((void**)&hp,   g_h);
    cudaGetSymbolAddress((void**)&wt,   g_w);

    // convert wq,wk,wv,wo -> fp16 (one launch); qkv rows contiguous
    cvt_h4<<<dim3((DD * DD / 4) / 256, 4), 256>>>(
        (const float4*)d_in[1], (const float4*)d_in[2],
        (const float4*)d_in[3], (const float4*)d_in[4], (__half2*)wt);
    const __half* wqkv = wt;
    const __half* wo   = wt + (size_t)3 * DD * DD;

    run_block(x,  ln1, wqkv, wo, bo, lnp, qkvp, ctxp, hp);
    run_block(hp, ln2, wqkv, wo, bo, lnp, qkvp, ctxp, out);
}

// round 10
// speedup vs baseline: 6.9677x; 1.0338x over previous
#include <cuda_runtime.h>
#include <cuda_fp16.h>
#include <cstdint>

#define BB 2
#define TT 2048
#define DD 1024
#define HH 16
#define HD 64
#define BTD ((size_t)BB*TT*DD)

// ---- scratch (device globals: allocation-free) ----
__device__ __half g_ln  [BTD];
__device__ __half g_qkv [3 * BTD];                 // q,k,v [B,H,T,hd] fp16 (q pre-scaled by 0.125)
__device__ __half g_ctx [BTD];                     // [B,T,D] fp16
__device__ float  g_h   [BTD];                     // block-1 output (fp32)
__device__ __half g_w   [4][(size_t)DD*DD];        // wq,wk,wv,wo fp16 (qkv rows contiguous)

// ===========================================================================
// helpers
// ===========================================================================
__device__ __forceinline__ void mma16(float* c, const uint32_t* a, const uint32_t* b) {
    asm volatile(
        "mma.sync.aligned.m16n8k16.row.col.f32.f16.f16.f32 "
        "{%0,%1,%2,%3}, {%4,%5,%6,%7}, {%8,%9}, {%0,%1,%2,%3};"
        : "+f"(c[0]), "+f"(c[1]), "+f"(c[2]), "+f"(c[3])
        : "r"(a[0]), "r"(a[1]), "r"(a[2]), "r"(a[3]), "r"(b[0]), "r"(b[1]));
}
__device__ __forceinline__ void ldsm4(uint32_t& r0, uint32_t& r1,
                                      uint32_t& r2, uint32_t& r3, uint32_t addr) {
    asm volatile("ldmatrix.sync.aligned.m8n8.x4.shared.b16 {%0,%1,%2,%3}, [%4];"
        : "=r"(r0), "=r"(r1), "=r"(r2), "=r"(r3) : "r"(addr));
}
__device__ __forceinline__ void ldsm4t(uint32_t& r0, uint32_t& r1,
                                       uint32_t& r2, uint32_t& r3, uint32_t addr) {
    asm volatile("ldmatrix.sync.aligned.m8n8.x4.trans.shared.b16 {%0,%1,%2,%3}, [%4];"
        : "=r"(r0), "=r"(r1), "=r"(r2), "=r"(r3) : "r"(addr));
}
__device__ __forceinline__ uint32_t s2u(const void* p) {
    return (uint32_t)__cvta_generic_to_shared(p);
}
__device__ __forceinline__ uint32_t packh2(float lo, float hi) {
    __half2 h = __floats2half2_rn(lo, hi);
    return *(uint32_t*)&h;
}
__device__ __forceinline__ uint32_t ex2h2(uint32_t x) {   // paired fp16 exp2
    uint32_t r;
    asm("ex2.approx.f16x2 %0, %1;" : "=r"(r) : "r"(x));
    return r;
}
__device__ __forceinline__ void cpa16(uint32_t dst, const void* src) {
    asm volatile("cp.async.ca.shared.global [%0], [%1], 16;" :: "r"(dst), "l"(src));
}
__device__ __forceinline__ void cp_commit() {
    asm volatile("cp.async.commit_group;" ::: "memory");
}
template <int N>
__device__ __forceinline__ void cp_wait() {
    asm volatile("cp.async.wait_group %0;" :: "n"(N) : "memory");
}

#define PADW 40          // dense smem row stride (halves); 80B rows
#define KP   72          // flash K/V row stride (halves); 144B rows
#define VP   72
#define FULL 0xffffffffu
#define GSTG (128 * PADW * 2)   // dense stage bytes
#define KSTG (64 * KP * 2)      // flash K/V stage bytes
#define L2E  1.4426950408889634f
#define ONE2 0x3C003C00u        // half2(1.0, 1.0)

// ===========================================================================
// weight converter: fp32 -> fp16, all 4 matrices in one launch
// ===========================================================================
__global__ void cvt_h4(const float4* __restrict__ w0, const float4* __restrict__ w1,
                       const float4* __restrict__ w2, const float4* __restrict__ w3,
                       __half2* __restrict__ out) {
    int m = blockIdx.y;
    const float4* in = (m == 0) ? w0 : (m == 1) ? w1 : (m == 2) ? w2 : w3;
    size_t base = (size_t)m * (DD * DD / 2);
    int i = blockIdx.x * 256 + threadIdx.x;
    float4 v = in[i];
    out[base + 2 * i]     = __floats2half2_rn(v.x, v.y);
    out[base + 2 * i + 1] = __floats2half2_rn(v.z, v.w);
}

// ===========================================================================
// Dense GEMM: C[4096, N] = A[4096,1024] @ W[N,1024]^T, fp16 in, fp32 accum.
// BM=BN=128, BK=32, 8 warps 2x4, warp tile 64x32, m16n8k16, ldmatrix,
// cp.async 2-stage double buffer.
//   MODE 0 (N=3072, fused QKV): emit fp16 into g_qkv; q part scaled by 0.125
//   MODE 1 (N=1024, out-proj):  fp32 out = res + bias + C
// ===========================================================================
template <int MODE>
__global__ __launch_bounds__(256)
void mma_gemm(const __half* __restrict__ A, const __half* __restrict__ W,
              const float* __restrict__ bias, const float* __restrict__ res,
              void* __restrict__ outv) {
    __shared__ __align__(16) __half As[2][128 * PADW];
    __shared__ __align__(16) __half Bs[2][128 * PADW];
    int tid = threadIdx.x, lane = tid & 31, warp = tid >> 5;
    int wm = (warp >> 2) * 64, wn = (warp & 3) * 32;
    int g = lane >> 2, t = lane & 3;
    int m0 = blockIdx.y * 128, n0 = blockIdx.x * 128;

    int lrow = tid >> 2, lc8 = (tid & 3) * 8;
    const __half* Ag0 = A + (size_t)(m0 + lrow) * DD + lc8;
    const __half* Ag1 = A + (size_t)(m0 + lrow + 64) * DD + lc8;
    const __half* Wg0 = W + (size_t)(n0 + lrow) * DD + lc8;
    const __half* Wg1 = W + (size_t)(n0 + lrow + 64) * DD + lc8;
    uint32_t aS = s2u(As) + (lrow * PADW + lc8) * 2;
    uint32_t bS = s2u(Bs) + (lrow * PADW + lc8) * 2;
    const uint32_t CH = 64 * PADW * 2;

    uint32_t asb = s2u(As), bsb = s2u(Bs);
    int lr = lane & 15, lch = (lane >> 4) * 8;
    int brow = (lane & 7) + ((lane & 16) >> 1);
    int bch = (lane & 8);
    uint32_t aA[4], bA[2];
#pragma unroll
    for (int i = 0; i < 4; i++)
        aA[i] = asb + ((wm + i * 16 + lr) * PADW + lch) * 2;
#pragma unroll
    for (int jp = 0; jp < 2; jp++)
        bA[jp] = bsb + ((wn + jp * 16 + brow) * PADW + bch) * 2;

    float acc[4][4][4] = {};

    cpa16(aS, Ag0); cpa16(aS + CH, Ag1);
    cpa16(bS, Wg0); cpa16(bS + CH, Wg1);
    cp_commit();

    const int NKT = DD / 32;
    for (int kt = 0; kt < NKT; kt++) {
        int st = kt & 1;
        if (kt + 1 < NKT) {
            int k0 = (kt + 1) * 32;
            uint32_t so = (st ^ 1) * (uint32_t)GSTG;
            cpa16(aS + so, Ag0 + k0); cpa16(aS + so + CH, Ag1 + k0);
            cpa16(bS + so, Wg0 + k0); cpa16(bS + so + CH, Wg1 + k0);
            cp_commit();
            cp_wait<1>();
        } else {
            cp_wait<0>();
        }
        __syncthreads();

        uint32_t so = st * (uint32_t)GSTG;
#pragma unroll
        for (int kk = 0; kk < 2; kk++) {
            int ko = kk * 32;
            uint32_t af[4][4], bf[4][2];
#pragma unroll
            for (int i = 0; i < 4; i++)
                ldsm4(af[i][0], af[i][1], af[i][2], af[i][3], aA[i] + so + ko);
#pragma unroll
            for (int jp = 0; jp < 2; jp++)
                ldsm4(bf[2*jp][0], bf[2*jp][1], bf[2*jp+1][0], bf[2*jp+1][1],
                      bA[jp] + so + ko);
#pragma unroll
            for (int i = 0; i < 4; i++)
#pragma unroll
                for (int j = 0; j < 4; j++)
                    mma16(acc[i][j], af[i], bf[j]);
        }
        __syncthreads();
    }

    if (MODE == 0) {
        __half* out = (__half*)outv + (size_t)(n0 >> 10) * BTD;   // q/k/v select
        float qs = (n0 < DD) ? 0.125f : 1.f;                      // fold 1/sqrt(hd) into Q
#pragma unroll
        for (int i = 0; i < 4; i++) {
            int row = m0 + wm + i * 16 + g;
            int b = row >> 11, tt = row & 2047;
#pragma unroll
            for (int j = 0; j < 4; j++) {
                int col = (n0 & 1023) + wn + j * 8 + 2 * t;
                int h = col >> 6, d = col & 63;
                __half* d0 = out + (((size_t)(b * HH + h)) * TT + tt) * HD + d;
                __half* d1 = out + (((size_t)(b * HH + h)) * TT + tt + 8) * HD + d;
                *(__half2*)d0 = __floats2half2_rn(acc[i][j][0] * qs, acc[i][j][1] * qs);
                *(__half2*)d1 = __floats2half2_rn(acc[i][j][2] * qs, acc[i][j][3] * qs);
            }
        }
    } else {
        float* out = (float*)outv;
#pragma unroll
        for (int i = 0; i < 4; i++) {
            int row = m0 + wm + i * 16 + g;
#pragma unroll
            for (int j = 0; j < 4; j++) {
                int col = n0 + wn + j * 8 + 2 * t;
                float2 b2 = *(const float2*)(bias + col);
                float2 r0 = *(const float2*)(res + (size_t)row * DD + col);
                float2 r1 = *(const float2*)(res + (size_t)(row + 8) * DD + col);
                *(float2*)(out + (size_t)row * DD + col) =
                    make_float2(acc[i][j][0] + r0.x + b2.x, acc[i][j][1] + r0.y + b2.y);
                *(float2*)(out + (size_t)(row + 8) * DD + col) =
                    make_float2(acc[i][j][2] + r1.x + b2.x, acc[i][j][3] + r1.y + b2.y);
            }
        }
    }
}

// ===========================================================================
// Fused flash attention (fp16 in/out, fp32 accum). Q pre-scaled by 0.125.
// cp.async 2-stage KV pipeline. exp via ex2.approx.f16x2 directly into P
// fragments; row-sums accumulated by an extra mma against an all-ones B.
// ===========================================================================
__global__ __launch_bounds__(256)
void flash_attn(const __half* __restrict__ Q, const __half* __restrict__ K,
                const __half* __restrict__ V, __half* __restrict__ C) {
    __shared__ __align__(16) __half Ks[2][64 * KP];
    __shared__ __align__(16) __half Vs[2][64 * VP];

    int bh = blockIdx.y;
    int m0 = (gridDim.x - 1 - blockIdx.x) * 128;    // heaviest first
    const __half* Qb = Q + (size_t)bh * TT * HD;
    const __half* Kb = K + (size_t)bh * TT * HD;
    const __half* Vb = V + (size_t)bh * TT * HD;

    int tid = threadIdx.x, lane = tid & 31, warp = tid >> 5;
    int wm = warp * 16;
    int g = lane >> 2, t = lane & 3;
    int row0 = m0 + wm + g, row1 = row0 + 8;

    int lrow = tid >> 3, lc8 = (tid & 7) * 8;
    const __half* Kg0 = Kb + (size_t)lrow * HD + lc8;
    const __half* Kg1 = Kb + (size_t)(lrow + 32) * HD + lc8;
    const __half* Vg0 = Vb + (size_t)lrow * HD + lc8;
    const __half* Vg1 = Vb + (size_t)(lrow + 32) * HD + lc8;
    uint32_t kS = s2u(Ks) + (lrow * KP + lc8) * 2;
    uint32_t vS = s2u(Vs) + (lrow * VP + lc8) * 2;
    const uint32_t CHK = 32 * KP * 2, CHV = 32 * VP * 2;

    uint32_t ksb = s2u(Ks), vsb = s2u(Vs);
    int krow = (lane & 7) + ((lane & 16) >> 1);
    int kch = (lane & 8);
    uint32_t kA[4];
#pragma unroll
    for (int jp = 0; jp < 4; jp++)
        kA[jp] = ksb + ((jp * 16 + krow) * KP + kch) * 2;
    uint32_t vA = vsb + (((lane & 7) + (lane & 8)) * VP + ((lane & 16) >> 1)) * 2;

    uint32_t qf[4][4];
#pragma unroll
    for (int ks = 0; ks < 4; ks++) {
        int kb = ks * 16;
        qf[ks][0] = *(const uint32_t*)(Qb + (size_t)row0 * HD + kb + 2 * t);
        qf[ks][1] = *(const uint32_t*)(Qb + (size_t)row1 * HD + kb + 2 * t);
        qf[ks][2] = *(const uint32_t*)(Qb + (size_t)row0 * HD + kb + 8 + 2 * t);
        qf[ks][3] = *(const uint32_t*)(Qb + (size_t)row1 * HD + kb + 8 + 2 * t);
    }

    float o[8][4] = {};
    float sacc[4] = {};                  // row-sum accumulator (mma C frag)
    float rmax0 = -1e30f, rmax1 = -1e30f;
    const uint32_t onef[2] = {ONE2, ONE2};

    int nkv = (m0 + 128) / 64;
    cpa16(kS, Kg0); cpa16(kS + CHK, Kg1);
    cpa16(vS, Vg0); cpa16(vS + CHV, Vg1);
    cp_commit();

    for (int kv = 0; kv < nkv; kv++) {
        int st = kv & 1;
        if (kv + 1 < nkv) {
            size_t go = (size_t)(kv + 1) * 64 * HD;
            uint32_t sk = (st ^ 1) * (uint32_t)KSTG;
            cpa16(kS + sk, Kg0 + go); cpa16(kS + sk + CHK, Kg1 + go);
            cpa16(vS + sk, Vg0 + go); cpa16(vS + sk + CHV, Vg1 + go);
            cp_commit();
            cp_wait<1>();
        } else {
            cp_wait<0>();
        }
        __syncthreads();
        int kv0 = kv * 64;
        uint32_t so = st * (uint32_t)KSTG;

        // ---- S = Q @ K^T (16 x 64), already scaled (Q pre-scaled) ----
        float s[8][4];
#pragma unroll
        for (int j = 0; j < 8; j++) { s[j][0]=0.f; s[j][1]=0.f; s[j][2]=0.f; s[j][3]=0.f; }
#pragma unroll
        for (int ks = 0; ks < 4; ks++) {
            int ko = ks * 32;
            uint32_t kf[8][2];
#pragma unroll
            for (int jp = 0; jp < 4; jp++)
                ldsm4(kf[2*jp][0], kf[2*jp][1], kf[2*jp+1][0], kf[2*jp+1][1],
                      kA[jp] + so + ko);
#pragma unroll
            for (int j = 0; j < 8; j++)
                mma16(s[j], qf[ks], kf[j]);
        }

        // ---- causal mask (only the diagonal tile) ----
        if (kv0 + 64 > m0) {
#pragma unroll
            for (int j = 0; j < 8; j++) {
                int c0 = kv0 + j * 8 + 2 * t, c1 = c0 + 1;
                if (c0 > row0) s[j][0] = -1e30f;
                if (c1 > row0) s[j][1] = -1e30f;
                if (c0 > row1) s[j][2] = -1e30f;
                if (c1 > row1) s[j][3] = -1e30f;
            }
        }

        // ---- online softmax ----
        float m0l = -1e30f, m1l = -1e30f;
#pragma unroll
        for (int j = 0; j < 8; j++) {
            m0l = fmaxf(m0l, fmaxf(s[j][0], s[j][1]));
            m1l = fmaxf(m1l, fmaxf(s[j][2], s[j][3]));
        }
        m0l = fmaxf(m0l, __shfl_xor_sync(FULL, m0l, 1));
        m0l = fmaxf(m0l, __shfl_xor_sync(FULL, m0l, 2));
        m1l = fmaxf(m1l, __shfl_xor_sync(FULL, m1l, 1));
        m1l = fmaxf(m1l, __shfl_xor_sync(FULL, m1l, 2));
        float mn0 = fmaxf(rmax0, m0l), mn1 = fmaxf(rmax1, m1l);
        float cr0 = __expf(rmax0 - mn0), cr1 = __expf(rmax1 - mn1);
        rmax0 = mn0; rmax1 = mn1;
        sacc[0] *= cr0; sacc[1] *= cr0; sacc[2] *= cr1; sacc[3] *= cr1;
#pragma unroll
        for (int j = 0; j < 8; j++) {
            o[j][0] *= cr0; o[j][1] *= cr0; o[j][2] *= cr1; o[j][3] *= cr1;
        }

        // ---- exp: FFMA to log2-domain, pack, paired fp16 exp2 -> P frags ----
        float b0 = -mn0 * L2E, b1 = -mn1 * L2E;
        uint32_t pan[4][4];
#pragma unroll
        for (int kb2 = 0; kb2 < 4; kb2++) {
            int j0 = 2 * kb2, j1 = 2 * kb2 + 1;
            pan[kb2][0] = ex2h2(packh2(fmaf(s[j0][0], L2E, b0), fmaf(s[j0][1], L2E, b0)));
            pan[kb2][1] = ex2h2(packh2(fmaf(s[j0][2], L2E, b1), fmaf(s[j0][3], L2E, b1)));
            pan[kb2][2] = ex2h2(packh2(fmaf(s[j1][0], L2E, b0), fmaf(s[j1][1], L2E, b0)));
            pan[kb2][3] = ex2h2(packh2(fmaf(s[j1][2], L2E, b1), fmaf(s[j1][3], L2E, b1)));
        }

        // ---- row sums via tensor core (B = ones) + O += P @ V ----
#pragma unroll
        for (int kb2 = 0; kb2 < 4; kb2++) {
            mma16(sacc, pan[kb2], onef);
            uint32_t vf[8][2];
#pragma unroll
            for (int jp = 0; jp < 4; jp++)
                ldsm4t(vf[2*jp][0], vf[2*jp][1], vf[2*jp+1][0], vf[2*jp+1][1],
                       vA + so + (kb2 * 16 * VP + jp * 16) * 2);
#pragma unroll
            for (int j = 0; j < 8; j++)
                mma16(o[j], pan[kb2], vf[j]);
        }
        __syncthreads();
    }

    // ---- epilogue: normalize + write ctx [B,T,D] fp16 ----
    float i0 = 1.f / sacc[0], i1 = 1.f / sacc[2];

    int b = bh >> 4, h = bh & 15;
#pragma unroll
    for (int j = 0; j < 8; j++) {
        int col = j * 8 + 2 * t;
        *(__half2*)(C + ((size_t)(b * TT + row0)) * DD + h * HD + col) =
            __floats2half2_rn(o[j][0] * i0, o[j][1] * i0);
        *(__half2*)(C + ((size_t)(b * TT + row1)) * DD + h * HD + col) =
            __floats2half2_rn(o[j][2] * i1, o[j][3] * i1);
    }
}

// ---------------------------------------------------------------------------
// LayerNorm (faithful bug: scale * x_norm + scale), emits fp16
// ---------------------------------------------------------------------------
__global__ void ln_kernel(const float* __restrict__ x,
                          const float* __restrict__ scale,
                          __half* __restrict__ y) {
    int row = blockIdx.x;
    const float* xr = x + (size_t)row * DD;
    __half* yr = y + (size_t)row * DD;
    int tid = threadIdx.x;
    float v[4];
    float s = 0.f, s2 = 0.f;
#pragma unroll
    for (int i = 0; i < 4; i++) {
        v[i] = xr[tid + 256 * i];
        s  += v[i];
        s2 += v[i] * v[i];
    }
    __shared__ float sh[256], sh2[256];
    sh[tid] = s; sh2[tid] = s2;
    __syncthreads();
    for (int o = 128; o > 0; o >>= 1) {
        if (tid < o) { sh[tid] += sh[tid + o]; sh2[tid] += sh2[tid + o]; }
        __syncthreads();
    }
    float mean = sh[0] * (1.f / DD);
    float var  = sh2[0] * (1.f / DD) - mean * mean;
    float rstd = rsqrtf(var + 1e-5f);
#pragma unroll
    for (int i = 0; i < 4; i++) {
        int c = tid + 256 * i;
        float sc = scale[c];
        yr[c] = __float2half(sc * ((v[i] - mean) * rstd) + sc);
    }
}

// ---------------------------------------------------------------------------
// Host driver
// ---------------------------------------------------------------------------
static void run_block(const float* x_in, const float* ln_scale,
                      const __half* wqkv, const __half* wo, const float* bo,
                      __half* lnp, __half* qkvp, __half* ctxp, float* out) {
    ln_kernel<<<BB * TT, 256>>>(x_in, ln_scale, lnp);
    mma_gemm<0><<<dim3(3 * DD / 128, (BB * TT) / 128), 256>>>(
        lnp, wqkv, nullptr, nullptr, qkvp);
    flash_attn<<<dim3(TT / 128, BB * HH), 256>>>(
        qkvp, qkvp + BTD, qkvp + 2 * BTD, ctxp);
    mma_gemm<1><<<dim3(DD / 128, (BB * TT) / 128), 256>>>(
        ctxp, wo, bo, x_in, out);
}

extern "C" void kernel_launch(void* const* d_in, const int* in_sizes, int n_in,
                              void* d_out, int out_size) {
    const float* x   = (const float*)d_in[0];
    const float* bo  = (const float*)d_in[5];
    const float* ln1 = (const float*)d_in[6];
    const float* ln2 = (const float*)d_in[7];
    float* out = (float*)d_out;

    __half *lnp, *qkvp, *ctxp, *wt;
    float* hp;
    cudaGetSymbolAddress((void**)&lnp,  g_ln);
    cudaGetSymbolAddress((void**)&qkvp, g_qkv);
    cudaGetSymbolAddress((void**)&ctxp, g_ctx);
    cudaGetSymbolAddress((void**)&hp,   g_h);
    cudaGetSymbolAddress((void**)&wt,   g_w);

    cvt_h4<<<dim3((DD * DD / 4) / 256, 4), 256>>>(
        (const float4*)d_in[1], (const float4*)d_in[2],
        (const float4*)d_in[3], (const float4*)d_in[4], (__half2*)wt);
    const __half* wqkv = wt;
    const __half* wo   = wt + (size_t)3 * DD * DD;

    run_block(x,  ln1, wqkv, wo, bo, lnp, qkvp, ctxp, hp);
    run_block(hp, ln2, wqkv, wo, bo, lnp, qkvp, ctxp, out);
}

// round 11
// speedup vs baseline: 7.6740x; 1.1014x over previous
#include <cuda_runtime.h>
#include <cuda_fp16.h>
#include <cstdint>

#define BB 2
#define TT 2048
#define DD 1024
#define HH 16
#define HD 64
#define BTD ((size_t)BB*TT*DD)

// ---- scratch (device globals: allocation-free) ----
__device__ __half g_ln  [BTD];
__device__ __half g_qkv [3 * BTD];                 // q,k,v [B,H,T,hd] fp16 (q pre-scaled by 0.125)
__device__ __half g_ctx [BTD];                     // [B,T,D] fp16
__device__ float  g_h   [BTD];                     // block-1 output (fp32)
__device__ __half g_w   [4][(size_t)DD*DD];        // wq,wk,wv,wo fp16 (qkv rows contiguous)

// ===========================================================================
// helpers
// ===========================================================================
__device__ __forceinline__ void mma16(float* c, const uint32_t* a, const uint32_t* b) {
    asm volatile(
        "mma.sync.aligned.m16n8k16.row.col.f32.f16.f16.f32 "
        "{%0,%1,%2,%3}, {%4,%5,%6,%7}, {%8,%9}, {%0,%1,%2,%3};"
        : "+f"(c[0]), "+f"(c[1]), "+f"(c[2]), "+f"(c[3])
        : "r"(a[0]), "r"(a[1]), "r"(a[2]), "r"(a[3]), "r"(b[0]), "r"(b[1]));
}
__device__ __forceinline__ void ldsm4(uint32_t& r0, uint32_t& r1,
                                      uint32_t& r2, uint32_t& r3, uint32_t addr) {
    asm volatile("ldmatrix.sync.aligned.m8n8.x4.shared.b16 {%0,%1,%2,%3}, [%4];"
        : "=r"(r0), "=r"(r1), "=r"(r2), "=r"(r3) : "r"(addr));
}
__device__ __forceinline__ void ldsm4t(uint32_t& r0, uint32_t& r1,
                                       uint32_t& r2, uint32_t& r3, uint32_t addr) {
    asm volatile("ldmatrix.sync.aligned.m8n8.x4.trans.shared.b16 {%0,%1,%2,%3}, [%4];"
        : "=r"(r0), "=r"(r1), "=r"(r2), "=r"(r3) : "r"(addr));
}
__device__ __forceinline__ uint32_t s2u(const void* p) {
    return (uint32_t)__cvta_generic_to_shared(p);
}
__device__ __forceinline__ uint32_t packh2(float lo, float hi) {
    __half2 h = __floats2half2_rn(lo, hi);
    return *(uint32_t*)&h;
}
__device__ __forceinline__ uint32_t ex2h2(uint32_t x) {   // paired fp16 exp2
    uint32_t r;
    asm("ex2.approx.f16x2 %0, %1;" : "=r"(r) : "r"(x));
    return r;
}
__device__ __forceinline__ uint32_t hmax2u(uint32_t a, uint32_t b) {
    __half2 r = __hmax2(*(__half2*)&a, *(__half2*)&b);
    return *(uint32_t*)&r;
}
__device__ __forceinline__ void cpa16(uint32_t dst, const void* src) {
    asm volatile("cp.async.ca.shared.global [%0], [%1], 16;" :: "r"(dst), "l"(src));
}
__device__ __forceinline__ void cp_commit() {
    asm volatile("cp.async.commit_group;" ::: "memory");
}
template <int N>
__device__ __forceinline__ void cp_wait() {
    asm volatile("cp.async.wait_group %0;" :: "n"(N) : "memory");
}

#define PADW 40          // dense smem row stride (halves); 80B rows
#define KP   72          // flash K/V row stride (halves); 144B rows
#define VP   72
#define FULL 0xffffffffu
#define GSTG (128 * PADW * 2)   // dense stage bytes
#define KSTG (64 * KP * 2)      // flash K/V stage bytes
#define L2E  1.4426950408889634f
#define ONE2 0x3C003C00u        // half2(1.0, 1.0)

// ===========================================================================
// weight converter: fp32 -> fp16, all 4 matrices in one launch
// ===========================================================================
__global__ void cvt_h4(const float4* __restrict__ w0, const float4* __restrict__ w1,
                       const float4* __restrict__ w2, const float4* __restrict__ w3,
                       __half2* __restrict__ out) {
    int m = blockIdx.y;
    const float4* in = (m == 0) ? w0 : (m == 1) ? w1 : (m == 2) ? w2 : w3;
    size_t base = (size_t)m * (DD * DD / 2);
    int i = blockIdx.x * 256 + threadIdx.x;
    float4 v = in[i];
    out[base + 2 * i]     = __floats2half2_rn(v.x, v.y);
    out[base + 2 * i + 1] = __floats2half2_rn(v.z, v.w);
}

// ===========================================================================
// Dense GEMM: C[4096, N] = A[4096,1024] @ W[N,1024]^T, fp16 in, fp32 accum.
// BM=BN=128, BK=32, 8 warps 2x4, warp tile 64x32, m16n8k16, ldmatrix,
// cp.async 2-stage, SINGLE barrier per k-tile (wait -> bar -> prefetch -> mma).
//   MODE 0 (N=3072, fused QKV): emit fp16 into g_qkv; q part scaled by 0.125
//   MODE 1 (N=1024, out-proj):  fp32 out = res + bias + C
// ===========================================================================
template <int MODE>
__global__ __launch_bounds__(256)
void mma_gemm(const __half* __restrict__ A, const __half* __restrict__ W,
              const float* __restrict__ bias, const float* __restrict__ res,
              void* __restrict__ outv) {
    __shared__ __align__(16) __half As[2][128 * PADW];
    __shared__ __align__(16) __half Bs[2][128 * PADW];
    int tid = threadIdx.x, lane = tid & 31, warp = tid >> 5;
    int wm = (warp >> 2) * 64, wn = (warp & 3) * 32;
    int g = lane >> 2, t = lane & 3;
    int m0 = blockIdx.y * 128, n0 = blockIdx.x * 128;

    int lrow = tid >> 2, lc8 = (tid & 3) * 8;
    const __half* Ag0 = A + (size_t)(m0 + lrow) * DD + lc8;
    const __half* Ag1 = A + (size_t)(m0 + lrow + 64) * DD + lc8;
    const __half* Wg0 = W + (size_t)(n0 + lrow) * DD + lc8;
    const __half* Wg1 = W + (size_t)(n0 + lrow + 64) * DD + lc8;
    uint32_t aS = s2u(As) + (lrow * PADW + lc8) * 2;
    uint32_t bS = s2u(Bs) + (lrow * PADW + lc8) * 2;
    const uint32_t CH = 64 * PADW * 2;

    uint32_t asb = s2u(As), bsb = s2u(Bs);
    int lr = lane & 15, lch = (lane >> 4) * 8;
    int brow = (lane & 7) + ((lane & 16) >> 1);
    int bch = (lane & 8);
    uint32_t aA[4], bA[2];
#pragma unroll
    for (int i = 0; i < 4; i++)
        aA[i] = asb + ((wm + i * 16 + lr) * PADW + lch) * 2;
#pragma unroll
    for (int jp = 0; jp < 2; jp++)
        bA[jp] = bsb + ((wn + jp * 16 + brow) * PADW + bch) * 2;

    float acc[4][4][4] = {};

    // prologue: stage 0 <- k-tile 0
    cpa16(aS, Ag0); cpa16(aS + CH, Ag1);
    cpa16(bS, Wg0); cpa16(bS + CH, Wg1);
    cp_commit();

    const int NKT = DD / 32;
    for (int kt = 0; kt < NKT; kt++) {
        cp_wait<0>();
        __syncthreads();        // publishes tile kt AND retires reads of stage kt^1
        if (kt + 1 < NKT) {     // prefetch tile kt+1 into stage (kt+1)&1, overlapped
            int k0 = (kt + 1) * 32;
            uint32_t sp = ((kt + 1) & 1) * (uint32_t)GSTG;
            cpa16(aS + sp, Ag0 + k0); cpa16(aS + sp + CH, Ag1 + k0);
            cpa16(bS + sp, Wg0 + k0); cpa16(bS + sp + CH, Wg1 + k0);
            cp_commit();
        }
        uint32_t so = (kt & 1) * (uint32_t)GSTG;
#pragma unroll
        for (int kk = 0; kk < 2; kk++) {
            int ko = kk * 32;
            uint32_t af[4][4], bf[4][2];
#pragma unroll
            for (int i = 0; i < 4; i++)
                ldsm4(af[i][0], af[i][1], af[i][2], af[i][3], aA[i] + so + ko);
#pragma unroll
            for (int jp = 0; jp < 2; jp++)
                ldsm4(bf[2*jp][0], bf[2*jp][1], bf[2*jp+1][0], bf[2*jp+1][1],
                      bA[jp] + so + ko);
#pragma unroll
            for (int i = 0; i < 4; i++)
#pragma unroll
                for (int j = 0; j < 4; j++)
                    mma16(acc[i][j], af[i], bf[j]);
        }
    }

    if (MODE == 0) {
        __half* out = (__half*)outv + (size_t)(n0 >> 10) * BTD;   // q/k/v select
        float qs = (n0 < DD) ? 0.125f : 1.f;                      // fold 1/sqrt(hd) into Q
#pragma unroll
        for (int i = 0; i < 4; i++) {
            int row = m0 + wm + i * 16 + g;
            int b = row >> 11, tt = row & 2047;
#pragma unroll
            for (int j = 0; j < 4; j++) {
                int col = (n0 & 1023) + wn + j * 8 + 2 * t;
                int h = col >> 6, d = col & 63;
                __half* d0 = out + (((size_t)(b * HH + h)) * TT + tt) * HD + d;
                __half* d1 = out + (((size_t)(b * HH + h)) * TT + tt + 8) * HD + d;
                *(__half2*)d0 = __floats2half2_rn(acc[i][j][0] * qs, acc[i][j][1] * qs);
                *(__half2*)d1 = __floats2half2_rn(acc[i][j][2] * qs, acc[i][j][3] * qs);
            }
        }
    } else {
        float* out = (float*)outv;
#pragma unroll
        for (int i = 0; i < 4; i++) {
            int row = m0 + wm + i * 16 + g;
#pragma unroll
            for (int j = 0; j < 4; j++) {
                int col = n0 + wn + j * 8 + 2 * t;
                float2 b2 = *(const float2*)(bias + col);
                float2 r0 = *(const float2*)(res + (size_t)row * DD + col);
                float2 r1 = *(const float2*)(res + (size_t)(row + 8) * DD + col);
                *(float2*)(out + (size_t)row * DD + col) =
                    make_float2(acc[i][j][0] + r0.x + b2.x, acc[i][j][1] + r0.y + b2.y);
                *(float2*)(out + (size_t)(row + 8) * DD + col) =
                    make_float2(acc[i][j][2] + r1.x + b2.x, acc[i][j][3] + r1.y + b2.y);
            }
        }
    }
}

// ===========================================================================
// Fused flash attention (fp16 in/out, fp32 accum). Q pre-scaled by 0.125.
// cp.async 2-stage, SINGLE barrier per kv-tile. Packed half2 max reduce
// (2 shuffles), conditional rescale, exp via ex2.approx.f16x2, row sums via
// an extra mma against an all-ones B fragment.
// ===========================================================================
__global__ __launch_bounds__(256)
void flash_attn(const __half* __restrict__ Q, const __half* __restrict__ K,
                const __half* __restrict__ V, __half* __restrict__ C) {
    __shared__ __align__(16) __half Ks[2][64 * KP];
    __shared__ __align__(16) __half Vs[2][64 * VP];

    int bh = blockIdx.y;
    int m0 = (gridDim.x - 1 - blockIdx.x) * 128;    // heaviest first
    const __half* Qb = Q + (size_t)bh * TT * HD;
    const __half* Kb = K + (size_t)bh * TT * HD;
    const __half* Vb = V + (size_t)bh * TT * HD;

    int tid = threadIdx.x, lane = tid & 31, warp = tid >> 5;
    int wm = warp * 16;
    int g = lane >> 2, t = lane & 3;
    int row0 = m0 + wm + g, row1 = row0 + 8;

    int lrow = tid >> 3, lc8 = (tid & 7) * 8;
    const __half* Kg0 = Kb + (size_t)lrow * HD + lc8;
    const __half* Kg1 = Kb + (size_t)(lrow + 32) * HD + lc8;
    const __half* Vg0 = Vb + (size_t)lrow * HD + lc8;
    const __half* Vg1 = Vb + (size_t)(lrow + 32) * HD + lc8;
    uint32_t kS = s2u(Ks) + (lrow * KP + lc8) * 2;
    uint32_t vS = s2u(Vs) + (lrow * VP + lc8) * 2;
    const uint32_t CHK = 32 * KP * 2, CHV = 32 * VP * 2;

    uint32_t ksb = s2u(Ks), vsb = s2u(Vs);
    int krow = (lane & 7) + ((lane & 16) >> 1);
    int kch = (lane & 8);
    uint32_t kA[4];
#pragma unroll
    for (int jp = 0; jp < 4; jp++)
        kA[jp] = ksb + ((jp * 16 + krow) * KP + kch) * 2;
    uint32_t vA = vsb + (((lane & 7) + (lane & 8)) * VP + ((lane & 16) >> 1)) * 2;

    uint32_t qf[4][4];
#pragma unroll
    for (int ks = 0; ks < 4; ks++) {
        int kb = ks * 16;
        qf[ks][0] = *(const uint32_t*)(Qb + (size_t)row0 * HD + kb + 2 * t);
        qf[ks][1] = *(const uint32_t*)(Qb + (size_t)row1 * HD + kb + 2 * t);
        qf[ks][2] = *(const uint32_t*)(Qb + (size_t)row0 * HD + kb + 8 + 2 * t);
        qf[ks][3] = *(const uint32_t*)(Qb + (size_t)row1 * HD + kb + 8 + 2 * t);
    }

    float o[8][4] = {};
    float sacc[4] = {};                  // row-sum accumulator (mma C frag)
    float rmax0 = -1e30f, rmax1 = -1e30f;
    const uint32_t onef[2] = {ONE2, ONE2};

    int nkv = (m0 + 128) / 64;
    cpa16(kS, Kg0); cpa16(kS + CHK, Kg1);
    cpa16(vS, Vg0); cpa16(vS + CHV, Vg1);
    cp_commit();

    for (int kv = 0; kv < nkv; kv++) {
        cp_wait<0>();
        __syncthreads();        // publishes tile kv AND retires reads of stage kv^1
        if (kv + 1 < nkv) {     // prefetch tile kv+1, overlapped with compute
            size_t go = (size_t)(kv + 1) * 64 * HD;
            uint32_t sk = ((kv + 1) & 1) * (uint32_t)KSTG;
            cpa16(kS + sk, Kg0 + go); cpa16(kS + sk + CHK, Kg1 + go);
            cpa16(vS + sk, Vg0 + go); cpa16(vS + sk + CHV, Vg1 + go);
            cp_commit();
        }
        int kv0 = kv * 64;
        uint32_t so = (kv & 1) * (uint32_t)KSTG;

        // ---- S = Q @ K^T (16 x 64), already scaled (Q pre-scaled) ----
        float s[8][4];
#pragma unroll
        for (int j = 0; j < 8; j++) { s[j][0]=0.f; s[j][1]=0.f; s[j][2]=0.f; s[j][3]=0.f; }
#pragma unroll
        for (int ks = 0; ks < 4; ks++) {
            int ko = ks * 32;
            uint32_t kf[8][2];
#pragma unroll
            for (int jp = 0; jp < 4; jp++)
                ldsm4(kf[2*jp][0], kf[2*jp][1], kf[2*jp+1][0], kf[2*jp+1][1],
                      kA[jp] + so + ko);
#pragma unroll
            for (int j = 0; j < 8; j++)
                mma16(s[j], qf[ks], kf[j]);
        }

        // ---- causal mask (only the diagonal tiles) ----
        if (kv0 + 64 > m0) {
#pragma unroll
            for (int j = 0; j < 8; j++) {
                int c0 = kv0 + j * 8 + 2 * t, c1 = c0 + 1;
                if (c0 > row0) s[j][0] = -1e30f;
                if (c1 > row0) s[j][1] = -1e30f;
                if (c0 > row1) s[j][2] = -1e30f;
                if (c1 > row1) s[j][3] = -1e30f;
            }
        }

        // ---- online softmax: packed half2 quad max (2 shuffles) ----
        float m0l = -1e30f, m1l = -1e30f;
#pragma unroll
        for (int j = 0; j < 8; j++) {
            m0l = fmaxf(m0l, fmaxf(s[j][0], s[j][1]));
            m1l = fmaxf(m1l, fmaxf(s[j][2], s[j][3]));
        }
        uint32_t pm = packh2(m0l, m1l);
        pm = hmax2u(pm, __shfl_xor_sync(FULL, pm, 1));
        pm = hmax2u(pm, __shfl_xor_sync(FULL, pm, 2));
        __half2 mh = *(__half2*)&pm;
        float mf0 = __low2float(mh), mf1 = __high2float(mh);
        float mn0 = fmaxf(rmax0, mf0), mn1 = fmaxf(rmax1, mf1);
        if (mf0 > rmax0 || mf1 > rmax1) {     // rescale only on a new max
            float cr0 = __expf(rmax0 - mn0), cr1 = __expf(rmax1 - mn1);
            sacc[0] *= cr0; sacc[1] *= cr0; sacc[2] *= cr1; sacc[3] *= cr1;
#pragma unroll
            for (int j = 0; j < 8; j++) {
                o[j][0] *= cr0; o[j][1] *= cr0; o[j][2] *= cr1; o[j][3] *= cr1;
            }
        }
        rmax0 = mn0; rmax1 = mn1;

        // ---- exp: FFMA to log2-domain, pack, paired fp16 exp2 -> P frags ----
        float b0 = -mn0 * L2E, b1 = -mn1 * L2E;
        uint32_t pan[4][4];
#pragma unroll
        for (int kb2 = 0; kb2 < 4; kb2++) {
            int j0 = 2 * kb2, j1 = 2 * kb2 + 1;
            pan[kb2][0] = ex2h2(packh2(fmaf(s[j0][0], L2E, b0), fmaf(s[j0][1], L2E, b0)));
            pan[kb2][1] = ex2h2(packh2(fmaf(s[j0][2], L2E, b1), fmaf(s[j0][3], L2E, b1)));
            pan[kb2][2] = ex2h2(packh2(fmaf(s[j1][0], L2E, b0), fmaf(s[j1][1], L2E, b0)));
            pan[kb2][3] = ex2h2(packh2(fmaf(s[j1][2], L2E, b1), fmaf(s[j1][3], L2E, b1)));
        }

        // ---- row sums via tensor core (B = ones) + O += P @ V ----
#pragma unroll
        for (int kb2 = 0; kb2 < 4; kb2++) {
            mma16(sacc, pan[kb2], onef);
            uint32_t vf[8][2];
#pragma unroll
            for (int jp = 0; jp < 4; jp++)
                ldsm4t(vf[2*jp][0], vf[2*jp][1], vf[2*jp+1][0], vf[2*jp+1][1],
                       vA + so + (kb2 * 16 * VP + jp * 16) * 2);
#pragma unroll
            for (int j = 0; j < 8; j++)
                mma16(o[j], pan[kb2], vf[j]);
        }
    }

    // ---- epilogue: normalize + write ctx [B,T,D] fp16 ----
    float i0 = 1.f / sacc[0], i1 = 1.f / sacc[2];

    int b = bh >> 4, h = bh & 15;
#pragma unroll
    for (int j = 0; j < 8; j++) {
        int col = j * 8 + 2 * t;
        *(__half2*)(C + ((size_t)(b * TT + row0)) * DD + h * HD + col) =
            __floats2half2_rn(o[j][0] * i0, o[j][1] * i0);
        *(__half2*)(C + ((size_t)(b * TT + row1)) * DD + h * HD + col) =
            __floats2half2_rn(o[j][2] * i1, o[j][3] * i1);
    }
}

// ---------------------------------------------------------------------------
// LayerNorm (faithful bug: scale * x_norm + scale), emits fp16
// ---------------------------------------------------------------------------
__global__ void ln_kernel(const float* __restrict__ x,
                          const float* __restrict__ scale,
                          __half* __restrict__ y) {
    int row = blockIdx.x;
    const float* xr = x + (size_t)row * DD;
    __half* yr = y + (size_t)row * DD;
    int tid = threadIdx.x;
    float v[4];
    float s = 0.f, s2 = 0.f;
#pragma unroll
    for (int i = 0; i < 4; i++) {
        v[i] = xr[tid + 256 * i];
        s  += v[i];
        s2 += v[i] * v[i];
    }
    __shared__ float sh[256], sh2[256];
    sh[tid] = s; sh2[tid] = s2;
    __syncthreads();
    for (int o = 128; o > 0; o >>= 1) {
        if (tid < o) { sh[tid] += sh[tid + o]; sh2[tid] += sh2[tid + o]; }
        __syncthreads();
    }
    float mean = sh[0] * (1.f / DD);
    float var  = sh2[0] * (1.f / DD) - mean * mean;
    float rstd = rsqrtf(var + 1e-5f);
#pragma unroll
    for (int i = 0; i < 4; i++) {
        int c = tid + 256 * i;
        float sc = scale[c];
        yr[c] = __float2half(sc * ((v[i] - mean) * rstd) + sc);
    }
}

// ---------------------------------------------------------------------------
// Host driver
// ---------------------------------------------------------------------------
static void run_block(const float* x_in, const float* ln_scale,
                      const __half* wqkv, const __half* wo, const float* bo,
                      __half* lnp, __half* qkvp, __half* ctxp, float* out) {
    ln_kernel<<<BB * TT, 256>>>(x_in, ln_scale, lnp);
    mma_gemm<0><<<dim3(3 * DD / 128, (BB * TT) / 128), 256>>>(
        lnp, wqkv, nullptr, nullptr, qkvp);
    flash_attn<<<dim3(TT / 128, BB * HH), 256>>>(
        qkvp, qkvp + BTD, qkvp + 2 * BTD, ctxp);
    mma_gemm<1><<<dim3(DD / 128, (BB * TT) / 128), 256>>>(
        ctxp, wo, bo, x_in, out);
}

extern "C" void kernel_launch(void* const* d_in, const int* in_sizes, int n_in,
                              void* d_out, int out_size) {
    const float* x   = (const float*)d_in[0];
    const float* bo  = (const float*)d_in[5];
    const float* ln1 = (const float*)d_in[6];
    const float* ln2 = (const float*)d_in[7];
    float* out = (float*)d_out;

    __half *lnp, *qkvp, *ctxp, *wt;
    float* hp;
    cudaGetSymbolAddress((void**)&lnp,  g_ln);
    cudaGetSymbolAddress((void**)&qkvp, g_qkv);
    cudaGetSymbolAddress((void**)&ctxp, g_ctx);
    cudaGetSymbolAddress((void**)&hp,   g_h);
    cudaGetSymbolAddress((void**)&wt,   g_w);

    cvt_h4<<<dim3((DD * DD / 4) / 256, 4), 256>>>(
        (const float4*)d_in[1], (const float4*)d_in[2],
        (const float4*)d_in[3], (const float4*)d_in[4], (__half2*)wt);
    const __half* wqkv = wt;
    const __half* wo   = wt + (size_t)3 * DD * DD;

    run_block(x,  ln1, wqkv, wo, bo, lnp, qkvp, ctxp, hp);
    run_block(hp, ln2, wqkv, wo, bo, lnp, qkvp, ctxp, out);
}

// round 12
// speedup vs baseline: 8.1548x; 1.0627x over previous
#include <cuda_runtime.h>
#include <cuda_fp16.h>
#include <cstdint>

#define BB 2
#define TT 2048
#define DD 1024
#define HH 16
#define HD 64
#define BTD ((size_t)BB*TT*DD)

// ---- scratch (device globals: allocation-free) ----
__device__ __half g_ln  [BTD];
__device__ __half g_qkv [3 * BTD];                 // q,k,v [B,H,T,hd] fp16 (q pre-scaled by 0.125)
__device__ __half g_ctx [BTD];                     // [B,T,D] fp16
__device__ float  g_h   [BTD];                     // block-1 output (fp32)
__device__ __half g_w   [4][(size_t)DD*DD];        // wq,wk,wv,wo fp16 (qkv rows contiguous)

// ===========================================================================
// helpers
// ===========================================================================
__device__ __forceinline__ void mma16(float* c, const uint32_t* a, const uint32_t* b) {
    asm volatile(
        "mma.sync.aligned.m16n8k16.row.col.f32.f16.f16.f32 "
        "{%0,%1,%2,%3}, {%4,%5,%6,%7}, {%8,%9}, {%0,%1,%2,%3};"
        : "+f"(c[0]), "+f"(c[1]), "+f"(c[2]), "+f"(c[3])
        : "r"(a[0]), "r"(a[1]), "r"(a[2]), "r"(a[3]), "r"(b[0]), "r"(b[1]));
}
__device__ __forceinline__ void ldsm4(uint32_t& r0, uint32_t& r1,
                                      uint32_t& r2, uint32_t& r3, uint32_t addr) {
    asm volatile("ldmatrix.sync.aligned.m8n8.x4.shared.b16 {%0,%1,%2,%3}, [%4];"
        : "=r"(r0), "=r"(r1), "=r"(r2), "=r"(r3) : "r"(addr));
}
__device__ __forceinline__ void ldsm4t(uint32_t& r0, uint32_t& r1,
                                       uint32_t& r2, uint32_t& r3, uint32_t addr) {
    asm volatile("ldmatrix.sync.aligned.m8n8.x4.trans.shared.b16 {%0,%1,%2,%3}, [%4];"
        : "=r"(r0), "=r"(r1), "=r"(r2), "=r"(r3) : "r"(addr));
}
__device__ __forceinline__ uint32_t s2u(const void* p) {
    return (uint32_t)__cvta_generic_to_shared(p);
}
__device__ __forceinline__ uint32_t packh2(float lo, float hi) {
    __half2 h = __floats2half2_rn(lo, hi);
    return *(uint32_t*)&h;
}
__device__ __forceinline__ uint32_t ex2h2(uint32_t x) {   // paired fp16 exp2
    uint32_t r;
    asm("ex2.approx.f16x2 %0, %1;" : "=r"(r) : "r"(x));
    return r;
}
__device__ __forceinline__ uint32_t hmax2u(uint32_t a, uint32_t b) {
    __half2 r = __hmax2(*(__half2*)&a, *(__half2*)&b);
    return *(uint32_t*)&r;
}
__device__ __forceinline__ void cpa16(uint32_t dst, const void* src) {
    asm volatile("cp.async.ca.shared.global [%0], [%1], 16;" :: "r"(dst), "l"(src));
}
__device__ __forceinline__ void cp_commit() {
    asm volatile("cp.async.commit_group;" ::: "memory");
}
template <int N>
__device__ __forceinline__ void cp_wait() {
    asm volatile("cp.async.wait_group %0;" :: "n"(N) : "memory");
}

#define KP   72          // flash K/V row stride (halves); 144B rows
#define VP   72
#define GP   72          // dense BK=64 row stride (halves); 144B rows
#define FULL 0xffffffffu
#define ASTB (128 * GP * 2)     // dense per-matrix per-stage bytes (18432)
#define GSMEM (4 * ASTB)        // dense dynamic smem total (73728)
#define KSTG (64 * KP * 2)      // flash K/V stage bytes
#define L2E  1.4426950408889634f
#define ONE2 0x3C003C00u        // half2(1.0, 1.0)

// ===========================================================================
// weight converter: fp32 -> fp16, all 4 matrices in one launch
// ===========================================================================
__global__ void cvt_h4(const float4* __restrict__ w0, const float4* __restrict__ w1,
                       const float4* __restrict__ w2, const float4* __restrict__ w3,
                       __half2* __restrict__ out) {
    int m = blockIdx.y;
    const float4* in = (m == 0) ? w0 : (m == 1) ? w1 : (m == 2) ? w2 : w3;
    size_t base = (size_t)m * (DD * DD / 2);
    int i = blockIdx.x * 256 + threadIdx.x;
    float4 v = in[i];
    out[base + 2 * i]     = __floats2half2_rn(v.x, v.y);
    out[base + 2 * i + 1] = __floats2half2_rn(v.z, v.w);
}

// ===========================================================================
// Dense GEMM: C[4096, N] = A[4096,1024] @ W[N,1024]^T, fp16 in, fp32 accum.
// BM=BN=128, BK=64, 8 warps 2x4, warp tile 64x32, m16n8k16, ldmatrix,
// cp.async 2-stage (dynamic smem), SINGLE barrier per 64-wide k-tile.
//   MODE 0 (N=3072, fused QKV): emit fp16 into g_qkv; q part scaled by 0.125
//   MODE 1 (N=1024, out-proj):  fp32 out = res + bias + C
// smem layout (bytes): A[st0], A[st1], B[st0], B[st1], each ASTB.
// ===========================================================================
template <int MODE>
__global__ __launch_bounds__(256)
void mma_gemm(const __half* __restrict__ A, const __half* __restrict__ W,
              const float* __restrict__ bias, const float* __restrict__ res,
              void* __restrict__ outv) {
    extern __shared__ __align__(16) __half dsm[];
    uint32_t base = s2u(dsm);
    int tid = threadIdx.x, lane = tid & 31, warp = tid >> 5;
    int wm = (warp >> 2) * 64, wn = (warp & 3) * 32;
    int g = lane >> 2, t = lane & 3;
    int m0 = blockIdx.y * 128, n0 = blockIdx.x * 128;

    // cp.async geometry: 32 rows x 64 halves per pass; 4 row-groups cover 128
    int lrow = tid >> 3, lc8 = (tid & 7) * 8;
    const __half* Ag = A + (size_t)(m0 + lrow) * DD + lc8;
    const __half* Wg = W + (size_t)(n0 + lrow) * DD + lc8;
    uint32_t aS = base + (lrow * GP + lc8) * 2;              // A stage 0
    uint32_t bS = base + 2 * ASTB + (lrow * GP + lc8) * 2;   // B stage 0
    const uint32_t RG = 32 * GP * 2;                          // row-group smem stride
    const size_t   RGg = (size_t)32 * DD;                     // row-group gmem stride

    // ldmatrix lane addresses (stage 0)
    int lr = lane & 15, lch = (lane >> 4) * 8;
    int brow = (lane & 7) + ((lane & 16) >> 1);
    int bch = (lane & 8);
    uint32_t aA[4], bA[2];
#pragma unroll
    for (int i = 0; i < 4; i++)
        aA[i] = base + ((wm + i * 16 + lr) * GP + lch) * 2;
#pragma unroll
    for (int jp = 0; jp < 2; jp++)
        bA[jp] = base + 2 * ASTB + ((wn + jp * 16 + brow) * GP + bch) * 2;

    float acc[4][4][4] = {};

    // prologue: stage 0 <- k-tile 0
#pragma unroll
    for (int rg = 0; rg < 4; rg++) {
        cpa16(aS + rg * RG, Ag + rg * RGg);
        cpa16(bS + rg * RG, Wg + rg * RGg);
    }
    cp_commit();

    const int NKT = DD / 64;                      // 16
    for (int kt = 0; kt < NKT; kt++) {
        cp_wait<0>();
        __syncthreads();        // publishes tile kt AND retires reads of stage kt^1
        if (kt + 1 < NKT) {     // prefetch tile kt+1, fully overlapped
            int k0 = (kt + 1) * 64;
            uint32_t sp = ((kt + 1) & 1) * (uint32_t)ASTB;
#pragma unroll
            for (int rg = 0; rg < 4; rg++) {
                cpa16(aS + sp + rg * RG, Ag + rg * RGg + k0);
                cpa16(bS + sp + rg * RG, Wg + rg * RGg + k0);
            }
            cp_commit();
        }
        uint32_t so = (kt & 1) * (uint32_t)ASTB;
#pragma unroll
        for (int kk = 0; kk < 4; kk++) {          // 4 x k16 chunks
            int ko = kk * 32;                     // bytes
            uint32_t af[4][4], bf[4][2];
#pragma unroll
            for (int i = 0; i < 4; i++)
                ldsm4(af[i][0], af[i][1], af[i][2], af[i][3], aA[i] + so + ko);
#pragma unroll
            for (int jp = 0; jp < 2; jp++)
                ldsm4(bf[2*jp][0], bf[2*jp][1], bf[2*jp+1][0], bf[2*jp+1][1],
                      bA[jp] + so + ko);
#pragma unroll
            for (int i = 0; i < 4; i++)
#pragma unroll
                for (int j = 0; j < 4; j++)
                    mma16(acc[i][j], af[i], bf[j]);
        }
    }

    if (MODE == 0) {
        __half* out = (__half*)outv + (size_t)(n0 >> 10) * BTD;   // q/k/v select
        float qs = (n0 < DD) ? 0.125f : 1.f;                      // fold 1/sqrt(hd) into Q
#pragma unroll
        for (int i = 0; i < 4; i++) {
            int row = m0 + wm + i * 16 + g;
            int b = row >> 11, tt = row & 2047;
#pragma unroll
            for (int j = 0; j < 4; j++) {
                int col = (n0 & 1023) + wn + j * 8 + 2 * t;
                int h = col >> 6, d = col & 63;
                __half* d0 = out + (((size_t)(b * HH + h)) * TT + tt) * HD + d;
                __half* d1 = out + (((size_t)(b * HH + h)) * TT + tt + 8) * HD + d;
                *(__half2*)d0 = __floats2half2_rn(acc[i][j][0] * qs, acc[i][j][1] * qs);
                *(__half2*)d1 = __floats2half2_rn(acc[i][j][2] * qs, acc[i][j][3] * qs);
            }
        }
    } else {
        float* out = (float*)outv;
#pragma unroll
        for (int i = 0; i < 4; i++) {
            int row = m0 + wm + i * 16 + g;
#pragma unroll
            for (int j = 0; j < 4; j++) {
                int col = n0 + wn + j * 8 + 2 * t;
                float2 b2 = *(const float2*)(bias + col);
                float2 r0 = *(const float2*)(res + (size_t)row * DD + col);
                float2 r1 = *(const float2*)(res + (size_t)(row + 8) * DD + col);
                *(float2*)(out + (size_t)row * DD + col) =
                    make_float2(acc[i][j][0] + r0.x + b2.x, acc[i][j][1] + r0.y + b2.y);
                *(float2*)(out + (size_t)(row + 8) * DD + col) =
                    make_float2(acc[i][j][2] + r1.x + b2.x, acc[i][j][3] + r1.y + b2.y);
            }
        }
    }
}

// ===========================================================================
// Fused flash attention (fp16 in/out, fp32 accum). Q pre-scaled by 0.125.
// cp.async 2-stage, single barrier per kv-tile. Packed half2 max reduce,
// conditional rescale, exp via ex2.approx.f16x2, row sums via an extra mma
// against an all-ones B fragment.
// ===========================================================================
__global__ __launch_bounds__(256)
void flash_attn(const __half* __restrict__ Q, const __half* __restrict__ K,
                const __half* __restrict__ V, __half* __restrict__ C) {
    __shared__ __align__(16) __half Ks[2][64 * KP];
    __shared__ __align__(16) __half Vs[2][64 * VP];

    int bh = blockIdx.y;
    int m0 = (gridDim.x - 1 - blockIdx.x) * 128;    // heaviest first
    const __half* Qb = Q + (size_t)bh * TT * HD;
    const __half* Kb = K + (size_t)bh * TT * HD;
    const __half* Vb = V + (size_t)bh * TT * HD;

    int tid = threadIdx.x, lane = tid & 31, warp = tid >> 5;
    int wm = warp * 16;
    int g = lane >> 2, t = lane & 3;
    int row0 = m0 + wm + g, row1 = row0 + 8;

    int lrow = tid >> 3, lc8 = (tid & 7) * 8;
    const __half* Kg0 = Kb + (size_t)lrow * HD + lc8;
    const __half* Kg1 = Kb + (size_t)(lrow + 32) * HD + lc8;
    const __half* Vg0 = Vb + (size_t)lrow * HD + lc8;
    const __half* Vg1 = Vb + (size_t)(lrow + 32) * HD + lc8;
    uint32_t kS = s2u(Ks) + (lrow * KP + lc8) * 2;
    uint32_t vS = s2u(Vs) + (lrow * VP + lc8) * 2;
    const uint32_t CHK = 32 * KP * 2, CHV = 32 * VP * 2;

    uint32_t ksb = s2u(Ks), vsb = s2u(Vs);
    int krow = (lane & 7) + ((lane & 16) >> 1);
    int kch = (lane & 8);
    uint32_t kA[4];
#pragma unroll
    for (int jp = 0; jp < 4; jp++)
        kA[jp] = ksb + ((jp * 16 + krow) * KP + kch) * 2;
    uint32_t vA = vsb + (((lane & 7) + (lane & 8)) * VP + ((lane & 16) >> 1)) * 2;

    uint32_t qf[4][4];
#pragma unroll
    for (int ks = 0; ks < 4; ks++) {
        int kb = ks * 16;
        qf[ks][0] = *(const uint32_t*)(Qb + (size_t)row0 * HD + kb + 2 * t);
        qf[ks][1] = *(const uint32_t*)(Qb + (size_t)row1 * HD + kb + 2 * t);
        qf[ks][2] = *(const uint32_t*)(Qb + (size_t)row0 * HD + kb + 8 + 2 * t);
        qf[ks][3] = *(const uint32_t*)(Qb + (size_t)row1 * HD + kb + 8 + 2 * t);
    }

    float o[8][4] = {};
    float sacc[4] = {};                  // row-sum accumulator (mma C frag)
    float rmax0 = -1e30f, rmax1 = -1e30f;
    const uint32_t onef[2] = {ONE2, ONE2};

    int nkv = (m0 + 128) / 64;
    cpa16(kS, Kg0); cpa16(kS + CHK, Kg1);
    cpa16(vS, Vg0); cpa16(vS + CHV, Vg1);
    cp_commit();

    for (int kv = 0; kv < nkv; kv++) {
        cp_wait<0>();
        __syncthreads();        // publishes tile kv AND retires reads of stage kv^1
        if (kv + 1 < nkv) {     // prefetch tile kv+1, overlapped with compute
            size_t go = (size_t)(kv + 1) * 64 * HD;
            uint32_t sk = ((kv + 1) & 1) * (uint32_t)KSTG;
            cpa16(kS + sk, Kg0 + go); cpa16(kS + sk + CHK, Kg1 + go);
            cpa16(vS + sk, Vg0 + go); cpa16(vS + sk + CHV, Vg1 + go);
            cp_commit();
        }
        int kv0 = kv * 64;
        uint32_t so = (kv & 1) * (uint32_t)KSTG;

        // ---- S = Q @ K^T (16 x 64), already scaled (Q pre-scaled) ----
        float s[8][4];
#pragma unroll
        for (int j = 0; j < 8; j++) { s[j][0]=0.f; s[j][1]=0.f; s[j][2]=0.f; s[j][3]=0.f; }
#pragma unroll
        for (int ks = 0; ks < 4; ks++) {
            int ko = ks * 32;
            uint32_t kf[8][2];
#pragma unroll
            for (int jp = 0; jp < 4; jp++)
                ldsm4(kf[2*jp][0], kf[2*jp][1], kf[2*jp+1][0], kf[2*jp+1][1],
                      kA[jp] + so + ko);
#pragma unroll
            for (int j = 0; j < 8; j++)
                mma16(s[j], qf[ks], kf[j]);
        }

        // ---- causal mask (only the diagonal tiles) ----
        if (kv0 + 64 > m0) {
#pragma unroll
            for (int j = 0; j < 8; j++) {
                int c0 = kv0 + j * 8 + 2 * t, c1 = c0 + 1;
                if (c0 > row0) s[j][0] = -1e30f;
                if (c1 > row0) s[j][1] = -1e30f;
                if (c0 > row1) s[j][2] = -1e30f;
                if (c1 > row1) s[j][3] = -1e30f;
            }
        }

        // ---- online softmax: packed half2 quad max (2 shuffles) ----
        float m0l = -1e30f, m1l = -1e30f;
#pragma unroll
        for (int j = 0; j < 8; j++) {
            m0l = fmaxf(m0l, fmaxf(s[j][0], s[j][1]));
            m1l = fmaxf(m1l, fmaxf(s[j][2], s[j][3]));
        }
        uint32_t pm = packh2(m0l, m1l);
        pm = hmax2u(pm, __shfl_xor_sync(FULL, pm, 1));
        pm = hmax2u(pm, __shfl_xor_sync(FULL, pm, 2));
        __half2 mh = *(__half2*)&pm;
        float mf0 = __low2float(mh), mf1 = __high2float(mh);
        float mn0 = fmaxf(rmax0, mf0), mn1 = fmaxf(rmax1, mf1);
        if (mf0 > rmax0 || mf1 > rmax1) {     // rescale only on a new max
            float cr0 = __expf(rmax0 - mn0), cr1 = __expf(rmax1 - mn1);
            sacc[0] *= cr0; sacc[1] *= cr0; sacc[2] *= cr1; sacc[3] *= cr1;
#pragma unroll
            for (int j = 0; j < 8; j++) {
                o[j][0] *= cr0; o[j][1] *= cr0; o[j][2] *= cr1; o[j][3] *= cr1;
            }
        }
        rmax0 = mn0; rmax1 = mn1;

        // ---- exp: FFMA to log2-domain, pack, paired fp16 exp2 -> P frags ----
        float b0 = -mn0 * L2E, b1 = -mn1 * L2E;
        uint32_t pan[4][4];
#pragma unroll
        for (int kb2 = 0; kb2 < 4; kb2++) {
            int j0 = 2 * kb2, j1 = 2 * kb2 + 1;
            pan[kb2][0] = ex2h2(packh2(fmaf(s[j0][0], L2E, b0), fmaf(s[j0][1], L2E, b0)));
            pan[kb2][1] = ex2h2(packh2(fmaf(s[j0][2], L2E, b1), fmaf(s[j0][3], L2E, b1)));
            pan[kb2][2] = ex2h2(packh2(fmaf(s[j1][0], L2E, b0), fmaf(s[j1][1], L2E, b0)));
            pan[kb2][3] = ex2h2(packh2(fmaf(s[j1][2], L2E, b1), fmaf(s[j1][3], L2E, b1)));
        }

        // ---- row sums via tensor core (B = ones) + O += P @ V ----
#pragma unroll
        for (int kb2 = 0; kb2 < 4; kb2++) {
            mma16(sacc, pan[kb2], onef);
            uint32_t vf[8][2];
#pragma unroll
            for (int jp = 0; jp < 4; jp++)
                ldsm4t(vf[2*jp][0], vf[2*jp][1], vf[2*jp+1][0], vf[2*jp+1][1],
                       vA + so + (kb2 * 16 * VP + jp * 16) * 2);
#pragma unroll
            for (int j = 0; j < 8; j++)
                mma16(o[j], pan[kb2], vf[j]);
        }
    }

    // ---- epilogue: normalize + write ctx [B,T,D] fp16 ----
    float i0 = 1.f / sacc[0], i1 = 1.f / sacc[2];

    int b = bh >> 4, h = bh & 15;
#pragma unroll
    for (int j = 0; j < 8; j++) {
        int col = j * 8 + 2 * t;
        *(__half2*)(C + ((size_t)(b * TT + row0)) * DD + h * HD + col) =
            __floats2half2_rn(o[j][0] * i0, o[j][1] * i0);
        *(__half2*)(C + ((size_t)(b * TT + row1)) * DD + h * HD + col) =
            __floats2half2_rn(o[j][2] * i1, o[j][3] * i1);
    }
}

// ---------------------------------------------------------------------------
// LayerNorm (faithful bug: scale * x_norm + scale), emits fp16
// ---------------------------------------------------------------------------
__global__ void ln_kernel(const float* __restrict__ x,
                          const float* __restrict__ scale,
                          __half* __restrict__ y) {
    int row = blockIdx.x;
    const float* xr = x + (size_t)row * DD;
    __half* yr = y + (size_t)row * DD;
    int tid = threadIdx.x;
    float v[4];
    float s = 0.f, s2 = 0.f;
#pragma unroll
    for (int i = 0; i < 4; i++) {
        v[i] = xr[tid + 256 * i];
        s  += v[i];
        s2 += v[i] * v[i];
    }
    __shared__ float sh[256], sh2[256];
    sh[tid] = s; sh2[tid] = s2;
    __syncthreads();
    for (int o = 128; o > 0; o >>= 1) {
        if (tid < o) { sh[tid] += sh[tid + o]; sh2[tid] += sh2[tid + o]; }
        __syncthreads();
    }
    float mean = sh[0] * (1.f / DD);
    float var  = sh2[0] * (1.f / DD) - mean * mean;
    float rstd = rsqrtf(var + 1e-5f);
#pragma unroll
    for (int i = 0; i < 4; i++) {
        int c = tid + 256 * i;
        float sc = scale[c];
        yr[c] = __float2half(sc * ((v[i] - mean) * rstd) + sc);
    }
}

// ---------------------------------------------------------------------------
// Host driver
// ---------------------------------------------------------------------------
static void run_block(const float* x_in, const float* ln_scale,
                      const __half* wqkv, const __half* wo, const float* bo,
                      __half* lnp, __half* qkvp, __half* ctxp, float* out) {
    ln_kernel<<<BB * TT, 256>>>(x_in, ln_scale, lnp);
    mma_gemm<0><<<dim3(3 * DD / 128, (BB * TT) / 128), 256, GSMEM>>>(
        lnp, wqkv, nullptr, nullptr, qkvp);
    flash_attn<<<dim3(TT / 128, BB * HH), 256>>>(
        qkvp, qkvp + BTD, qkvp + 2 * BTD, ctxp);
    mma_gemm<1><<<dim3(DD / 128, (BB * TT) / 128), 256, GSMEM>>>(
        ctxp, wo, bo, x_in, out);
}

extern "C" void kernel_launch(void* const* d_in, const int* in_sizes, int n_in,
                              void* d_out, int out_size) {
    const float* x   = (const float*)d_in[0];
    const float* bo  = (const float*)d_in[5];
    const float* ln1 = (const float*)d_in[6];
    const float* ln2 = (const float*)d_in[7];
    float* out = (float*)d_out;

    // allow > 48KB dynamic smem for the dense GEMMs (attribute set, not alloc;
    // executes immediately even under graph capture and persists)
    static bool attr_set = false;
    if (!attr_set) {
        cudaFuncSetAttribute(mma_gemm<0>, cudaFuncAttributeMaxDynamicSharedMemorySize, GSMEM);
        cudaFuncSetAttribute(mma_gemm<1>, cudaFuncAttributeMaxDynamicSharedMemorySize, GSMEM);
        attr_set = true;
    }

    __half *lnp, *qkvp, *ctxp, *wt;
    float* hp;
    cudaGetSymbolAddress((void**)&lnp,  g_ln);
    cudaGetSymbolAddress((void**)&qkvp, g_qkv);
    cudaGetSymbolAddress((void**)&ctxp, g_ctx);
    cudaGetSymbolAddress((void**)&hp,   g_h);
    cudaGetSymbolAddress((void**)&wt,   g_w);

    cvt_h4<<<dim3((DD * DD / 4) / 256, 4), 256>>>(
        (const float4*)d_in[1], (const float4*)d_in[2],
        (const float4*)d_in[3], (const float4*)d_in[4], (__half2*)wt);
    const __half* wqkv = wt;
    const __half* wo   = wt + (size_t)3 * DD * DD;

    run_block(x,  ln1, wqkv, wo, bo, lnp, qkvp, ctxp, hp);
    run_block(hp, ln2, wqkv, wo, bo, lnp, qkvp, ctxp, out);
}

// round 13
// speedup vs baseline: 8.5403x; 1.0473x over previous
#include <cuda_runtime.h>
#include <cuda_fp16.h>
#include <cstdint>

#define BB 2
#define TT 2048
#define DD 1024
#define HH 16
#define HD 64
#define BTD ((size_t)BB*TT*DD)

// ---- scratch (device globals: allocation-free) ----
__device__ __half g_ln  [BTD];
__device__ __half g_qkv [3 * BTD];                 // q,k,v [B,H,T,hd] fp16 (q pre-scaled by 0.125)
__device__ __half g_ctx [BTD];                     // [B,T,D] fp16
__device__ float  g_h   [BTD];                     // block-1 output (fp32)
__device__ __half g_w   [4][(size_t)DD*DD];        // wq,wk,wv,wo fp16 (qkv rows contiguous)

// ===========================================================================
// helpers
// ===========================================================================
__device__ __forceinline__ void mma16(float* c, const uint32_t* a, const uint32_t* b) {
    asm volatile(
        "mma.sync.aligned.m16n8k16.row.col.f32.f16.f16.f32 "
        "{%0,%1,%2,%3}, {%4,%5,%6,%7}, {%8,%9}, {%0,%1,%2,%3};"
        : "+f"(c[0]), "+f"(c[1]), "+f"(c[2]), "+f"(c[3])
        : "r"(a[0]), "r"(a[1]), "r"(a[2]), "r"(a[3]), "r"(b[0]), "r"(b[1]));
}
__device__ __forceinline__ void ldsm4(uint32_t& r0, uint32_t& r1,
                                      uint32_t& r2, uint32_t& r3, uint32_t addr) {
    asm volatile("ldmatrix.sync.aligned.m8n8.x4.shared.b16 {%0,%1,%2,%3}, [%4];"
        : "=r"(r0), "=r"(r1), "=r"(r2), "=r"(r3) : "r"(addr));
}
__device__ __forceinline__ void ldsm4t(uint32_t& r0, uint32_t& r1,
                                       uint32_t& r2, uint32_t& r3, uint32_t addr) {
    asm volatile("ldmatrix.sync.aligned.m8n8.x4.trans.shared.b16 {%0,%1,%2,%3}, [%4];"
        : "=r"(r0), "=r"(r1), "=r"(r2), "=r"(r3) : "r"(addr));
}
__device__ __forceinline__ uint32_t s2u(const void* p) {
    return (uint32_t)__cvta_generic_to_shared(p);
}
__device__ __forceinline__ uint32_t packh2(float lo, float hi) {
    __half2 h = __floats2half2_rn(lo, hi);
    return *(uint32_t*)&h;
}
__device__ __forceinline__ uint32_t ex2h2(uint32_t x) {   // paired fp16 exp2
    uint32_t r;
    asm("ex2.approx.f16x2 %0, %1;" : "=r"(r) : "r"(x));
    return r;
}
__device__ __forceinline__ uint32_t hmax2u(uint32_t a, uint32_t b) {
    __half2 r = __hmax2(*(__half2*)&a, *(__half2*)&b);
    return *(uint32_t*)&r;
}
__device__ __forceinline__ void cpa16(uint32_t dst, const void* src) {
    asm volatile("cp.async.ca.shared.global [%0], [%1], 16;" :: "r"(dst), "l"(src));
}
__device__ __forceinline__ void cp_commit() {
    asm volatile("cp.async.commit_group;" ::: "memory");
}
template <int N>
__device__ __forceinline__ void cp_wait() {
    asm volatile("cp.async.wait_group %0;" :: "n"(N) : "memory");
}

#define KP   72          // flash K/V row stride (halves); 144B rows
#define VP   72
#define GP   72          // dense BK=64 row stride (halves); 144B rows
#define FULL 0xffffffffu
#define ASTB (128 * GP * 2)     // dense per-matrix per-stage bytes (18432)
#define GSMEM (4 * ASTB)        // dense dynamic smem total (73728)
#define KSTG (64 * KP * 2)      // flash K/V stage bytes
#define L2E  1.4426950408889634f
#define ONE2 0x3C003C00u        // half2(1.0, 1.0)

// ===========================================================================
// weight converter: fp32 -> fp16, all 4 matrices in one launch
// ===========================================================================
__global__ void cvt_h4(const float4* __restrict__ w0, const float4* __restrict__ w1,
                       const float4* __restrict__ w2, const float4* __restrict__ w3,
                       __half2* __restrict__ out) {
    int m = blockIdx.y;
    const float4* in = (m == 0) ? w0 : (m == 1) ? w1 : (m == 2) ? w2 : w3;
    size_t base = (size_t)m * (DD * DD / 2);
    int i = blockIdx.x * 256 + threadIdx.x;
    float4 v = in[i];
    out[base + 2 * i]     = __floats2half2_rn(v.x, v.y);
    out[base + 2 * i + 1] = __floats2half2_rn(v.z, v.w);
}

// ===========================================================================
// Dense GEMM: C[4096, N] = A[4096,1024] @ W[N,1024]^T, fp16 in, fp32 accum.
// BM=BN=128, BK=64, 8 warps 2x4, warp tile 64x32, m16n8k16, ldmatrix,
// cp.async 2-stage (dynamic smem), SINGLE barrier per 64-wide k-tile.
//   MODE 0 (N=3072, fused QKV): emit fp16 into g_qkv; q part scaled by 0.125
//   MODE 1 (N=1024, out-proj):  fp32 out = res + bias + C
// ===========================================================================
template <int MODE>
__global__ __launch_bounds__(256)
void mma_gemm(const __half* __restrict__ A, const __half* __restrict__ W,
              const float* __restrict__ bias, const float* __restrict__ res,
              void* __restrict__ outv) {
    extern __shared__ __align__(16) __half dsm[];
    uint32_t base = s2u(dsm);
    int tid = threadIdx.x, lane = tid & 31, warp = tid >> 5;
    int wm = (warp >> 2) * 64, wn = (warp & 3) * 32;
    int g = lane >> 2, t = lane & 3;
    int m0 = blockIdx.y * 128, n0 = blockIdx.x * 128;

    int lrow = tid >> 3, lc8 = (tid & 7) * 8;
    const __half* Ag = A + (size_t)(m0 + lrow) * DD + lc8;
    const __half* Wg = W + (size_t)(n0 + lrow) * DD + lc8;
    uint32_t aS = base + (lrow * GP + lc8) * 2;
    uint32_t bS = base + 2 * ASTB + (lrow * GP + lc8) * 2;
    const uint32_t RG = 32 * GP * 2;
    const size_t   RGg = (size_t)32 * DD;

    int lr = lane & 15, lch = (lane >> 4) * 8;
    int brow = (lane & 7) + ((lane & 16) >> 1);
    int bch = (lane & 8);
    uint32_t aA[4], bA[2];
#pragma unroll
    for (int i = 0; i < 4; i++)
        aA[i] = base + ((wm + i * 16 + lr) * GP + lch) * 2;
#pragma unroll
    for (int jp = 0; jp < 2; jp++)
        bA[jp] = base + 2 * ASTB + ((wn + jp * 16 + brow) * GP + bch) * 2;

    float acc[4][4][4] = {};

#pragma unroll
    for (int rg = 0; rg < 4; rg++) {
        cpa16(aS + rg * RG, Ag + rg * RGg);
        cpa16(bS + rg * RG, Wg + rg * RGg);
    }
    cp_commit();

    const int NKT = DD / 64;
    for (int kt = 0; kt < NKT; kt++) {
        cp_wait<0>();
        __syncthreads();
        if (kt + 1 < NKT) {
            int k0 = (kt + 1) * 64;
            uint32_t sp = ((kt + 1) & 1) * (uint32_t)ASTB;
#pragma unroll
            for (int rg = 0; rg < 4; rg++) {
                cpa16(aS + sp + rg * RG, Ag + rg * RGg + k0);
                cpa16(bS + sp + rg * RG, Wg + rg * RGg + k0);
            }
            cp_commit();
        }
        uint32_t so = (kt & 1) * (uint32_t)ASTB;
#pragma unroll
        for (int kk = 0; kk < 4; kk++) {
            int ko = kk * 32;
            uint32_t af[4][4], bf[4][2];
#pragma unroll
            for (int i = 0; i < 4; i++)
                ldsm4(af[i][0], af[i][1], af[i][2], af[i][3], aA[i] + so + ko);
#pragma unroll
            for (int jp = 0; jp < 2; jp++)
                ldsm4(bf[2*jp][0], bf[2*jp][1], bf[2*jp+1][0], bf[2*jp+1][1],
                      bA[jp] + so + ko);
#pragma unroll
            for (int i = 0; i < 4; i++)
#pragma unroll
                for (int j = 0; j < 4; j++)
                    mma16(acc[i][j], af[i], bf[j]);
        }
    }

    if (MODE == 0) {
        __half* out = (__half*)outv + (size_t)(n0 >> 10) * BTD;
        float qs = (n0 < DD) ? 0.125f : 1.f;
#pragma unroll
        for (int i = 0; i < 4; i++) {
            int row = m0 + wm + i * 16 + g;
            int b = row >> 11, tt = row & 2047;
#pragma unroll
            for (int j = 0; j < 4; j++) {
                int col = (n0 & 1023) + wn + j * 8 + 2 * t;
                int h = col >> 6, d = col & 63;
                __half* d0 = out + (((size_t)(b * HH + h)) * TT + tt) * HD + d;
                __half* d1 = out + (((size_t)(b * HH + h)) * TT + tt + 8) * HD + d;
                *(__half2*)d0 = __floats2half2_rn(acc[i][j][0] * qs, acc[i][j][1] * qs);
                *(__half2*)d1 = __floats2half2_rn(acc[i][j][2] * qs, acc[i][j][3] * qs);
            }
        }
    } else {
        float* out = (float*)outv;
#pragma unroll
        for (int i = 0; i < 4; i++) {
            int row = m0 + wm + i * 16 + g;
#pragma unroll
            for (int j = 0; j < 4; j++) {
                int col = n0 + wn + j * 8 + 2 * t;
                float2 b2 = *(const float2*)(bias + col);
                float2 r0 = *(const float2*)(res + (size_t)row * DD + col);
                float2 r1 = *(const float2*)(res + (size_t)(row + 8) * DD + col);
                *(float2*)(out + (size_t)row * DD + col) =
                    make_float2(acc[i][j][0] + r0.x + b2.x, acc[i][j][1] + r0.y + b2.y);
                *(float2*)(out + (size_t)(row + 8) * DD + col) =
                    make_float2(acc[i][j][2] + r1.x + b2.x, acc[i][j][3] + r1.y + b2.y);
            }
        }
    }
}

// ===========================================================================
// Fused flash attention (fp16 in/out, fp32 accum). Q pre-scaled by 0.125.
// 64 q-rows per CTA, 128 threads (4 warps x 16 rows) -> 4 CTAs/SM residency.
// cp.async 2-stage, single barrier per kv-tile. Packed half2 max reduce,
// conditional rescale, ex2.approx.f16x2 exp, row sums via ones-mma.
// ===========================================================================
__global__ __launch_bounds__(128, 4)
void flash_attn(const __half* __restrict__ Q, const __half* __restrict__ K,
                const __half* __restrict__ V, __half* __restrict__ C) {
    __shared__ __align__(16) __half Ks[2][64 * KP];
    __shared__ __align__(16) __half Vs[2][64 * VP];

    int bh = blockIdx.y;
    int m0 = (gridDim.x - 1 - blockIdx.x) * 64;     // heaviest first
    const __half* Qb = Q + (size_t)bh * TT * HD;
    const __half* Kb = K + (size_t)bh * TT * HD;
    const __half* Vb = V + (size_t)bh * TT * HD;

    int tid = threadIdx.x, lane = tid & 31, warp = tid >> 5;
    int wm = warp * 16;                              // 4 warps cover 64 rows
    int g = lane >> 2, t = lane & 3;
    int row0 = m0 + wm + g, row1 = row0 + 8;

    // cp.async: 64 rows x 64 halves per matrix = 512 chunks; 128 thr -> 4/matrix
    int lrow = tid >> 3, lc8 = (tid & 7) * 8;        // rows 0..15 base
    const __half* Kg = Kb + (size_t)lrow * HD + lc8;
    const __half* Vg = Vb + (size_t)lrow * HD + lc8;
    uint32_t kS = s2u(Ks) + (lrow * KP + lc8) * 2;
    uint32_t vS = s2u(Vs) + (lrow * VP + lc8) * 2;
    const uint32_t RGK = 16 * KP * 2, RGV = 16 * VP * 2;
    const size_t RGg = (size_t)16 * HD;

    uint32_t ksb = s2u(Ks), vsb = s2u(Vs);
    int krow = (lane & 7) + ((lane & 16) >> 1);
    int kch = (lane & 8);
    uint32_t kA[4];
#pragma unroll
    for (int jp = 0; jp < 4; jp++)
        kA[jp] = ksb + ((jp * 16 + krow) * KP + kch) * 2;
    uint32_t vA = vsb + (((lane & 7) + (lane & 8)) * VP + ((lane & 16) >> 1)) * 2;

    uint32_t qf[4][4];
#pragma unroll
    for (int ks = 0; ks < 4; ks++) {
        int kb = ks * 16;
        qf[ks][0] = *(const uint32_t*)(Qb + (size_t)row0 * HD + kb + 2 * t);
        qf[ks][1] = *(const uint32_t*)(Qb + (size_t)row1 * HD + kb + 2 * t);
        qf[ks][2] = *(const uint32_t*)(Qb + (size_t)row0 * HD + kb + 8 + 2 * t);
        qf[ks][3] = *(const uint32_t*)(Qb + (size_t)row1 * HD + kb + 8 + 2 * t);
    }

    float o[8][4] = {};
    float sacc[4] = {};
    float rmax0 = -1e30f, rmax1 = -1e30f;
    const uint32_t onef[2] = {ONE2, ONE2};

    int nkv = (m0 + 64) / 64;
#pragma unroll
    for (int rg = 0; rg < 4; rg++) {
        cpa16(kS + rg * RGK, Kg + rg * RGg);
        cpa16(vS + rg * RGV, Vg + rg * RGg);
    }
    cp_commit();

    for (int kv = 0; kv < nkv; kv++) {
        cp_wait<0>();
        __syncthreads();
        if (kv + 1 < nkv) {
            size_t go = (size_t)(kv + 1) * 64 * HD;
            uint32_t sk = ((kv + 1) & 1) * (uint32_t)KSTG;
#pragma unroll
            for (int rg = 0; rg < 4; rg++) {
                cpa16(kS + sk + rg * RGK, Kg + go + rg * RGg);
                cpa16(vS + sk + rg * RGV, Vg + go + rg * RGg);
            }
            cp_commit();
        }
        int kv0 = kv * 64;
        uint32_t so = (kv & 1) * (uint32_t)KSTG;

        // ---- S = Q @ K^T (16 x 64) ----
        float s[8][4];
#pragma unroll
        for (int j = 0; j < 8; j++) { s[j][0]=0.f; s[j][1]=0.f; s[j][2]=0.f; s[j][3]=0.f; }
#pragma unroll
        for (int ks = 0; ks < 4; ks++) {
            int ko = ks * 32;
            uint32_t kf[8][2];
#pragma unroll
            for (int jp = 0; jp < 4; jp++)
                ldsm4(kf[2*jp][0], kf[2*jp][1], kf[2*jp+1][0], kf[2*jp+1][1],
                      kA[jp] + so + ko);
#pragma unroll
            for (int j = 0; j < 8; j++)
                mma16(s[j], qf[ks], kf[j]);
        }

        // ---- causal mask (diagonal tile only) ----
        if (kv0 + 64 > m0) {
#pragma unroll
            for (int j = 0; j < 8; j++) {
                int c0 = kv0 + j * 8 + 2 * t, c1 = c0 + 1;
                if (c0 > row0) s[j][0] = -1e30f;
                if (c1 > row0) s[j][1] = -1e30f;
                if (c0 > row1) s[j][2] = -1e30f;
                if (c1 > row1) s[j][3] = -1e30f;
            }
        }

        // ---- online softmax: packed half2 quad max (2 shuffles) ----
        float m0l = -1e30f, m1l = -1e30f;
#pragma unroll
        for (int j = 0; j < 8; j++) {
            m0l = fmaxf(m0l, fmaxf(s[j][0], s[j][1]));
            m1l = fmaxf(m1l, fmaxf(s[j][2], s[j][3]));
        }
        uint32_t pm = packh2(m0l, m1l);
        pm = hmax2u(pm, __shfl_xor_sync(FULL, pm, 1));
        pm = hmax2u(pm, __shfl_xor_sync(FULL, pm, 2));
        __half2 mh = *(__half2*)&pm;
        float mf0 = __low2float(mh), mf1 = __high2float(mh);
        float mn0 = fmaxf(rmax0, mf0), mn1 = fmaxf(rmax1, mf1);
        if (mf0 > rmax0 || mf1 > rmax1) {
            float cr0 = __expf(rmax0 - mn0), cr1 = __expf(rmax1 - mn1);
            sacc[0] *= cr0; sacc[1] *= cr0; sacc[2] *= cr1; sacc[3] *= cr1;
#pragma unroll
            for (int j = 0; j < 8; j++) {
                o[j][0] *= cr0; o[j][1] *= cr0; o[j][2] *= cr1; o[j][3] *= cr1;
            }
        }
        rmax0 = mn0; rmax1 = mn1;

        // ---- exp (log2 domain, paired fp16) -> P frags ----
        float b0 = -mn0 * L2E, b1 = -mn1 * L2E;
        uint32_t pan[4][4];
#pragma unroll
        for (int kb2 = 0; kb2 < 4; kb2++) {
            int j0 = 2 * kb2, j1 = 2 * kb2 + 1;
            pan[kb2][0] = ex2h2(packh2(fmaf(s[j0][0], L2E, b0), fmaf(s[j0][1], L2E, b0)));
            pan[kb2][1] = ex2h2(packh2(fmaf(s[j0][2], L2E, b1), fmaf(s[j0][3], L2E, b1)));
            pan[kb2][2] = ex2h2(packh2(fmaf(s[j1][0], L2E, b0), fmaf(s[j1][1], L2E, b0)));
            pan[kb2][3] = ex2h2(packh2(fmaf(s[j1][2], L2E, b1), fmaf(s[j1][3], L2E, b1)));
        }

        // ---- row sums (ones-mma) + O += P @ V ----
#pragma unroll
        for (int kb2 = 0; kb2 < 4; kb2++) {
            mma16(sacc, pan[kb2], onef);
            uint32_t vf[8][2];
#pragma unroll
            for (int jp = 0; jp < 4; jp++)
                ldsm4t(vf[2*jp][0], vf[2*jp][1], vf[2*jp+1][0], vf[2*jp+1][1],
                       vA + so + (kb2 * 16 * VP + jp * 16) * 2);
#pragma unroll
            for (int j = 0; j < 8; j++)
                mma16(o[j], pan[kb2], vf[j]);
        }
    }

    // ---- epilogue ----
    float i0 = 1.f / sacc[0], i1 = 1.f / sacc[2];
    int b = bh >> 4, h = bh & 15;
#pragma unroll
    for (int j = 0; j < 8; j++) {
        int col = j * 8 + 2 * t;
        *(__half2*)(C + ((size_t)(b * TT + row0)) * DD + h * HD + col) =
            __floats2half2_rn(o[j][0] * i0, o[j][1] * i0);
        *(__half2*)(C + ((size_t)(b * TT + row1)) * DD + h * HD + col) =
            __floats2half2_rn(o[j][2] * i1, o[j][3] * i1);
    }
}

// ---------------------------------------------------------------------------
// LayerNorm (faithful bug: scale * x_norm + scale), emits fp16
// ---------------------------------------------------------------------------
__global__ void ln_kernel(const float* __restrict__ x,
                          const float* __restrict__ scale,
                          __half* __restrict__ y) {
    int row = blockIdx.x;
    const float* xr = x + (size_t)row * DD;
    __half* yr = y + (size_t)row * DD;
    int tid = threadIdx.x;
    float v[4];
    float s = 0.f, s2 = 0.f;
#pragma unroll
    for (int i = 0; i < 4; i++) {
        v[i] = xr[tid + 256 * i];
        s  += v[i];
        s2 += v[i] * v[i];
    }
    __shared__ float sh[256], sh2[256];
    sh[tid] = s; sh2[tid] = s2;
    __syncthreads();
    for (int o = 128; o > 0; o >>= 1) {
        if (tid < o) { sh[tid] += sh[tid + o]; sh2[tid] += sh2[tid + o]; }
        __syncthreads();
    }
    float mean = sh[0] * (1.f / DD);
    float var  = sh2[0] * (1.f / DD) - mean * mean;
    float rstd = rsqrtf(var + 1e-5f);
#pragma unroll
    for (int i = 0; i < 4; i++) {
        int c = tid + 256 * i;
        float sc = scale[c];
        yr[c] = __float2half(sc * ((v[i] - mean) * rstd) + sc);
    }
}

// ---------------------------------------------------------------------------
// Host driver
// ---------------------------------------------------------------------------
static void run_block(const float* x_in, const float* ln_scale,
                      const __half* wqkv, const __half* wo, const float* bo,
                      __half* lnp, __half* qkvp, __half* ctxp, float* out) {
    ln_kernel<<<BB * TT, 256>>>(x_in, ln_scale, lnp);
    mma_gemm<0><<<dim3(3 * DD / 128, (BB * TT) / 128), 256, GSMEM>>>(
        lnp, wqkv, nullptr, nullptr, qkvp);
    flash_attn<<<dim3(TT / 64, BB * HH), 128>>>(
        qkvp, qkvp + BTD, qkvp + 2 * BTD, ctxp);
    mma_gemm<1><<<dim3(DD / 128, (BB * TT) / 128), 256, GSMEM>>>(
        ctxp, wo, bo, x_in, out);
}

extern "C" void kernel_launch(void* const* d_in, const int* in_sizes, int n_in,
                              void* d_out, int out_size) {
    const float* x   = (const float*)d_in[0];
    const float* bo  = (const float*)d_in[5];
    const float* ln1 = (const float*)d_in[6];
    const float* ln2 = (const float*)d_in[7];
    float* out = (float*)d_out;

    static bool attr_set = false;
    if (!attr_set) {
        cudaFuncSetAttribute(mma_gemm<0>, cudaFuncAttributeMaxDynamicSharedMemorySize, GSMEM);
        cudaFuncSetAttribute(mma_gemm<1>, cudaFuncAttributeMaxDynamicSharedMemorySize, GSMEM);
        attr_set = true;
    }

    __half *lnp, *qkvp, *ctxp, *wt;
    float* hp;
    cudaGetSymbolAddress((void**)&lnp,  g_ln);
    cudaGetSymbolAddress((void**)&qkvp, g_qkv);
    cudaGetSymbolAddress((void**)&ctxp, g_ctx);
    cudaGetSymbolAddress((void**)&hp,   g_h);
    cudaGetSymbolAddress((void**)&wt,   g_w);

    cvt_h4<<<dim3((DD * DD / 4) / 256, 4), 256>>>(
        (const float4*)d_in[1], (const float4*)d_in[2],
        (const float4*)d_in[3], (const float4*)d_in[4], (__half2*)wt);
    const __half* wqkv = wt;
    const __half* wo   = wt + (size_t)3 * DD * DD;

    run_block(x,  ln1, wqkv, wo, bo, lnp, qkvp, ctxp, hp);
    run_block(hp, ln2, wqkv, wo, bo, lnp, qkvp, ctxp, out);
}